// round 3
// baseline (speedup 1.0000x reference)
#include <cuda_runtime.h>
#include <math.h>

#define B_    8
#define CIN   64
#define COUT  128
#define C2    256
#define HW    65536
#define NBLK  4096
#define EPSV  1e-5f

// ---------------- scratch (device globals: no allocation allowed) ----------------
__device__ float g1buf[(size_t)NBLK * C2 * 64];   // relu(conv1+b1), pre-BN  [blk][ch][px]
__device__ float g2buf[(size_t)NBLK * C2 * 64];   // relu(conv2+b2), pre-BN  [blk][ch][px]
__device__ float g3buf[(size_t)NBLK * COUT * 64]; // relu(conv3+b3), pre-BN  [blk][ch][px]

__device__ double d_sum0[COUT], d_sq0[COUT];
__device__ double d_sum1[C2],   d_sq1[C2];
__device__ double d_sum2[C2],   d_sq2[C2];
__device__ double d_sum3[COUT], d_sq3[COUT];
__device__ float  d_a0[COUT], d_b0[COUT];
__device__ float  d_a1[C2],   d_b1[C2];
__device__ float  d_a2[C2],   d_b2[C2];
__device__ float  d_a3[COUT], d_b3[COUT];

// ---------------- f32x2 packed-FMA helpers ----------------
__device__ __forceinline__ unsigned long long ffma2(unsigned long long a,
                                                    unsigned long long b,
                                                    unsigned long long c) {
    unsigned long long d;
    asm("fma.rn.f32x2 %0, %1, %2, %3;" : "=l"(d) : "l"(a), "l"(b), "l"(c));
    return d;
}
__device__ __forceinline__ unsigned long long pack2(float lo, float hi) {
    unsigned long long r;
    asm("mov.b64 %0, {%1, %2};" : "=l"(r) : "f"(lo), "f"(hi));
    return r;
}
__device__ __forceinline__ unsigned long long dup2(float w) {
    unsigned long long r;
    asm("mov.b64 %0, {%1, %1};" : "=l"(r) : "f"(w));
    return r;
}
__device__ __forceinline__ float2 unpk(unsigned long long v) {
    float2 r;
    asm("mov.b64 {%0, %1}, %2;" : "=f"(r.x), "=f"(r.y) : "l"(v));
    return r;
}

// ---------------- utility ----------------
__global__ void zero_stats_kernel() {
    int t = threadIdx.x;               // 256 threads
    if (t < COUT) { d_sum0[t] = 0.0; d_sq0[t] = 0.0; d_sum3[t] = 0.0; d_sq3[t] = 0.0; }
    d_sum1[t] = 0.0; d_sq1[t] = 0.0; d_sum2[t] = 0.0; d_sq2[t] = 0.0;
}

__device__ __forceinline__ void block_reduce_2(float s, float s2, double* gsum, double* gsq) {
    __shared__ float rs[256], rq[256];
    int t = threadIdx.x;
    rs[t] = s; rq[t] = s2;
    __syncthreads();
    for (int o = 128; o > 0; o >>= 1) {
        if (t < o) { rs[t] += rs[t + o]; rq[t] += rq[t + o]; }
        __syncthreads();
    }
    if (t == 0) { atomicAdd(gsum, (double)rs[0]); atomicAdd(gsq, (double)rq[0]); }
}

__global__ void finalize_kernel(int stage, const float* __restrict__ gamma,
                                const float* __restrict__ beta, double invN) {
    int t = threadIdx.x;
    const double *sum, *sq; float *a, *bsh; int C;
    if (stage == 0)      { sum = d_sum0; sq = d_sq0; a = d_a0; bsh = d_b0; C = COUT; }
    else if (stage == 1) { sum = d_sum1; sq = d_sq1; a = d_a1; bsh = d_b1; C = C2; }
    else if (stage == 2) { sum = d_sum2; sq = d_sq2; a = d_a2; bsh = d_b2; C = C2; }
    else                 { sum = d_sum3; sq = d_sq3; a = d_a3; bsh = d_b3; C = COUT; }
    if (t < C) {
        double mean = sum[t] * invN;
        double var  = sq[t] * invN - mean * mean;
        float v = fmaxf((float)var, 0.0f);
        float av = gamma[t] * rsqrtf(v + EPSV);
        a[t] = av;
        bsh[t] = beta[t] - av * (float)mean;
    }
}

// ---------------- K1: 1x1 conv 64->128 + relu over full image ----------------
#define SMEM_CONVC ((64 * 64 + 128 * 65) * 4)
__global__ __launch_bounds__(256) void convc_kernel(const float* __restrict__ x,
                                                    const float* __restrict__ wc,
                                                    const float* __restrict__ bc,
                                                    float* __restrict__ out) {
    extern __shared__ float sm[];
    float* xs = sm;             // 64*64
    float* ws = sm + 64 * 64;   // 128*65
    int b  = blockIdx.x >> 10;
    int p0 = (blockIdx.x & 1023) << 6;
    int t  = threadIdx.x;

    for (int i = t; i < 128 * 64; i += 256) {
        int oc = i >> 6, ic = i & 63;
        ws[oc * 65 + ic] = wc[i];
    }
    for (int i = t; i < 1024; i += 256) {   // 1024 float4 = 64ic x 64px
        int ic = i >> 4, q = i & 15;
        float4 v = *reinterpret_cast<const float4*>(x + (((size_t)(b * CIN + ic)) << 16) + p0 + q * 4);
        *reinterpret_cast<float4*>(xs + ic * 64 + q * 4) = v;
    }
    __syncthreads();

    int px0 = (t & 7) * 8;
    int oc0 = (t >> 3) * 4;
    float acc[4][8];
    #pragma unroll
    for (int j = 0; j < 4; j++)
        #pragma unroll
        for (int c = 0; c < 8; c++) acc[j][c] = 0.0f;

    for (int ic = 0; ic < 64; ic++) {
        float4 xa = *reinterpret_cast<float4*>(xs + ic * 64 + px0);
        float4 xb = *reinterpret_cast<float4*>(xs + ic * 64 + px0 + 4);
        #pragma unroll
        for (int j = 0; j < 4; j++) {
            float w = ws[(oc0 + j) * 65 + ic];
            acc[j][0] += w * xa.x; acc[j][1] += w * xa.y;
            acc[j][2] += w * xa.z; acc[j][3] += w * xa.w;
            acc[j][4] += w * xb.x; acc[j][5] += w * xb.y;
            acc[j][6] += w * xb.z; acc[j][7] += w * xb.w;
        }
    }
    float* dstb = out + (((size_t)(b * COUT)) << 16) + p0;
    #pragma unroll
    for (int j = 0; j < 4; j++) {
        int oc = oc0 + j;
        float bb = bc[oc];
        float4 o1, o2;
        o1.x = fmaxf(acc[j][0] + bb, 0.f); o1.y = fmaxf(acc[j][1] + bb, 0.f);
        o1.z = fmaxf(acc[j][2] + bb, 0.f); o1.w = fmaxf(acc[j][3] + bb, 0.f);
        o2.x = fmaxf(acc[j][4] + bb, 0.f); o2.y = fmaxf(acc[j][5] + bb, 0.f);
        o2.z = fmaxf(acc[j][6] + bb, 0.f); o2.w = fmaxf(acc[j][7] + bb, 0.f);
        *reinterpret_cast<float4*>(dstb + (((size_t)oc) << 16) + px0)     = o1;
        *reinterpret_cast<float4*>(dstb + (((size_t)oc) << 16) + px0 + 4) = o2;
    }
}

// ---------------- stats over d_out [8][128][65536] ----------------
__global__ __launch_bounds__(256) void stats0_kernel(const float* __restrict__ y) {
    int c   = blockIdx.x & 127;
    int seg = blockIdx.x >> 7;           // 0..63
    int b   = seg >> 3;
    int off = (seg & 7) << 13;           // 8192 px per segment
    const float4* p = reinterpret_cast<const float4*>(y + (((size_t)(b * COUT + c)) << 16) + off);
    float s = 0.f, s2 = 0.f;
    for (int i = threadIdx.x; i < 2048; i += 256) {
        float4 v = p[i];
        s  += v.x + v.y + v.z + v.w;
        s2 += v.x * v.x + v.y * v.y + v.z * v.z + v.w * v.w;
    }
    block_reduce_2(s, s2, &d_sum0[c], &d_sq0[c]);
}

// ---------------- apply BN0 to the whole image ----------------
__global__ __launch_bounds__(256) void bnapply_kernel(float* __restrict__ y) {
    int nth = gridDim.x * blockDim.x;
    int total = (B_ * COUT * HW) / 4;
    for (int i = blockIdx.x * blockDim.x + threadIdx.x; i < total; i += nth) {
        int c = (i >> 14) & 127;
        float4 v = reinterpret_cast<float4*>(y)[i];
        float a = d_a0[c], bb = d_b0[c];
        v.x = a * v.x + bb; v.y = a * v.y + bb;
        v.z = a * v.z + bb; v.w = a * v.w + bb;
        reinterpret_cast<float4*>(y)[i] = v;
    }
}

// ---------------- conv1: gather + 1x1 128->256 + relu (FFMA2) ----------------
// grid 4096 (1 block, all 256 oc), 256 threads
// smem: xs[128][64] + ws[64 ic][260] transposed [ic][oc]
#define SMEM_C1 ((128 * 64 + 64 * 260) * 4)
__global__ __launch_bounds__(256) void conv1f2_kernel(const float* __restrict__ xbn,
                                                      const int* __restrict__ abi,
                                                      const float* __restrict__ w1,
                                                      const float* __restrict__ b1) {
    extern __shared__ float sm[];
    float* xs = sm;              // [128ic][64px]
    float* ws = sm + 128 * 64;   // [64ic][260] (oc-major rows)
    int blk  = blockIdx.x;
    int t    = threadIdx.x;
    int lane = t & 31;
    int warp = t >> 5;
    int px0  = warp * 8;

    int n  = abi[blk * 3 + 0];
    int bi = abi[blk * 3 + 1];
    int bj = abi[blk * 3 + 2];
    const float* src = xbn + (((size_t)(n * COUT)) << 16) + bi * 8 * 256 + bj * 8;

    for (int i = t; i < 2048; i += 256) {   // 2048 float4 = 128ic x 64px
        int ic = i >> 4, q = i & 15;
        int r = q >> 1, c4 = (q & 1) * 4;
        float4 v = *reinterpret_cast<const float4*>(src + (((size_t)ic) << 16) + r * 256 + c4);
        *reinterpret_cast<float4*>(xs + ic * 64 + r * 8 + c4) = v;
    }

    unsigned long long acc[8][4];
    #pragma unroll
    for (int j = 0; j < 8; j++)
        #pragma unroll
        for (int p = 0; p < 4; p++) acc[j][p] = 0ull;

    for (int cc = 0; cc < 2; cc++) {
        __syncthreads();
        // load + transpose weights: ws[ic][oc], ic in [cc*64, cc*64+64)
        for (int i = t; i < 16384; i += 256) {
            int ic = i & 63, oc = i >> 6;
            ws[ic * 260 + oc] = w1[(size_t)oc * 128 + cc * 64 + ic];
        }
        __syncthreads();

        #pragma unroll 2
        for (int ic = 0; ic < 64; ic++) {
            ulonglong2 xa = *reinterpret_cast<const ulonglong2*>(xs + (cc * 64 + ic) * 64 + px0);
            ulonglong2 xb = *reinterpret_cast<const ulonglong2*>(xs + (cc * 64 + ic) * 64 + px0 + 4);
            float4 wlo = *reinterpret_cast<const float4*>(ws + ic * 260 + lane * 4);
            float4 whi = *reinterpret_cast<const float4*>(ws + ic * 260 + 128 + lane * 4);
            unsigned long long wd[8];
            wd[0] = dup2(wlo.x); wd[1] = dup2(wlo.y); wd[2] = dup2(wlo.z); wd[3] = dup2(wlo.w);
            wd[4] = dup2(whi.x); wd[5] = dup2(whi.y); wd[6] = dup2(whi.z); wd[7] = dup2(whi.w);
            #pragma unroll
            for (int j = 0; j < 8; j++) {
                acc[j][0] = ffma2(xa.x, wd[j], acc[j][0]);
                acc[j][1] = ffma2(xa.y, wd[j], acc[j][1]);
                acc[j][2] = ffma2(xb.x, wd[j], acc[j][2]);
                acc[j][3] = ffma2(xb.y, wd[j], acc[j][3]);
            }
        }
    }

    float* dst = g1buf + (size_t)blk * C2 * 64;
    #pragma unroll
    for (int j = 0; j < 8; j++) {
        int oc = (j < 4) ? (lane * 4 + j) : (128 + lane * 4 + (j - 4));
        float bb = b1[oc];
        float2 p0 = unpk(acc[j][0]), p1 = unpk(acc[j][1]);
        float2 p2 = unpk(acc[j][2]), p3 = unpk(acc[j][3]);
        float4 o1, o2;
        o1.x = fmaxf(p0.x + bb, 0.f); o1.y = fmaxf(p0.y + bb, 0.f);
        o1.z = fmaxf(p1.x + bb, 0.f); o1.w = fmaxf(p1.y + bb, 0.f);
        o2.x = fmaxf(p2.x + bb, 0.f); o2.y = fmaxf(p2.y + bb, 0.f);
        o2.z = fmaxf(p3.x + bb, 0.f); o2.w = fmaxf(p3.y + bb, 0.f);
        *reinterpret_cast<float4*>(dst + oc * 64 + px0)     = o1;
        *reinterpret_cast<float4*>(dst + oc * 64 + px0 + 4) = o2;
    }
}

// ---------------- generic stats over [NBLK][C][64] buffer ----------------
__device__ __forceinline__ void stats_body(const float* __restrict__ buf, int C,
                                           double* gsum, double* gsq) {
    int c    = blockIdx.x % C;
    int seg  = blockIdx.x / C;     // 0..31
    int blk0 = seg * 128;
    float s = 0.f, s2 = 0.f;
    for (int i = threadIdx.x; i < 128 * 16; i += 256) {
        int bo = i >> 4, q = i & 15;
        float4 v = *reinterpret_cast<const float4*>(buf + ((size_t)(blk0 + bo) * C + c) * 64 + q * 4);
        s  += v.x + v.y + v.z + v.w;
        s2 += v.x * v.x + v.y * v.y + v.z * v.z + v.w * v.w;
    }
    block_reduce_2(s, s2, &gsum[c], &gsq[c]);
}
__global__ __launch_bounds__(256) void stats_g1_kernel() { stats_body(g1buf, C2,   d_sum1, d_sq1); }
__global__ __launch_bounds__(256) void stats_g2_kernel() { stats_body(g2buf, C2,   d_sum2, d_sq2); }
__global__ __launch_bounds__(256) void stats_g3_kernel() { stats_body(g3buf, COUT, d_sum3, d_sq3); }

// ---------------- conv2: 3x3 256->256, FFMA2, 2 blocks x 64 oc per CTA ----------------
// grid 8192 = 2048 block-pairs x 4 oc-quarters, 128 threads
// smem: xs[2][32][10 rows x 12] + ws[288][66]  ([ic*9+k][oc] transposed)
#define SMEM_C2K ((2 * 32 * 120 + 288 * 66) * 4)
__global__ __launch_bounds__(128) void conv2f2_kernel(const float* __restrict__ w2,
                                                      const float* __restrict__ b2) {
    extern __shared__ float sm[];
    float* xs = sm;                 // 2 * 3840
    float* ws = sm + 2 * 3840;      // 288 * 66
    int pairidx = blockIdx.x >> 2;
    int ocbase  = (blockIdx.x & 3) << 6;
    int blk0    = pairidx * 2;
    int t   = threadIdx.x;
    int ocg = t & 15;       // 16 oc groups
    int r   = t >> 4;       // 8 rows

    for (int i = t; i < 2 * 3840; i += 128) xs[i] = 0.0f;   // zero incl. halo

    unsigned long long acc[2][4][4];
    #pragma unroll
    for (int bq = 0; bq < 2; bq++)
        #pragma unroll
        for (int j = 0; j < 4; j++)
            #pragma unroll
            for (int p = 0; p < 4; p++) acc[bq][j][p] = 0ull;

    const float* g0 = g1buf + (size_t)blk0 * C2 * 64;

    for (int cc = 0; cc < 8; cc++) {
        __syncthreads();
        // x: 2 blocks x 32 ic, BN1 applied, into padded 10x12 tiles
        for (int i = t; i < 1024; i += 128) {        // 1024 float4
            int bq = i >> 9, ic = (i >> 4) & 31, q = i & 15;
            int icg = cc * 32 + ic;
            float4 v = *reinterpret_cast<const float4*>(g0 + ((size_t)bq * C2 + icg) * 64 + q * 4);
            float a = d_a1[icg], bb = d_b1[icg];
            int rr = q >> 1, c4 = (q & 1) * 4;
            float* row = xs + bq * 3840 + ic * 120 + (rr + 1) * 12 + c4 + 1;
            row[0] = a * v.x + bb; row[1] = a * v.y + bb;
            row[2] = a * v.z + bb; row[3] = a * v.w + bb;
        }
        // weights: [oc 64][ic 32][9] -> ws[(ic*9+k)][oc]
        const float* wsrc = w2 + (size_t)ocbase * C2 * 9 + cc * 288;
        for (int i = t; i < 18432; i += 128) {
            int oc = i / 288;
            int rem = i - oc * 288;
            ws[rem * 66 + oc] = wsrc[(size_t)oc * C2 * 9 + rem];
        }
        __syncthreads();

        #pragma unroll 1
        for (int ic = 0; ic < 32; ic++) {
            const float* wrow = ws + ic * 9 * 66;
            #pragma unroll
            for (int dr = 0; dr < 3; dr++) {
                unsigned long long wp[3][4];
                #pragma unroll
                for (int dc = 0; dc < 3; dc++) {
                    float2 wl = *reinterpret_cast<const float2*>(wrow + (dr * 3 + dc) * 66 + ocg * 2);
                    float2 wh = *reinterpret_cast<const float2*>(wrow + (dr * 3 + dc) * 66 + 32 + ocg * 2);
                    wp[dc][0] = dup2(wl.x); wp[dc][1] = dup2(wl.y);
                    wp[dc][2] = dup2(wh.x); wp[dc][3] = dup2(wh.y);
                }
                #pragma unroll
                for (int bq = 0; bq < 2; bq++) {
                    const float* row = xs + bq * 3840 + ic * 120 + (r + dr) * 12;
                    float4 xa = *reinterpret_cast<const float4*>(row);
                    float4 xb = *reinterpret_cast<const float4*>(row + 4);
                    float2 xc = *reinterpret_cast<const float2*>(row + 8);
                    float xv[10] = {xa.x, xa.y, xa.z, xa.w, xb.x, xb.y, xb.z, xb.w, xc.x, xc.y};
                    #pragma unroll
                    for (int dc = 0; dc < 3; dc++) {
                        #pragma unroll
                        for (int p = 0; p < 4; p++) {
                            unsigned long long xp = pack2(xv[2 * p + dc], xv[2 * p + dc + 1]);
                            acc[bq][0][p] = ffma2(xp, wp[dc][0], acc[bq][0][p]);
                            acc[bq][1][p] = ffma2(xp, wp[dc][1], acc[bq][1][p]);
                            acc[bq][2][p] = ffma2(xp, wp[dc][2], acc[bq][2][p]);
                            acc[bq][3][p] = ffma2(xp, wp[dc][3], acc[bq][3][p]);
                        }
                    }
                }
            }
        }
    }

    #pragma unroll
    for (int bq = 0; bq < 2; bq++) {
        float* dst = g2buf + (size_t)(blk0 + bq) * C2 * 64 + r * 8;
        #pragma unroll
        for (int j = 0; j < 4; j++) {
            int oc = ocbase + ((j < 2) ? (ocg * 2 + j) : (32 + ocg * 2 + (j - 2)));
            float bb = b2[oc];
            float2 p0 = unpk(acc[bq][j][0]), p1 = unpk(acc[bq][j][1]);
            float2 p2 = unpk(acc[bq][j][2]), p3 = unpk(acc[bq][j][3]);
            float4 o1, o2;
            o1.x = fmaxf(p0.x + bb, 0.f); o1.y = fmaxf(p0.y + bb, 0.f);
            o1.z = fmaxf(p1.x + bb, 0.f); o1.w = fmaxf(p1.y + bb, 0.f);
            o2.x = fmaxf(p2.x + bb, 0.f); o2.y = fmaxf(p2.y + bb, 0.f);
            o2.z = fmaxf(p3.x + bb, 0.f); o2.w = fmaxf(p3.y + bb, 0.f);
            *reinterpret_cast<float4*>(dst + oc * 64)     = o1;
            *reinterpret_cast<float4*>(dst + oc * 64 + 4) = o2;
        }
    }
}

// ---------------- conv3: 1x1 256->128, FFMA2, BN2 folded ----------------
// grid 4096, 128 threads; smem xs[128][64] + ws[128][132]
#define SMEM_C3 ((128 * 64 + 128 * 132) * 4)
__global__ __launch_bounds__(128) void conv3f2_kernel(const float* __restrict__ w3,
                                                      const float* __restrict__ b3) {
    extern __shared__ float sm[];
    float* xs = sm;              // [128ic][64px]
    float* ws = sm + 128 * 64;   // [128ic][132]
    int blk = blockIdx.x;
    int t   = threadIdx.x;
    int ocg = t & 15;
    int px0 = (t >> 4) * 8;

    unsigned long long acc[8][4];
    #pragma unroll
    for (int j = 0; j < 8; j++)
        #pragma unroll
        for (int p = 0; p < 4; p++) acc[j][p] = 0ull;

    const float* gsrc = g2buf + (size_t)blk * C2 * 64;

    for (int cc = 0; cc < 2; cc++) {
        __syncthreads();
        for (int i = t; i < 2048; i += 128) {    // 2048 f4 = 128ic x 64px
            int ic = i >> 4, q = i & 15;
            int icg = cc * 128 + ic;
            float4 v = *reinterpret_cast<const float4*>(gsrc + (size_t)icg * 64 + q * 4);
            float a = d_a2[icg], bb = d_b2[icg];
            v.x = a * v.x + bb; v.y = a * v.y + bb;
            v.z = a * v.z + bb; v.w = a * v.w + bb;
            *reinterpret_cast<float4*>(xs + ic * 64 + q * 4) = v;
        }
        for (int i = t; i < 16384; i += 128) {
            int ic = i & 127, oc = i >> 7;
            ws[ic * 132 + oc] = w3[(size_t)oc * C2 + cc * 128 + ic];
        }
        __syncthreads();

        #pragma unroll 2
        for (int ic = 0; ic < 128; ic++) {
            ulonglong2 xa = *reinterpret_cast<const ulonglong2*>(xs + ic * 64 + px0);
            ulonglong2 xb = *reinterpret_cast<const ulonglong2*>(xs + ic * 64 + px0 + 4);
            float4 wlo = *reinterpret_cast<const float4*>(ws + ic * 132 + ocg * 4);
            float4 whi = *reinterpret_cast<const float4*>(ws + ic * 132 + 64 + ocg * 4);
            unsigned long long wd[8];
            wd[0] = dup2(wlo.x); wd[1] = dup2(wlo.y); wd[2] = dup2(wlo.z); wd[3] = dup2(wlo.w);
            wd[4] = dup2(whi.x); wd[5] = dup2(whi.y); wd[6] = dup2(whi.z); wd[7] = dup2(whi.w);
            #pragma unroll
            for (int j = 0; j < 8; j++) {
                acc[j][0] = ffma2(xa.x, wd[j], acc[j][0]);
                acc[j][1] = ffma2(xa.y, wd[j], acc[j][1]);
                acc[j][2] = ffma2(xb.x, wd[j], acc[j][2]);
                acc[j][3] = ffma2(xb.y, wd[j], acc[j][3]);
            }
        }
    }

    float* dst = g3buf + (size_t)blk * COUT * 64;
    #pragma unroll
    for (int j = 0; j < 8; j++) {
        int oc = (j < 4) ? (ocg * 4 + j) : (64 + ocg * 4 + (j - 4));
        float bb = b3[oc];
        float2 p0 = unpk(acc[j][0]), p1 = unpk(acc[j][1]);
        float2 p2 = unpk(acc[j][2]), p3 = unpk(acc[j][3]);
        float4 o1, o2;
        o1.x = fmaxf(p0.x + bb, 0.f); o1.y = fmaxf(p0.y + bb, 0.f);
        o1.z = fmaxf(p1.x + bb, 0.f); o1.w = fmaxf(p1.y + bb, 0.f);
        o2.x = fmaxf(p2.x + bb, 0.f); o2.y = fmaxf(p2.y + bb, 0.f);
        o2.z = fmaxf(p3.x + bb, 0.f); o2.w = fmaxf(p3.y + bb, 0.f);
        *reinterpret_cast<float4*>(dst + oc * 64 + px0)     = o1;
        *reinterpret_cast<float4*>(dst + oc * 64 + px0 + 4) = o2;
    }
}

// ---------------- scatter: BN3(g3) back into the image ----------------
__global__ __launch_bounds__(256) void scatter_kernel(const int* __restrict__ abi,
                                                      float* __restrict__ out) {
    int blk = blockIdx.x;
    int n  = abi[blk * 3 + 0];
    int bi = abi[blk * 3 + 1];
    int bj = abi[blk * 3 + 2];
    const float* src = g3buf + (size_t)blk * COUT * 64;
    float* dst = out + (((size_t)(n * COUT)) << 16) + bi * 8 * 256 + bj * 8;
    for (int i = threadIdx.x; i < 2048; i += 256) {   // 2048 f4 = 128ch x 64px
        int c = i >> 4, q = i & 15;
        int r = q >> 1, c4 = (q & 1) * 4;
        float4 v = *reinterpret_cast<const float4*>(src + c * 64 + q * 4);
        float a = d_a3[c], bb = d_b3[c];
        v.x = a * v.x + bb; v.y = a * v.y + bb;
        v.z = a * v.z + bb; v.w = a * v.w + bb;
        *reinterpret_cast<float4*>(dst + (((size_t)c) << 16) + r * 256 + c4) = v;
    }
}

// ---------------- launch ----------------
extern "C" void kernel_launch(void* const* d_in, const int* in_sizes, int n_in,
                              void* d_out, int out_size) {
    const float* x    = (const float*)d_in[0];
    const int*   abi  = (const int*)  d_in[1];
    const float* w_c  = (const float*)d_in[2];
    const float* b_c  = (const float*)d_in[3];
    const float* gm_c = (const float*)d_in[4];
    const float* be_c = (const float*)d_in[5];
    const float* w1   = (const float*)d_in[6];
    const float* b1   = (const float*)d_in[7];
    const float* gm1  = (const float*)d_in[8];
    const float* be1  = (const float*)d_in[9];
    const float* w2   = (const float*)d_in[10];
    const float* b2   = (const float*)d_in[11];
    const float* gm2  = (const float*)d_in[12];
    const float* be2  = (const float*)d_in[13];
    const float* w3   = (const float*)d_in[14];
    const float* b3   = (const float*)d_in[15];
    const float* gm3  = (const float*)d_in[16];
    const float* be3  = (const float*)d_in[17];
    float* out = (float*)d_out;

    cudaFuncSetAttribute(convc_kernel,   cudaFuncAttributeMaxDynamicSharedMemorySize, SMEM_CONVC);
    cudaFuncSetAttribute(conv1f2_kernel, cudaFuncAttributeMaxDynamicSharedMemorySize, SMEM_C1);
    cudaFuncSetAttribute(conv2f2_kernel, cudaFuncAttributeMaxDynamicSharedMemorySize, SMEM_C2K);
    cudaFuncSetAttribute(conv3f2_kernel, cudaFuncAttributeMaxDynamicSharedMemorySize, SMEM_C3);

    zero_stats_kernel<<<1, 256>>>();

    convc_kernel<<<8192, 256, SMEM_CONVC>>>(x, w_c, b_c, out);
    stats0_kernel<<<128 * 64, 256>>>(out);
    finalize_kernel<<<1, 256>>>(0, gm_c, be_c, 1.0 / 524288.0);
    bnapply_kernel<<<16384, 256>>>(out);

    conv1f2_kernel<<<4096, 256, SMEM_C1>>>(out, abi, w1, b1);
    stats_g1_kernel<<<256 * 32, 256>>>();
    finalize_kernel<<<1, 256>>>(1, gm1, be1, 1.0 / 262144.0);

    conv2f2_kernel<<<8192, 128, SMEM_C2K>>>(w2, b2);
    stats_g2_kernel<<<256 * 32, 256>>>();
    finalize_kernel<<<1, 256>>>(2, gm2, be2, 1.0 / 262144.0);

    conv3f2_kernel<<<4096, 128, SMEM_C3>>>(w3, b3);
    stats_g3_kernel<<<128 * 32, 256>>>();
    finalize_kernel<<<1, 256>>>(3, gm3, be3, 1.0 / 262144.0);

    scatter_kernel<<<4096, 256>>>(abi, out);
}

// round 5
// speedup vs baseline: 1.6137x; 1.6137x over previous
#include <cuda_runtime.h>
#include <cuda_bf16.h>
#include <math.h>
#include <stdint.h>

#define B_    8
#define CIN   64
#define COUT  128
#define C2    256
#define HW    65536
#define NBLK  4096
#define EPSV  1e-5f

// ---------------- scratch ----------------
__device__ float g1buf[(size_t)NBLK * C2 * 64];
__device__ float g2buf[(size_t)NBLK * C2 * 64];
__device__ float g3buf[(size_t)NBLK * COUT * 64];

// conv2 weights converted to bf16 hi/lo: [tap*4+chunk][oc 256][ic 64]
__device__ __nv_bfloat16 w2h[36 * 16384];
__device__ __nv_bfloat16 w2l[36 * 16384];

__device__ double d_sum0[COUT], d_sq0[COUT];
__device__ double d_sum1[C2],   d_sq1[C2];
__device__ double d_sum2[C2],   d_sq2[C2];
__device__ double d_sum3[COUT], d_sq3[COUT];
__device__ float  d_a0[COUT], d_b0[COUT];
__device__ float  d_a1[C2],   d_b1[C2];
__device__ float  d_a2[C2],   d_b2[C2];
__device__ float  d_a3[COUT], d_b3[COUT];

// ---------------- f32x2 helpers ----------------
__device__ __forceinline__ unsigned long long ffma2(unsigned long long a,
                                                    unsigned long long b,
                                                    unsigned long long c) {
    unsigned long long d;
    asm("fma.rn.f32x2 %0, %1, %2, %3;" : "=l"(d) : "l"(a), "l"(b), "l"(c));
    return d;
}
__device__ __forceinline__ unsigned long long dup2(float w) {
    unsigned long long r;
    asm("mov.b64 %0, {%1, %1};" : "=l"(r) : "f"(w));
    return r;
}
__device__ __forceinline__ float2 unpk(unsigned long long v) {
    float2 r;
    asm("mov.b64 {%0, %1}, %2;" : "=f"(r.x), "=f"(r.y) : "l"(v));
    return r;
}

// ---------------- bf16 HMMA helper ----------------
__device__ __forceinline__ void mma16816(float* d, const unsigned* a, unsigned b0, unsigned b1) {
    asm volatile(
        "mma.sync.aligned.m16n8k16.row.col.f32.bf16.bf16.f32 "
        "{%0,%1,%2,%3}, {%4,%5,%6,%7}, {%8,%9}, {%0,%1,%2,%3};"
        : "+f"(d[0]), "+f"(d[1]), "+f"(d[2]), "+f"(d[3])
        : "r"(a[0]), "r"(a[1]), "r"(a[2]), "r"(a[3]), "r"(b0), "r"(b1));
}

// ---------------- utility ----------------
__global__ void zero_stats_kernel() {
    int t = threadIdx.x;
    if (t < COUT) { d_sum0[t] = 0.0; d_sq0[t] = 0.0; d_sum3[t] = 0.0; d_sq3[t] = 0.0; }
    d_sum1[t] = 0.0; d_sq1[t] = 0.0; d_sum2[t] = 0.0; d_sq2[t] = 0.0;
}

__device__ __forceinline__ void block_reduce_2(float s, float s2, double* gsum, double* gsq) {
    __shared__ float rs[256], rq[256];
    int t = threadIdx.x;
    rs[t] = s; rq[t] = s2;
    __syncthreads();
    for (int o = 128; o > 0; o >>= 1) {
        if (t < o) { rs[t] += rs[t + o]; rq[t] += rq[t + o]; }
        __syncthreads();
    }
    if (t == 0) { atomicAdd(gsum, (double)rs[0]); atomicAdd(gsq, (double)rq[0]); }
}

__global__ void finalize_kernel(int stage, const float* __restrict__ gamma,
                                const float* __restrict__ beta, double invN) {
    int t = threadIdx.x;
    const double *sum, *sq; float *a, *bsh; int C;
    if (stage == 0)      { sum = d_sum0; sq = d_sq0; a = d_a0; bsh = d_b0; C = COUT; }
    else if (stage == 1) { sum = d_sum1; sq = d_sq1; a = d_a1; bsh = d_b1; C = C2; }
    else if (stage == 2) { sum = d_sum2; sq = d_sq2; a = d_a2; bsh = d_b2; C = C2; }
    else                 { sum = d_sum3; sq = d_sq3; a = d_a3; bsh = d_b3; C = COUT; }
    if (t < C) {
        double mean = sum[t] * invN;
        double var  = sq[t] * invN - mean * mean;
        float v = fmaxf((float)var, 0.0f);
        float av = gamma[t] * rsqrtf(v + EPSV);
        a[t] = av;
        bsh[t] = beta[t] - av * (float)mean;
    }
}

// ---------------- w2 convert: fp32 OIHW -> bf16 hi/lo [tc][oc][ic] ----------------
__global__ __launch_bounds__(256) void w2cvt_kernel(const float* __restrict__ w2) {
    int i4 = blockIdx.x * 256 + threadIdx.x;        // 147456 total
    int ic0 = (i4 & 15) * 4;
    int oc  = (i4 >> 4) & 255;
    int tc  = i4 >> 12;                             // tap*4+chunk, 0..35
    int tap = tc >> 2, chunk = tc & 3;
    #pragma unroll
    for (int e = 0; e < 4; e++) {
        int ic = ic0 + e;
        float v = w2[(size_t)oc * 2304 + (chunk * 64 + ic) * 9 + tap];
        __nv_bfloat16 h = __float2bfloat16(v);
        float l = v - __bfloat162float(h);
        w2h[(size_t)tc * 16384 + oc * 64 + ic] = h;
        w2l[(size_t)tc * 16384 + oc * 64 + ic] = __float2bfloat16(l);
    }
}

// ---------------- K1: 1x1 conv 64->128 + relu full image ----------------
#define SMEM_CONVC ((64 * 64 + 128 * 65) * 4)
__global__ __launch_bounds__(256) void convc_kernel(const float* __restrict__ x,
                                                    const float* __restrict__ wc,
                                                    const float* __restrict__ bc,
                                                    float* __restrict__ out) {
    extern __shared__ float sm[];
    float* xs = sm;
    float* ws = sm + 64 * 64;
    int b  = blockIdx.x >> 10;
    int p0 = (blockIdx.x & 1023) << 6;
    int t  = threadIdx.x;

    for (int i = t; i < 128 * 64; i += 256) {
        int oc = i >> 6, ic = i & 63;
        ws[oc * 65 + ic] = wc[i];
    }
    for (int i = t; i < 1024; i += 256) {
        int ic = i >> 4, q = i & 15;
        float4 v = *reinterpret_cast<const float4*>(x + (((size_t)(b * CIN + ic)) << 16) + p0 + q * 4);
        *reinterpret_cast<float4*>(xs + ic * 64 + q * 4) = v;
    }
    __syncthreads();

    int px0 = (t & 7) * 8;
    int oc0 = (t >> 3) * 4;
    float acc[4][8];
    #pragma unroll
    for (int j = 0; j < 4; j++)
        #pragma unroll
        for (int c = 0; c < 8; c++) acc[j][c] = 0.0f;

    for (int ic = 0; ic < 64; ic++) {
        float4 xa = *reinterpret_cast<float4*>(xs + ic * 64 + px0);
        float4 xb = *reinterpret_cast<float4*>(xs + ic * 64 + px0 + 4);
        #pragma unroll
        for (int j = 0; j < 4; j++) {
            float w = ws[(oc0 + j) * 65 + ic];
            acc[j][0] += w * xa.x; acc[j][1] += w * xa.y;
            acc[j][2] += w * xa.z; acc[j][3] += w * xa.w;
            acc[j][4] += w * xb.x; acc[j][5] += w * xb.y;
            acc[j][6] += w * xb.z; acc[j][7] += w * xb.w;
        }
    }
    float* dstb = out + (((size_t)(b * COUT)) << 16) + p0;
    #pragma unroll
    for (int j = 0; j < 4; j++) {
        int oc = oc0 + j;
        float bb = bc[oc];
        float4 o1, o2;
        o1.x = fmaxf(acc[j][0] + bb, 0.f); o1.y = fmaxf(acc[j][1] + bb, 0.f);
        o1.z = fmaxf(acc[j][2] + bb, 0.f); o1.w = fmaxf(acc[j][3] + bb, 0.f);
        o2.x = fmaxf(acc[j][4] + bb, 0.f); o2.y = fmaxf(acc[j][5] + bb, 0.f);
        o2.z = fmaxf(acc[j][6] + bb, 0.f); o2.w = fmaxf(acc[j][7] + bb, 0.f);
        *reinterpret_cast<float4*>(dstb + (((size_t)oc) << 16) + px0)     = o1;
        *reinterpret_cast<float4*>(dstb + (((size_t)oc) << 16) + px0 + 4) = o2;
    }
}

__global__ __launch_bounds__(256) void stats0_kernel(const float* __restrict__ y) {
    int c   = blockIdx.x & 127;
    int seg = blockIdx.x >> 7;
    int b   = seg >> 3;
    int off = (seg & 7) << 13;
    const float4* p = reinterpret_cast<const float4*>(y + (((size_t)(b * COUT + c)) << 16) + off);
    float s = 0.f, s2 = 0.f;
    for (int i = threadIdx.x; i < 2048; i += 256) {
        float4 v = p[i];
        s  += v.x + v.y + v.z + v.w;
        s2 += v.x * v.x + v.y * v.y + v.z * v.z + v.w * v.w;
    }
    block_reduce_2(s, s2, &d_sum0[c], &d_sq0[c]);
}

__global__ __launch_bounds__(256) void bnapply_kernel(float* __restrict__ y) {
    int nth = gridDim.x * blockDim.x;
    int total = (B_ * COUT * HW) / 4;
    for (int i = blockIdx.x * blockDim.x + threadIdx.x; i < total; i += nth) {
        int c = (i >> 14) & 127;
        float4 v = reinterpret_cast<float4*>(y)[i];
        float a = d_a0[c], bb = d_b0[c];
        v.x = a * v.x + bb; v.y = a * v.y + bb;
        v.z = a * v.z + bb; v.w = a * v.w + bb;
        reinterpret_cast<float4*>(y)[i] = v;
    }
}

// ---------------- conv1: gather + 1x1 128->256 + relu (FFMA2) ----------------
#define SMEM_C1 ((128 * 64 + 64 * 260) * 4)
__global__ __launch_bounds__(256) void conv1f2_kernel(const float* __restrict__ xbn,
                                                      const int* __restrict__ abi,
                                                      const float* __restrict__ w1,
                                                      const float* __restrict__ b1) {
    extern __shared__ float sm[];
    float* xs = sm;
    float* ws = sm + 128 * 64;
    int blk  = blockIdx.x;
    int t    = threadIdx.x;
    int lane = t & 31;
    int warp = t >> 5;
    int px0  = warp * 8;

    int n  = abi[blk * 3 + 0];
    int bi = abi[blk * 3 + 1];
    int bj = abi[blk * 3 + 2];
    const float* src = xbn + (((size_t)(n * COUT)) << 16) + bi * 8 * 256 + bj * 8;

    for (int i = t; i < 2048; i += 256) {
        int ic = i >> 4, q = i & 15;
        int r = q >> 1, c4 = (q & 1) * 4;
        float4 v = *reinterpret_cast<const float4*>(src + (((size_t)ic) << 16) + r * 256 + c4);
        *reinterpret_cast<float4*>(xs + ic * 64 + r * 8 + c4) = v;
    }

    unsigned long long acc[8][4];
    #pragma unroll
    for (int j = 0; j < 8; j++)
        #pragma unroll
        for (int p = 0; p < 4; p++) acc[j][p] = 0ull;

    for (int cc = 0; cc < 2; cc++) {
        __syncthreads();
        for (int i = t; i < 16384; i += 256) {
            int ic = i & 63, oc = i >> 6;
            ws[ic * 260 + oc] = w1[(size_t)oc * 128 + cc * 64 + ic];
        }
        __syncthreads();

        #pragma unroll 2
        for (int ic = 0; ic < 64; ic++) {
            ulonglong2 xa = *reinterpret_cast<const ulonglong2*>(xs + (cc * 64 + ic) * 64 + px0);
            ulonglong2 xb = *reinterpret_cast<const ulonglong2*>(xs + (cc * 64 + ic) * 64 + px0 + 4);
            float4 wlo = *reinterpret_cast<const float4*>(ws + ic * 260 + lane * 4);
            float4 whi = *reinterpret_cast<const float4*>(ws + ic * 260 + 128 + lane * 4);
            unsigned long long wd[8];
            wd[0] = dup2(wlo.x); wd[1] = dup2(wlo.y); wd[2] = dup2(wlo.z); wd[3] = dup2(wlo.w);
            wd[4] = dup2(whi.x); wd[5] = dup2(whi.y); wd[6] = dup2(whi.z); wd[7] = dup2(whi.w);
            #pragma unroll
            for (int j = 0; j < 8; j++) {
                acc[j][0] = ffma2(xa.x, wd[j], acc[j][0]);
                acc[j][1] = ffma2(xa.y, wd[j], acc[j][1]);
                acc[j][2] = ffma2(xb.x, wd[j], acc[j][2]);
                acc[j][3] = ffma2(xb.y, wd[j], acc[j][3]);
            }
        }
    }

    float* dst = g1buf + (size_t)blk * C2 * 64;
    #pragma unroll
    for (int j = 0; j < 8; j++) {
        int oc = (j < 4) ? (lane * 4 + j) : (128 + lane * 4 + (j - 4));
        float bb = b1[oc];
        float2 p0 = unpk(acc[j][0]), p1 = unpk(acc[j][1]);
        float2 p2 = unpk(acc[j][2]), p3 = unpk(acc[j][3]);
        float4 o1, o2;
        o1.x = fmaxf(p0.x + bb, 0.f); o1.y = fmaxf(p0.y + bb, 0.f);
        o1.z = fmaxf(p1.x + bb, 0.f); o1.w = fmaxf(p1.y + bb, 0.f);
        o2.x = fmaxf(p2.x + bb, 0.f); o2.y = fmaxf(p2.y + bb, 0.f);
        o2.z = fmaxf(p3.x + bb, 0.f); o2.w = fmaxf(p3.y + bb, 0.f);
        *reinterpret_cast<float4*>(dst + oc * 64 + px0)     = o1;
        *reinterpret_cast<float4*>(dst + oc * 64 + px0 + 4) = o2;
    }
}

// ---------------- stats over [NBLK][C][64] ----------------
__device__ __forceinline__ void stats_body(const float* __restrict__ buf, int C,
                                           double* gsum, double* gsq) {
    int c    = blockIdx.x % C;
    int seg  = blockIdx.x / C;
    int blk0 = seg * 128;
    float s = 0.f, s2 = 0.f;
    for (int i = threadIdx.x; i < 128 * 16; i += 256) {
        int bo = i >> 4, q = i & 15;
        float4 v = *reinterpret_cast<const float4*>(buf + ((size_t)(blk0 + bo) * C + c) * 64 + q * 4);
        s  += v.x + v.y + v.z + v.w;
        s2 += v.x * v.x + v.y * v.y + v.z * v.z + v.w * v.w;
    }
    block_reduce_2(s, s2, &gsum[c], &gsq[c]);
}
__global__ __launch_bounds__(256) void stats_g1_kernel() { stats_body(g1buf, C2,   d_sum1, d_sq1); }
__global__ __launch_bounds__(256) void stats_g2_kernel() { stats_body(g2buf, C2,   d_sum2, d_sq2); }
__global__ __launch_bounds__(256) void stats_g3_kernel() { stats_body(g3buf, COUT, d_sum3, d_sq3); }

// ---------------- conv2: 3x3 via mma.sync bf16 hi/lo, 2 blocks/CTA ----------------
// smem: X @0:  [blk2][dc3][part2] arrays of [px 80][ic 72] bf16 = 12*11520 = 138240 B
//       W @138240: [part2][oc 256][ic 72] bf16 = 73728 B
#define XSTR   144           // bytes per px row (72 bf16)
#define XARR   11520         // bytes per X array
#define WOFF   138240
#define WPART  36864
#define SMEM_C2M (WOFF + 2 * WPART)
__global__ __launch_bounds__(256, 1) void conv2m_kernel(const float* __restrict__ b2) {
    extern __shared__ float smf[];
    char* smem = (char*)smf;
    int t = threadIdx.x, w = t >> 5, lane = t & 31;
    int g = lane >> 2, tg = lane & 3;
    int blk0 = blockIdx.x * 2;
    int mblk = w >> 2;              // which block this warp computes
    int ocb  = (w & 3) * 64;        // 64 oc per warp

    float acc[4][8][4];
    #pragma unroll
    for (int mt = 0; mt < 4; mt++)
        #pragma unroll
        for (int nt = 0; nt < 8; nt++)
            #pragma unroll
            for (int e = 0; e < 4; e++) acc[mt][nt][e] = 0.0f;

    int brow = t >> 1, bsub = t & 1;           // X build: 128 rows x 2 halves
    int xblk = brow >> 6, xic = brow & 63;

    for (int chunk = 0; chunk < 4; chunk++) {
        __syncthreads();                        // prior frag reads done
        // zero X
        for (int i = t; i < WOFF / 16; i += 256) ((uint4*)smem)[i] = make_uint4(0, 0, 0, 0);
        __syncthreads();

        // build X (BN1 applied, bf16 hi/lo, 3 dc-shift variants, transposed [px][ic])
        {
            int icg = chunk * 64 + xic;
            const float* src = g1buf + ((size_t)(blk0 + xblk) * C2 + icg) * 64 + bsub * 32;
            float a = d_a1[icg], bb = d_b1[icg];
            char* xb = smem + xblk * 6 * XARR + xic * 2;
            #pragma unroll
            for (int j = 0; j < 8; j++) {
                float4 v4 = ((const float4*)src)[j];
                float vals[4] = {v4.x, v4.y, v4.z, v4.w};
                #pragma unroll
                for (int e = 0; e < 4; e++) {
                    int px = bsub * 32 + j * 4 + e;
                    float xv = a * vals[e] + bb;
                    __nv_bfloat16 h = __float2bfloat16(xv);
                    __nv_bfloat16 l = __float2bfloat16(xv - __bfloat162float(h));
                    int col = px & 7;
                    // dc=1 at row px+8
                    *(__nv_bfloat16*)(xb + 2 * XARR + (px + 8) * XSTR) = h;
                    *(__nv_bfloat16*)(xb + 3 * XARR + (px + 8) * XSTR) = l;
                    if (col != 7) {   // dc=0 at px+9
                        *(__nv_bfloat16*)(xb + 0 * XARR + (px + 9) * XSTR) = h;
                        *(__nv_bfloat16*)(xb + 1 * XARR + (px + 9) * XSTR) = l;
                    }
                    if (col != 0) {   // dc=2 at px+7
                        *(__nv_bfloat16*)(xb + 4 * XARR + (px + 7) * XSTR) = h;
                        *(__nv_bfloat16*)(xb + 5 * XARR + (px + 7) * XSTR) = l;
                    }
                }
            }
        }

        for (int tap = 0; tap < 9; tap++) {
            __syncthreads();                   // X build / prior frag reads done
            // copy W hi+lo for (tap, chunk): 512 rows of 64 bf16
            {
                int tc = tap * 4 + chunk;
                #pragma unroll
                for (int rr = 0; rr < 2; rr++) {
                    int r = t + rr * 256;
                    int part = r >> 8, oc = r & 255;
                    const __nv_bfloat16* gsrc = (part ? w2l : w2h) + (size_t)tc * 16384 + oc * 64;
                    const uint4* s = (const uint4*)gsrc;
                    uint4* d = (uint4*)(smem + WOFF + part * WPART + oc * XSTR);
                    #pragma unroll
                    for (int q = 0; q < 8; q++) d[q] = s[q];
                }
            }
            __syncthreads();

            int dr = tap / 3, dc = tap % 3;
            const char* Bbase = smem + (mblk * 6 + dc * 2) * XARR + dr * 8 * XSTR;
            #pragma unroll 1
            for (int pass = 0; pass < 3; pass++) {
                const char* A = smem + WOFF + ((pass == 1) ? WPART : 0);
                const char* Bp = Bbase + ((pass == 2) ? XARR : 0);
                #pragma unroll
                for (int k4 = 0; k4 < 4; k4++) {
                    int kb = (k4 * 16 + 2 * tg) * 2;
                    unsigned af[4][4];
                    #pragma unroll
                    for (int mt = 0; mt < 4; mt++) {
                        const char* ar = A + (ocb + mt * 16 + g) * XSTR + kb;
                        af[mt][0] = *(const unsigned*)ar;
                        af[mt][1] = *(const unsigned*)(ar + 8 * XSTR);
                        af[mt][2] = *(const unsigned*)(ar + 16);
                        af[mt][3] = *(const unsigned*)(ar + 8 * XSTR + 16);
                    }
                    #pragma unroll
                    for (int nt = 0; nt < 8; nt++) {
                        const char* br = Bp + (nt * 8 + g) * XSTR + kb;
                        unsigned b0 = *(const unsigned*)br;
                        unsigned b1 = *(const unsigned*)(br + 16);
                        #pragma unroll
                        for (int mt = 0; mt < 4; mt++)
                            mma16816(acc[mt][nt], af[mt], b0, b1);
                    }
                }
            }
        }
    }

    // readout: bias + relu -> g2buf
    #pragma unroll
    for (int mt = 0; mt < 4; mt++) {
        int oc_a = ocb + mt * 16 + g;
        int oc_b = oc_a + 8;
        float ba = b2[oc_a], bbv = b2[oc_b];
        float* da = g2buf + ((size_t)(blk0 + mblk) * C2 + oc_a) * 64;
        float* db = g2buf + ((size_t)(blk0 + mblk) * C2 + oc_b) * 64;
        #pragma unroll
        for (int nt = 0; nt < 8; nt++) {
            int n0 = nt * 8 + tg * 2;
            float2 e0, e1;
            e0.x = fmaxf(acc[mt][nt][0] + ba, 0.f);
            e0.y = fmaxf(acc[mt][nt][1] + ba, 0.f);
            e1.x = fmaxf(acc[mt][nt][2] + bbv, 0.f);
            e1.y = fmaxf(acc[mt][nt][3] + bbv, 0.f);
            *(float2*)(da + n0) = e0;
            *(float2*)(db + n0) = e1;
        }
    }
}

// ---------------- conv3: 1x1 256->128, FFMA2, BN2 folded ----------------
#define SMEM_C3 ((128 * 64 + 128 * 132) * 4)
__global__ __launch_bounds__(128) void conv3f2_kernel(const float* __restrict__ w3,
                                                      const float* __restrict__ b3) {
    extern __shared__ float sm[];
    float* xs = sm;
    float* ws = sm + 128 * 64;
    int blk = blockIdx.x;
    int t   = threadIdx.x;
    int ocg = t & 15;
    int px0 = (t >> 4) * 8;

    unsigned long long acc[8][4];
    #pragma unroll
    for (int j = 0; j < 8; j++)
        #pragma unroll
        for (int p = 0; p < 4; p++) acc[j][p] = 0ull;

    const float* gsrc = g2buf + (size_t)blk * C2 * 64;

    for (int cc = 0; cc < 2; cc++) {
        __syncthreads();
        for (int i = t; i < 2048; i += 128) {
            int ic = i >> 4, q = i & 15;
            int icg = cc * 128 + ic;
            float4 v = *reinterpret_cast<const float4*>(gsrc + (size_t)icg * 64 + q * 4);
            float a = d_a2[icg], bb = d_b2[icg];
            v.x = a * v.x + bb; v.y = a * v.y + bb;
            v.z = a * v.z + bb; v.w = a * v.w + bb;
            *reinterpret_cast<float4*>(xs + ic * 64 + q * 4) = v;
        }
        for (int i = t; i < 16384; i += 128) {
            int ic = i & 127, oc = i >> 7;
            ws[ic * 132 + oc] = w3[(size_t)oc * C2 + cc * 128 + ic];
        }
        __syncthreads();

        #pragma unroll 2
        for (int ic = 0; ic < 128; ic++) {
            ulonglong2 xa = *reinterpret_cast<const ulonglong2*>(xs + ic * 64 + px0);
            ulonglong2 xb = *reinterpret_cast<const ulonglong2*>(xs + ic * 64 + px0 + 4);
            float4 wlo = *reinterpret_cast<const float4*>(ws + ic * 132 + ocg * 4);
            float4 whi = *reinterpret_cast<const float4*>(ws + ic * 132 + 64 + ocg * 4);
            unsigned long long wd[8];
            wd[0] = dup2(wlo.x); wd[1] = dup2(wlo.y); wd[2] = dup2(wlo.z); wd[3] = dup2(wlo.w);
            wd[4] = dup2(whi.x); wd[5] = dup2(whi.y); wd[6] = dup2(whi.z); wd[7] = dup2(whi.w);
            #pragma unroll
            for (int j = 0; j < 8; j++) {
                acc[j][0] = ffma2(xa.x, wd[j], acc[j][0]);
                acc[j][1] = ffma2(xa.y, wd[j], acc[j][1]);
                acc[j][2] = ffma2(xb.x, wd[j], acc[j][2]);
                acc[j][3] = ffma2(xb.y, wd[j], acc[j][3]);
            }
        }
    }

    float* dst = g3buf + (size_t)blk * COUT * 64;
    #pragma unroll
    for (int j = 0; j < 8; j++) {
        int oc = (j < 4) ? (ocg * 4 + j) : (64 + ocg * 4 + (j - 4));
        float bb = b3[oc];
        float2 p0 = unpk(acc[j][0]), p1 = unpk(acc[j][1]);
        float2 p2 = unpk(acc[j][2]), p3 = unpk(acc[j][3]);
        float4 o1, o2;
        o1.x = fmaxf(p0.x + bb, 0.f); o1.y = fmaxf(p0.y + bb, 0.f);
        o1.z = fmaxf(p1.x + bb, 0.f); o1.w = fmaxf(p1.y + bb, 0.f);
        o2.x = fmaxf(p2.x + bb, 0.f); o2.y = fmaxf(p2.y + bb, 0.f);
        o2.z = fmaxf(p3.x + bb, 0.f); o2.w = fmaxf(p3.y + bb, 0.f);
        *reinterpret_cast<float4*>(dst + oc * 64 + px0)     = o1;
        *reinterpret_cast<float4*>(dst + oc * 64 + px0 + 4) = o2;
    }
}

// ---------------- scatter: BN3(g3) -> image ----------------
__global__ __launch_bounds__(256) void scatter_kernel(const int* __restrict__ abi,
                                                      float* __restrict__ out) {
    int blk = blockIdx.x;
    int n  = abi[blk * 3 + 0];
    int bi = abi[blk * 3 + 1];
    int bj = abi[blk * 3 + 2];
    const float* src = g3buf + (size_t)blk * COUT * 64;
    float* dst = out + (((size_t)(n * COUT)) << 16) + bi * 8 * 256 + bj * 8;
    for (int i = threadIdx.x; i < 2048; i += 256) {
        int c = i >> 4, q = i & 15;
        int r = q >> 1, c4 = (q & 1) * 4;
        float4 v = *reinterpret_cast<const float4*>(src + c * 64 + q * 4);
        float a = d_a3[c], bb = d_b3[c];
        v.x = a * v.x + bb; v.y = a * v.y + bb;
        v.z = a * v.z + bb; v.w = a * v.w + bb;
        *reinterpret_cast<float4*>(dst + (((size_t)c) << 16) + r * 256 + c4) = v;
    }
}

// ---------------- launch ----------------
extern "C" void kernel_launch(void* const* d_in, const int* in_sizes, int n_in,
                              void* d_out, int out_size) {
    const float* x    = (const float*)d_in[0];
    const int*   abi  = (const int*)  d_in[1];
    const float* w_c  = (const float*)d_in[2];
    const float* b_c  = (const float*)d_in[3];
    const float* gm_c = (const float*)d_in[4];
    const float* be_c = (const float*)d_in[5];
    const float* w1   = (const float*)d_in[6];
    const float* b1   = (const float*)d_in[7];
    const float* gm1  = (const float*)d_in[8];
    const float* be1  = (const float*)d_in[9];
    const float* w2   = (const float*)d_in[10];
    const float* b2   = (const float*)d_in[11];
    const float* gm2  = (const float*)d_in[12];
    const float* be2  = (const float*)d_in[13];
    const float* w3   = (const float*)d_in[14];
    const float* b3   = (const float*)d_in[15];
    const float* gm3  = (const float*)d_in[16];
    const float* be3  = (const float*)d_in[17];
    float* out = (float*)d_out;

    cudaFuncSetAttribute(convc_kernel,   cudaFuncAttributeMaxDynamicSharedMemorySize, SMEM_CONVC);
    cudaFuncSetAttribute(conv1f2_kernel, cudaFuncAttributeMaxDynamicSharedMemorySize, SMEM_C1);
    cudaFuncSetAttribute(conv2m_kernel,  cudaFuncAttributeMaxDynamicSharedMemorySize, SMEM_C2M);
    cudaFuncSetAttribute(conv3f2_kernel, cudaFuncAttributeMaxDynamicSharedMemorySize, SMEM_C3);

    zero_stats_kernel<<<1, 256>>>();
    w2cvt_kernel<<<576, 256>>>(w2);

    convc_kernel<<<8192, 256, SMEM_CONVC>>>(x, w_c, b_c, out);
    stats0_kernel<<<128 * 64, 256>>>(out);
    finalize_kernel<<<1, 256>>>(0, gm_c, be_c, 1.0 / 524288.0);
    bnapply_kernel<<<16384, 256>>>(out);

    conv1f2_kernel<<<4096, 256, SMEM_C1>>>(out, abi, w1, b1);
    stats_g1_kernel<<<256 * 32, 256>>>();
    finalize_kernel<<<1, 256>>>(1, gm1, be1, 1.0 / 262144.0);

    conv2m_kernel<<<2048, 256, SMEM_C2M>>>(b2);
    stats_g2_kernel<<<256 * 32, 256>>>();
    finalize_kernel<<<1, 256>>>(2, gm2, be2, 1.0 / 262144.0);

    conv3f2_kernel<<<4096, 128, SMEM_C3>>>(w3, b3);
    stats_g3_kernel<<<128 * 32, 256>>>();
    finalize_kernel<<<1, 256>>>(3, gm3, be3, 1.0 / 262144.0);

    scatter_kernel<<<4096, 256>>>(abi, out);
}

// round 6
// speedup vs baseline: 1.7768x; 1.1011x over previous
#include <cuda_runtime.h>
#include <cuda_bf16.h>
#include <math.h>
#include <stdint.h>

#define B_    8
#define CIN   64
#define COUT  128
#define C2    256
#define HW    65536
#define NBLK  4096
#define EPSV  1e-5f

// ---------------- scratch ----------------
__device__ float g1buf[(size_t)NBLK * C2 * 64];
__device__ float g2buf[(size_t)NBLK * C2 * 64];
__device__ float g3buf[(size_t)NBLK * COUT * 64];

// bf16 hi/lo weights
__device__ __nv_bfloat16 w2h[36 * 16384];   // [tap*4+chunk][oc 256][ic 64]
__device__ __nv_bfloat16 w2l[36 * 16384];
__device__ __nv_bfloat16 w1h[2 * 16384];    // [chunk2][oc 256][ic 64]
__device__ __nv_bfloat16 w1l[2 * 16384];
__device__ __nv_bfloat16 w3h[4 * 8192];     // [chunk4][oc 128][ic 64]
__device__ __nv_bfloat16 w3l[4 * 8192];

__device__ double d_sum0[COUT], d_sq0[COUT];
__device__ double d_sum1[C2],   d_sq1[C2];
__device__ double d_sum2[C2],   d_sq2[C2];
__device__ double d_sum3[COUT], d_sq3[COUT];
__device__ float  d_a0[COUT], d_b0[COUT];
__device__ float  d_a1[C2],   d_b1[C2];
__device__ float  d_a2[C2],   d_b2[C2];
__device__ float  d_a3[COUT], d_b3[COUT];

// ---------------- bf16 HMMA helper ----------------
__device__ __forceinline__ void mma16816(float* d, const unsigned* a, unsigned b0, unsigned b1) {
    asm volatile(
        "mma.sync.aligned.m16n8k16.row.col.f32.bf16.bf16.f32 "
        "{%0,%1,%2,%3}, {%4,%5,%6,%7}, {%8,%9}, {%0,%1,%2,%3};"
        : "+f"(d[0]), "+f"(d[1]), "+f"(d[2]), "+f"(d[3])
        : "r"(a[0]), "r"(a[1]), "r"(a[2]), "r"(a[3]), "r"(b0), "r"(b1));
}

// ---------------- utility ----------------
__global__ void zero_stats_kernel() {
    int t = threadIdx.x;
    if (t < COUT) { d_sum0[t] = 0.0; d_sq0[t] = 0.0; d_sum3[t] = 0.0; d_sq3[t] = 0.0; }
    d_sum1[t] = 0.0; d_sq1[t] = 0.0; d_sum2[t] = 0.0; d_sq2[t] = 0.0;
}

__device__ __forceinline__ void block_reduce_2(float s, float s2, double* gsum, double* gsq) {
    __shared__ float rs[256], rq[256];
    int t = threadIdx.x;
    rs[t] = s; rq[t] = s2;
    __syncthreads();
    for (int o = 128; o > 0; o >>= 1) {
        if (t < o) { rs[t] += rs[t + o]; rq[t] += rq[t + o]; }
        __syncthreads();
    }
    if (t == 0) { atomicAdd(gsum, (double)rs[0]); atomicAdd(gsq, (double)rq[0]); }
}

__global__ void finalize_kernel(int stage, const float* __restrict__ gamma,
                                const float* __restrict__ beta, double invN) {
    int t = threadIdx.x;
    const double *sum, *sq; float *a, *bsh; int C;
    if (stage == 0)      { sum = d_sum0; sq = d_sq0; a = d_a0; bsh = d_b0; C = COUT; }
    else if (stage == 1) { sum = d_sum1; sq = d_sq1; a = d_a1; bsh = d_b1; C = C2; }
    else if (stage == 2) { sum = d_sum2; sq = d_sq2; a = d_a2; bsh = d_b2; C = C2; }
    else                 { sum = d_sum3; sq = d_sq3; a = d_a3; bsh = d_b3; C = COUT; }
    if (t < C) {
        double mean = sum[t] * invN;
        double var  = sq[t] * invN - mean * mean;
        float v = fmaxf((float)var, 0.0f);
        float av = gamma[t] * rsqrtf(v + EPSV);
        a[t] = av;
        bsh[t] = beta[t] - av * (float)mean;
    }
}

// ---------------- weight converts ----------------
__global__ __launch_bounds__(256) void w2cvt_kernel(const float* __restrict__ w2) {
    int i4 = blockIdx.x * 256 + threadIdx.x;
    int ic0 = (i4 & 15) * 4;
    int oc  = (i4 >> 4) & 255;
    int tc  = i4 >> 12;
    int tap = tc >> 2, chunk = tc & 3;
    #pragma unroll
    for (int e = 0; e < 4; e++) {
        int ic = ic0 + e;
        float v = w2[(size_t)oc * 2304 + (chunk * 64 + ic) * 9 + tap];
        __nv_bfloat16 h = __float2bfloat16(v);
        w2h[(size_t)tc * 16384 + oc * 64 + ic] = h;
        w2l[(size_t)tc * 16384 + oc * 64 + ic] = __float2bfloat16(v - __bfloat162float(h));
    }
}

// w1: [256 oc][128 ic] -> [chunk2][oc][64], w3: [128 oc][256 ic] -> [chunk4][oc][64]
__global__ __launch_bounds__(256) void w13cvt_kernel(const float* __restrict__ w1,
                                                     const float* __restrict__ w3) {
    int i = blockIdx.x * 256 + threadIdx.x;   // 0..16383
    {   // w1: 32768 elems, 2 per thread
        #pragma unroll
        for (int e = 0; e < 2; e++) {
            int idx = i * 2 + e;
            int ic = idx & 63, oc = (idx >> 6) & 255, ch = idx >> 14;
            float v = w1[(size_t)oc * 128 + ch * 64 + ic];
            __nv_bfloat16 h = __float2bfloat16(v);
            w1h[idx] = h;
            w1l[idx] = __float2bfloat16(v - __bfloat162float(h));
        }
    }
    {   // w3: 32768 elems
        #pragma unroll
        for (int e = 0; e < 2; e++) {
            int idx = i * 2 + e;
            int ic = idx & 63, oc = (idx >> 6) & 127, ch = idx >> 13;
            float v = w3[(size_t)oc * 256 + ch * 64 + ic];
            __nv_bfloat16 h = __float2bfloat16(v);
            w3h[idx] = h;
            w3l[idx] = __float2bfloat16(v - __bfloat162float(h));
        }
    }
}

// ---------------- K1: 1x1 conv 64->128 + relu full image ----------------
#define SMEM_CONVC ((64 * 64 + 128 * 65) * 4)
__global__ __launch_bounds__(256) void convc_kernel(const float* __restrict__ x,
                                                    const float* __restrict__ wc,
                                                    const float* __restrict__ bc,
                                                    float* __restrict__ out) {
    extern __shared__ float sm[];
    float* xs = sm;
    float* ws = sm + 64 * 64;
    int b  = blockIdx.x >> 10;
    int p0 = (blockIdx.x & 1023) << 6;
    int t  = threadIdx.x;

    for (int i = t; i < 128 * 64; i += 256) {
        int oc = i >> 6, ic = i & 63;
        ws[oc * 65 + ic] = wc[i];
    }
    for (int i = t; i < 1024; i += 256) {
        int ic = i >> 4, q = i & 15;
        float4 v = *reinterpret_cast<const float4*>(x + (((size_t)(b * CIN + ic)) << 16) + p0 + q * 4);
        *reinterpret_cast<float4*>(xs + ic * 64 + q * 4) = v;
    }
    __syncthreads();

    int px0 = (t & 7) * 8;
    int oc0 = (t >> 3) * 4;
    float acc[4][8];
    #pragma unroll
    for (int j = 0; j < 4; j++)
        #pragma unroll
        for (int c = 0; c < 8; c++) acc[j][c] = 0.0f;

    for (int ic = 0; ic < 64; ic++) {
        float4 xa = *reinterpret_cast<float4*>(xs + ic * 64 + px0);
        float4 xb = *reinterpret_cast<float4*>(xs + ic * 64 + px0 + 4);
        #pragma unroll
        for (int j = 0; j < 4; j++) {
            float w = ws[(oc0 + j) * 65 + ic];
            acc[j][0] += w * xa.x; acc[j][1] += w * xa.y;
            acc[j][2] += w * xa.z; acc[j][3] += w * xa.w;
            acc[j][4] += w * xb.x; acc[j][5] += w * xb.y;
            acc[j][6] += w * xb.z; acc[j][7] += w * xb.w;
        }
    }
    float* dstb = out + (((size_t)(b * COUT)) << 16) + p0;
    #pragma unroll
    for (int j = 0; j < 4; j++) {
        int oc = oc0 + j;
        float bb = bc[oc];
        float4 o1, o2;
        o1.x = fmaxf(acc[j][0] + bb, 0.f); o1.y = fmaxf(acc[j][1] + bb, 0.f);
        o1.z = fmaxf(acc[j][2] + bb, 0.f); o1.w = fmaxf(acc[j][3] + bb, 0.f);
        o2.x = fmaxf(acc[j][4] + bb, 0.f); o2.y = fmaxf(acc[j][5] + bb, 0.f);
        o2.z = fmaxf(acc[j][6] + bb, 0.f); o2.w = fmaxf(acc[j][7] + bb, 0.f);
        *reinterpret_cast<float4*>(dstb + (((size_t)oc) << 16) + px0)     = o1;
        *reinterpret_cast<float4*>(dstb + (((size_t)oc) << 16) + px0 + 4) = o2;
    }
}

__global__ __launch_bounds__(256) void stats0_kernel(const float* __restrict__ y) {
    int c   = blockIdx.x & 127;
    int seg = blockIdx.x >> 7;
    int b   = seg >> 3;
    int off = (seg & 7) << 13;
    const float4* p = reinterpret_cast<const float4*>(y + (((size_t)(b * COUT + c)) << 16) + off);
    float s = 0.f, s2 = 0.f;
    for (int i = threadIdx.x; i < 2048; i += 256) {
        float4 v = p[i];
        s  += v.x + v.y + v.z + v.w;
        s2 += v.x * v.x + v.y * v.y + v.z * v.z + v.w * v.w;
    }
    block_reduce_2(s, s2, &d_sum0[c], &d_sq0[c]);
}

__global__ __launch_bounds__(256) void bnapply_kernel(float* __restrict__ y) {
    int nth = gridDim.x * blockDim.x;
    int total = (B_ * COUT * HW) / 4;
    for (int i = blockIdx.x * blockDim.x + threadIdx.x; i < total; i += nth) {
        int c = (i >> 14) & 127;
        float4 v = reinterpret_cast<float4*>(y)[i];
        float a = d_a0[c], bb = d_b0[c];
        v.x = a * v.x + bb; v.y = a * v.y + bb;
        v.z = a * v.z + bb; v.w = a * v.w + bb;
        reinterpret_cast<float4*>(y)[i] = v;
    }
}

// ---------------- stats over [NBLK][C][64] ----------------
__device__ __forceinline__ void stats_body(const float* __restrict__ buf, int C,
                                           double* gsum, double* gsq) {
    int c    = blockIdx.x % C;
    int seg  = blockIdx.x / C;
    int blk0 = seg * 128;
    float s = 0.f, s2 = 0.f;
    for (int i = threadIdx.x; i < 128 * 16; i += 256) {
        int bo = i >> 4, q = i & 15;
        float4 v = *reinterpret_cast<const float4*>(buf + ((size_t)(blk0 + bo) * C + c) * 64 + q * 4);
        s  += v.x + v.y + v.z + v.w;
        s2 += v.x * v.x + v.y * v.y + v.z * v.z + v.w * v.w;
    }
    block_reduce_2(s, s2, &gsum[c], &gsq[c]);
}
__global__ __launch_bounds__(256) void stats_g1_kernel() { stats_body(g1buf, C2,   d_sum1, d_sq1); }
__global__ __launch_bounds__(256) void stats_g2_kernel() { stats_body(g2buf, C2,   d_sum2, d_sq2); }
__global__ __launch_bounds__(256) void stats_g3_kernel() { stats_body(g3buf, COUT, d_sum3, d_sq3); }

// ---------------- conv1: gather + 1x1 128->256 via HMMA, 2 blocks/CTA ----------------
// X: [blk2][part2][px64][ic 72] = 2*18432 = 36864 B ; W @36864: [part2][oc256][72] = 73728 B
#define X1STR  144
#define X1PART 9216
#define X1BLK  18432
#define W1OFF  36864
#define W1PART 36864
#define SMEM_C1M (W1OFF + 2 * W1PART)
__global__ __launch_bounds__(256, 1) void conv1m_kernel(const float* __restrict__ xbn,
                                                        const int* __restrict__ abi,
                                                        const float* __restrict__ b1) {
    extern __shared__ float smf[];
    char* smem = (char*)smf;
    int t = threadIdx.x, w = t >> 5, lane = t & 31;
    int g = lane >> 2, tg = lane & 3;
    int blk0 = blockIdx.x * 2;
    int mblk = w >> 2;
    int ocb  = (w & 3) * 64;

    float acc[4][8][4];
    #pragma unroll
    for (int mt = 0; mt < 4; mt++)
        #pragma unroll
        for (int nt = 0; nt < 8; nt++)
            #pragma unroll
            for (int e = 0; e < 4; e++) acc[mt][nt][e] = 0.0f;

    int brow = t >> 1, bsub = t & 1;
    int xblk = brow >> 6, xic = brow & 63;
    int n_  = abi[(blk0 + xblk) * 3 + 0];
    int bi_ = abi[(blk0 + xblk) * 3 + 1];
    int bj_ = abi[(blk0 + xblk) * 3 + 2];
    const float* gsrc0 = xbn + (((size_t)(n_ * COUT)) << 16) + bi_ * 2048 + bj_ * 8;

    for (int chunk = 0; chunk < 2; chunk++) {
        __syncthreads();
        // X build: thread handles (xblk, xic), 32 px (4 rows of 8)
        {
            int icg = chunk * 64 + xic;
            const float* src = gsrc0 + (((size_t)icg) << 16) + bsub * 4 * 256;
            char* xb = smem + xblk * X1BLK + xic * 2;
            #pragma unroll
            for (int r4 = 0; r4 < 4; r4++) {
                float4 u  = *reinterpret_cast<const float4*>(src + r4 * 256);
                float4 v2 = *reinterpret_cast<const float4*>(src + r4 * 256 + 4);
                float vals[8] = {u.x, u.y, u.z, u.w, v2.x, v2.y, v2.z, v2.w};
                int px0 = bsub * 32 + r4 * 8;
                #pragma unroll
                for (int e = 0; e < 8; e++) {
                    float xv = vals[e];
                    __nv_bfloat16 h = __float2bfloat16(xv);
                    __nv_bfloat16 l = __float2bfloat16(xv - __bfloat162float(h));
                    *(__nv_bfloat16*)(xb + (px0 + e) * X1STR) = h;
                    *(__nv_bfloat16*)(xb + X1PART + (px0 + e) * X1STR) = l;
                }
            }
        }
        // W copy: 512 rows of 128B
        #pragma unroll
        for (int rr = 0; rr < 2; rr++) {
            int r = t + rr * 256;
            int part = r >> 8, oc = r & 255;
            const __nv_bfloat16* ws = (part ? w1l : w1h) + (size_t)chunk * 16384 + oc * 64;
            const uint4* s = (const uint4*)ws;
            uint4* d = (uint4*)(smem + W1OFF + part * W1PART + oc * X1STR);
            #pragma unroll
            for (int q = 0; q < 8; q++) d[q] = s[q];
        }
        __syncthreads();

        #pragma unroll 1
        for (int pass = 0; pass < 3; pass++) {
            const char* A  = smem + W1OFF + ((pass == 1) ? W1PART : 0);
            const char* Bp = smem + mblk * X1BLK + ((pass == 2) ? X1PART : 0);
            #pragma unroll
            for (int k4 = 0; k4 < 4; k4++) {
                int kb = (k4 * 16 + 2 * tg) * 2;
                unsigned af[4][4];
                #pragma unroll
                for (int mt = 0; mt < 4; mt++) {
                    const char* ar = A + (ocb + mt * 16 + g) * X1STR + kb;
                    af[mt][0] = *(const unsigned*)ar;
                    af[mt][1] = *(const unsigned*)(ar + 8 * X1STR);
                    af[mt][2] = *(const unsigned*)(ar + 16);
                    af[mt][3] = *(const unsigned*)(ar + 8 * X1STR + 16);
                }
                #pragma unroll
                for (int nt = 0; nt < 8; nt++) {
                    const char* br = Bp + (nt * 8 + g) * X1STR + kb;
                    unsigned b0 = *(const unsigned*)br;
                    unsigned b1v = *(const unsigned*)(br + 16);
                    #pragma unroll
                    for (int mt = 0; mt < 4; mt++)
                        mma16816(acc[mt][nt], af[mt], b0, b1v);
                }
            }
        }
    }

    #pragma unroll
    for (int mt = 0; mt < 4; mt++) {
        int oc_a = ocb + mt * 16 + g;
        int oc_b = oc_a + 8;
        float ba = b1[oc_a], bbv = b1[oc_b];
        float* da = g1buf + ((size_t)(blk0 + mblk) * C2 + oc_a) * 64;
        float* db = g1buf + ((size_t)(blk0 + mblk) * C2 + oc_b) * 64;
        #pragma unroll
        for (int nt = 0; nt < 8; nt++) {
            int n0 = nt * 8 + tg * 2;
            float2 e0, e1;
            e0.x = fmaxf(acc[mt][nt][0] + ba, 0.f);
            e0.y = fmaxf(acc[mt][nt][1] + ba, 0.f);
            e1.x = fmaxf(acc[mt][nt][2] + bbv, 0.f);
            e1.y = fmaxf(acc[mt][nt][3] + bbv, 0.f);
            *(float2*)(da + n0) = e0;
            *(float2*)(db + n0) = e1;
        }
    }
}

// ---------------- conv2: 3x3 via mma.sync bf16 hi/lo, 2 blocks/CTA ----------------
#define XSTR   144
#define XARR   11520
#define WOFF   138240
#define WPART  36864
#define SMEM_C2M (WOFF + 2 * WPART)
__global__ __launch_bounds__(256, 1) void conv2m_kernel(const float* __restrict__ b2) {
    extern __shared__ float smf[];
    char* smem = (char*)smf;
    int t = threadIdx.x, w = t >> 5, lane = t & 31;
    int g = lane >> 2, tg = lane & 3;
    int blk0 = blockIdx.x * 2;
    int mblk = w >> 2;
    int ocb  = (w & 3) * 64;

    float acc[4][8][4];
    #pragma unroll
    for (int mt = 0; mt < 4; mt++)
        #pragma unroll
        for (int nt = 0; nt < 8; nt++)
            #pragma unroll
            for (int e = 0; e < 4; e++) acc[mt][nt][e] = 0.0f;

    int brow = t >> 1, bsub = t & 1;
    int xblk = brow >> 6, xic = brow & 63;

    for (int chunk = 0; chunk < 4; chunk++) {
        __syncthreads();
        for (int i = t; i < WOFF / 16; i += 256) ((uint4*)smem)[i] = make_uint4(0, 0, 0, 0);
        __syncthreads();

        {
            int icg = chunk * 64 + xic;
            const float* src = g1buf + ((size_t)(blk0 + xblk) * C2 + icg) * 64 + bsub * 32;
            float a = d_a1[icg], bb = d_b1[icg];
            char* xb = smem + xblk * 6 * XARR + xic * 2;
            #pragma unroll
            for (int j = 0; j < 8; j++) {
                float4 v4 = ((const float4*)src)[j];
                float vals[4] = {v4.x, v4.y, v4.z, v4.w};
                #pragma unroll
                for (int e = 0; e < 4; e++) {
                    int px = bsub * 32 + j * 4 + e;
                    float xv = a * vals[e] + bb;
                    __nv_bfloat16 h = __float2bfloat16(xv);
                    __nv_bfloat16 l = __float2bfloat16(xv - __bfloat162float(h));
                    int col = px & 7;
                    *(__nv_bfloat16*)(xb + 2 * XARR + (px + 8) * XSTR) = h;
                    *(__nv_bfloat16*)(xb + 3 * XARR + (px + 8) * XSTR) = l;
                    if (col != 7) {
                        *(__nv_bfloat16*)(xb + 0 * XARR + (px + 9) * XSTR) = h;
                        *(__nv_bfloat16*)(xb + 1 * XARR + (px + 9) * XSTR) = l;
                    }
                    if (col != 0) {
                        *(__nv_bfloat16*)(xb + 4 * XARR + (px + 7) * XSTR) = h;
                        *(__nv_bfloat16*)(xb + 5 * XARR + (px + 7) * XSTR) = l;
                    }
                }
            }
        }

        for (int tap = 0; tap < 9; tap++) {
            __syncthreads();
            {
                int tc = tap * 4 + chunk;
                #pragma unroll
                for (int rr = 0; rr < 2; rr++) {
                    int r = t + rr * 256;
                    int part = r >> 8, oc = r & 255;
                    const __nv_bfloat16* gsrc = (part ? w2l : w2h) + (size_t)tc * 16384 + oc * 64;
                    const uint4* s = (const uint4*)gsrc;
                    uint4* d = (uint4*)(smem + WOFF + part * WPART + oc * XSTR);
                    #pragma unroll
                    for (int q = 0; q < 8; q++) d[q] = s[q];
                }
            }
            __syncthreads();

            int dr = tap / 3, dc = tap % 3;
            const char* Bbase = smem + (mblk * 6 + dc * 2) * XARR + dr * 8 * XSTR;
            #pragma unroll 1
            for (int pass = 0; pass < 3; pass++) {
                const char* A = smem + WOFF + ((pass == 1) ? WPART : 0);
                const char* Bp = Bbase + ((pass == 2) ? XARR : 0);
                #pragma unroll
                for (int k4 = 0; k4 < 4; k4++) {
                    int kb = (k4 * 16 + 2 * tg) * 2;
                    unsigned af[4][4];
                    #pragma unroll
                    for (int mt = 0; mt < 4; mt++) {
                        const char* ar = A + (ocb + mt * 16 + g) * XSTR + kb;
                        af[mt][0] = *(const unsigned*)ar;
                        af[mt][1] = *(const unsigned*)(ar + 8 * XSTR);
                        af[mt][2] = *(const unsigned*)(ar + 16);
                        af[mt][3] = *(const unsigned*)(ar + 8 * XSTR + 16);
                    }
                    #pragma unroll
                    for (int nt = 0; nt < 8; nt++) {
                        const char* br = Bp + (nt * 8 + g) * XSTR + kb;
                        unsigned b0 = *(const unsigned*)br;
                        unsigned b1 = *(const unsigned*)(br + 16);
                        #pragma unroll
                        for (int mt = 0; mt < 4; mt++)
                            mma16816(acc[mt][nt], af[mt], b0, b1);
                    }
                }
            }
        }
    }

    #pragma unroll
    for (int mt = 0; mt < 4; mt++) {
        int oc_a = ocb + mt * 16 + g;
        int oc_b = oc_a + 8;
        float ba = b2[oc_a], bbv = b2[oc_b];
        float* da = g2buf + ((size_t)(blk0 + mblk) * C2 + oc_a) * 64;
        float* db = g2buf + ((size_t)(blk0 + mblk) * C2 + oc_b) * 64;
        #pragma unroll
        for (int nt = 0; nt < 8; nt++) {
            int n0 = nt * 8 + tg * 2;
            float2 e0, e1;
            e0.x = fmaxf(acc[mt][nt][0] + ba, 0.f);
            e0.y = fmaxf(acc[mt][nt][1] + ba, 0.f);
            e1.x = fmaxf(acc[mt][nt][2] + bbv, 0.f);
            e1.y = fmaxf(acc[mt][nt][3] + bbv, 0.f);
            *(float2*)(da + n0) = e0;
            *(float2*)(db + n0) = e1;
        }
    }
}

// ---------------- conv3: 1x1 256->128 via HMMA, 4 blocks/CTA, BN2 folded ----------------
// X: [blk4][part2][px64][ic72] = 4*18432 = 73728 ; W @73728: [part2][oc128][72] = 36864
#define X3BLK  18432
#define W3OFF  73728
#define W3PART 18432
#define SMEM_C3M (W3OFF + 2 * W3PART)
__global__ __launch_bounds__(256, 1) void conv3m_kernel(const float* __restrict__ b3) {
    extern __shared__ float smf[];
    char* smem = (char*)smf;
    int t = threadIdx.x, w = t >> 5, lane = t & 31;
    int g = lane >> 2, tg = lane & 3;
    int blk0 = blockIdx.x * 4;
    int mblk = w >> 1;
    int ocb  = (w & 1) * 64;

    float acc[4][8][4];
    #pragma unroll
    for (int mt = 0; mt < 4; mt++)
        #pragma unroll
        for (int nt = 0; nt < 8; nt++)
            #pragma unroll
            for (int e = 0; e < 4; e++) acc[mt][nt][e] = 0.0f;

    int xblk = t >> 6, xic = t & 63;

    for (int chunk = 0; chunk < 4; chunk++) {
        __syncthreads();
        {
            int icg = chunk * 64 + xic;
            const float* src = g2buf + ((size_t)(blk0 + xblk) * C2 + icg) * 64;
            float a = d_a2[icg], bb = d_b2[icg];
            char* xb = smem + xblk * X3BLK + xic * 2;
            #pragma unroll
            for (int j = 0; j < 16; j++) {
                float4 v4 = ((const float4*)src)[j];
                float vals[4] = {v4.x, v4.y, v4.z, v4.w};
                #pragma unroll
                for (int e = 0; e < 4; e++) {
                    int px = j * 4 + e;
                    float xv = a * vals[e] + bb;
                    __nv_bfloat16 h = __float2bfloat16(xv);
                    __nv_bfloat16 l = __float2bfloat16(xv - __bfloat162float(h));
                    *(__nv_bfloat16*)(xb + px * X1STR) = h;
                    *(__nv_bfloat16*)(xb + X1PART + px * X1STR) = l;
                }
            }
        }
        // W copy: 256 rows of 128B
        {
            int part = t >> 7, oc = t & 127;
            const __nv_bfloat16* ws = (part ? w3l : w3h) + (size_t)chunk * 8192 + oc * 64;
            const uint4* s = (const uint4*)ws;
            uint4* d = (uint4*)(smem + W3OFF + part * W3PART + oc * X1STR);
            #pragma unroll
            for (int q = 0; q < 8; q++) d[q] = s[q];
        }
        __syncthreads();

        #pragma unroll 1
        for (int pass = 0; pass < 3; pass++) {
            const char* A  = smem + W3OFF + ((pass == 1) ? W3PART : 0);
            const char* Bp = smem + mblk * X3BLK + ((pass == 2) ? X1PART : 0);
            #pragma unroll
            for (int k4 = 0; k4 < 4; k4++) {
                int kb = (k4 * 16 + 2 * tg) * 2;
                unsigned af[4][4];
                #pragma unroll
                for (int mt = 0; mt < 4; mt++) {
                    const char* ar = A + (ocb + mt * 16 + g) * X1STR + kb;
                    af[mt][0] = *(const unsigned*)ar;
                    af[mt][1] = *(const unsigned*)(ar + 8 * X1STR);
                    af[mt][2] = *(const unsigned*)(ar + 16);
                    af[mt][3] = *(const unsigned*)(ar + 8 * X1STR + 16);
                }
                #pragma unroll
                for (int nt = 0; nt < 8; nt++) {
                    const char* br = Bp + (nt * 8 + g) * X1STR + kb;
                    unsigned b0 = *(const unsigned*)br;
                    unsigned b1v = *(const unsigned*)(br + 16);
                    #pragma unroll
                    for (int mt = 0; mt < 4; mt++)
                        mma16816(acc[mt][nt], af[mt], b0, b1v);
                }
            }
        }
    }

    #pragma unroll
    for (int mt = 0; mt < 4; mt++) {
        int oc_a = ocb + mt * 16 + g;
        int oc_b = oc_a + 8;
        float ba = b3[oc_a], bbv = b3[oc_b];
        float* da = g3buf + ((size_t)(blk0 + mblk) * COUT + oc_a) * 64;
        float* db = g3buf + ((size_t)(blk0 + mblk) * COUT + oc_b) * 64;
        #pragma unroll
        for (int nt = 0; nt < 8; nt++) {
            int n0 = nt * 8 + tg * 2;
            float2 e0, e1;
            e0.x = fmaxf(acc[mt][nt][0] + ba, 0.f);
            e0.y = fmaxf(acc[mt][nt][1] + ba, 0.f);
            e1.x = fmaxf(acc[mt][nt][2] + bbv, 0.f);
            e1.y = fmaxf(acc[mt][nt][3] + bbv, 0.f);
            *(float2*)(da + n0) = e0;
            *(float2*)(db + n0) = e1;
        }
    }
}

// ---------------- scatter: BN3(g3) -> image ----------------
__global__ __launch_bounds__(256) void scatter_kernel(const int* __restrict__ abi,
                                                      float* __restrict__ out) {
    int blk = blockIdx.x;
    int n  = abi[blk * 3 + 0];
    int bi = abi[blk * 3 + 1];
    int bj = abi[blk * 3 + 2];
    const float* src = g3buf + (size_t)blk * COUT * 64;
    float* dst = out + (((size_t)(n * COUT)) << 16) + bi * 8 * 256 + bj * 8;
    for (int i = threadIdx.x; i < 2048; i += 256) {
        int c = i >> 4, q = i & 15;
        int r = q >> 1, c4 = (q & 1) * 4;
        float4 v = *reinterpret_cast<const float4*>(src + c * 64 + q * 4);
        float a = d_a3[c], bb = d_b3[c];
        v.x = a * v.x + bb; v.y = a * v.y + bb;
        v.z = a * v.z + bb; v.w = a * v.w + bb;
        *reinterpret_cast<float4*>(dst + (((size_t)c) << 16) + r * 256 + c4) = v;
    }
}

// ---------------- launch ----------------
extern "C" void kernel_launch(void* const* d_in, const int* in_sizes, int n_in,
                              void* d_out, int out_size) {
    const float* x    = (const float*)d_in[0];
    const int*   abi  = (const int*)  d_in[1];
    const float* w_c  = (const float*)d_in[2];
    const float* b_c  = (const float*)d_in[3];
    const float* gm_c = (const float*)d_in[4];
    const float* be_c = (const float*)d_in[5];
    const float* w1   = (const float*)d_in[6];
    const float* b1   = (const float*)d_in[7];
    const float* gm1  = (const float*)d_in[8];
    const float* be1  = (const float*)d_in[9];
    const float* w2   = (const float*)d_in[10];
    const float* b2   = (const float*)d_in[11];
    const float* gm2  = (const float*)d_in[12];
    const float* be2  = (const float*)d_in[13];
    const float* w3   = (const float*)d_in[14];
    const float* b3   = (const float*)d_in[15];
    const float* gm3  = (const float*)d_in[16];
    const float* be3  = (const float*)d_in[17];
    float* out = (float*)d_out;

    cudaFuncSetAttribute(convc_kernel,  cudaFuncAttributeMaxDynamicSharedMemorySize, SMEM_CONVC);
    cudaFuncSetAttribute(conv1m_kernel, cudaFuncAttributeMaxDynamicSharedMemorySize, SMEM_C1M);
    cudaFuncSetAttribute(conv2m_kernel, cudaFuncAttributeMaxDynamicSharedMemorySize, SMEM_C2M);
    cudaFuncSetAttribute(conv3m_kernel, cudaFuncAttributeMaxDynamicSharedMemorySize, SMEM_C3M);

    zero_stats_kernel<<<1, 256>>>();
    w2cvt_kernel<<<576, 256>>>(w2);
    w13cvt_kernel<<<64, 256>>>(w1, w3);

    convc_kernel<<<8192, 256, SMEM_CONVC>>>(x, w_c, b_c, out);
    stats0_kernel<<<128 * 64, 256>>>(out);
    finalize_kernel<<<1, 256>>>(0, gm_c, be_c, 1.0 / 524288.0);
    bnapply_kernel<<<16384, 256>>>(out);

    conv1m_kernel<<<2048, 256, SMEM_C1M>>>(out, abi, b1);
    stats_g1_kernel<<<256 * 32, 256>>>();
    finalize_kernel<<<1, 256>>>(1, gm1, be1, 1.0 / 262144.0);

    conv2m_kernel<<<2048, 256, SMEM_C2M>>>(b2);
    stats_g2_kernel<<<256 * 32, 256>>>();
    finalize_kernel<<<1, 256>>>(2, gm2, be2, 1.0 / 262144.0);

    conv3m_kernel<<<1024, 256, SMEM_C3M>>>(b3);
    stats_g3_kernel<<<128 * 32, 256>>>();
    finalize_kernel<<<1, 256>>>(3, gm3, be3, 1.0 / 262144.0);

    scatter_kernel<<<4096, 256>>>(abi, out);
}

// round 7
// speedup vs baseline: 1.9849x; 1.1171x over previous
#include <cuda_runtime.h>
#include <cuda_bf16.h>
#include <math.h>
#include <stdint.h>

#define B_    8
#define CIN   64
#define COUT  128
#define C2    256
#define HW    65536
#define NBLK  4096
#define EPSV  1e-5f

// ---------------- scratch ----------------
__device__ float g1buf[(size_t)NBLK * C2 * 64];
__device__ float g2buf[(size_t)NBLK * C2 * 64];
__device__ float g3buf[(size_t)NBLK * COUT * 64];

// bf16 hi/lo weights
__device__ __nv_bfloat16 w2h[36 * 16384];   // [tap*4+chunk][oc 256][ic 64]
__device__ __nv_bfloat16 w2l[36 * 16384];
__device__ __nv_bfloat16 w1h[2 * 16384];    // [chunk2][oc 256][ic 64]
__device__ __nv_bfloat16 w1l[2 * 16384];
__device__ __nv_bfloat16 w3h[4 * 8192];     // [chunk4][oc 128][ic 64]
__device__ __nv_bfloat16 w3l[4 * 8192];

__device__ double d_sum0[COUT], d_sq0[COUT];
__device__ double d_sum1[C2],   d_sq1[C2];
__device__ double d_sum2[C2],   d_sq2[C2];
__device__ double d_sum3[COUT], d_sq3[COUT];
__device__ float  d_a0[COUT], d_b0[COUT];
__device__ float  d_a1[C2],   d_b1[C2];
__device__ float  d_a2[C2],   d_b2[C2];
__device__ float  d_a3[COUT], d_b3[COUT];

#define PKU(x, y) ((unsigned)(x) | ((unsigned)(y) << 16))

// ---------------- bf16 HMMA helper ----------------
__device__ __forceinline__ void mma16816(float* d, const unsigned* a, unsigned b0, unsigned b1) {
    asm volatile(
        "mma.sync.aligned.m16n8k16.row.col.f32.bf16.bf16.f32 "
        "{%0,%1,%2,%3}, {%4,%5,%6,%7}, {%8,%9}, {%0,%1,%2,%3};"
        : "+f"(d[0]), "+f"(d[1]), "+f"(d[2]), "+f"(d[3])
        : "r"(a[0]), "r"(a[1]), "r"(a[2]), "r"(a[3]), "r"(b0), "r"(b1));
}

// quad-shuffle reduce (lanes tg=0..3 within a quad share a channel), then atomic
__device__ __forceinline__ void quad_stats(float s, float s2, int tg,
                                           double* gsum, double* gsq) {
    s  += __shfl_xor_sync(0xffffffffu, s, 1);
    s  += __shfl_xor_sync(0xffffffffu, s, 2);
    s2 += __shfl_xor_sync(0xffffffffu, s2, 1);
    s2 += __shfl_xor_sync(0xffffffffu, s2, 2);
    if (tg == 0) { atomicAdd(gsum, (double)s); atomicAdd(gsq, (double)s2); }
}

// ---------------- utility ----------------
__global__ void zero_stats_kernel() {
    int t = threadIdx.x;
    if (t < COUT) { d_sum0[t] = 0.0; d_sq0[t] = 0.0; d_sum3[t] = 0.0; d_sq3[t] = 0.0; }
    d_sum1[t] = 0.0; d_sq1[t] = 0.0; d_sum2[t] = 0.0; d_sq2[t] = 0.0;
}

__global__ void finalize_kernel(int stage, const float* __restrict__ gamma,
                                const float* __restrict__ beta, double invN) {
    int t = threadIdx.x;
    const double *sum, *sq; float *a, *bsh; int C;
    if (stage == 0)      { sum = d_sum0; sq = d_sq0; a = d_a0; bsh = d_b0; C = COUT; }
    else if (stage == 1) { sum = d_sum1; sq = d_sq1; a = d_a1; bsh = d_b1; C = C2; }
    else if (stage == 2) { sum = d_sum2; sq = d_sq2; a = d_a2; bsh = d_b2; C = C2; }
    else                 { sum = d_sum3; sq = d_sq3; a = d_a3; bsh = d_b3; C = COUT; }
    if (t < C) {
        double mean = sum[t] * invN;
        double var  = sq[t] * invN - mean * mean;
        float v = fmaxf((float)var, 0.0f);
        float av = gamma[t] * rsqrtf(v + EPSV);
        a[t] = av;
        bsh[t] = beta[t] - av * (float)mean;
    }
}

// ---------------- weight converts ----------------
__global__ __launch_bounds__(256) void w2cvt_kernel(const float* __restrict__ w2) {
    int i4 = blockIdx.x * 256 + threadIdx.x;
    int ic0 = (i4 & 15) * 4;
    int oc  = (i4 >> 4) & 255;
    int tc  = i4 >> 12;
    int tap = tc >> 2, chunk = tc & 3;
    #pragma unroll
    for (int e = 0; e < 4; e++) {
        int ic = ic0 + e;
        float v = w2[(size_t)oc * 2304 + (chunk * 64 + ic) * 9 + tap];
        __nv_bfloat16 h = __float2bfloat16(v);
        w2h[(size_t)tc * 16384 + oc * 64 + ic] = h;
        w2l[(size_t)tc * 16384 + oc * 64 + ic] = __float2bfloat16(v - __bfloat162float(h));
    }
}

__global__ __launch_bounds__(256) void w13cvt_kernel(const float* __restrict__ w1,
                                                     const float* __restrict__ w3) {
    int i = blockIdx.x * 256 + threadIdx.x;
    {
        #pragma unroll
        for (int e = 0; e < 2; e++) {
            int idx = i * 2 + e;
            int ic = idx & 63, oc = (idx >> 6) & 255, ch = idx >> 14;
            float v = w1[(size_t)oc * 128 + ch * 64 + ic];
            __nv_bfloat16 h = __float2bfloat16(v);
            w1h[idx] = h;
            w1l[idx] = __float2bfloat16(v - __bfloat162float(h));
        }
    }
    {
        #pragma unroll
        for (int e = 0; e < 2; e++) {
            int idx = i * 2 + e;
            int ic = idx & 63, oc = (idx >> 6) & 127, ch = idx >> 13;
            float v = w3[(size_t)oc * 256 + ch * 64 + ic];
            __nv_bfloat16 h = __float2bfloat16(v);
            w3h[idx] = h;
            w3l[idx] = __float2bfloat16(v - __bfloat162float(h));
        }
    }
}

// ---------------- K1: 1x1 conv 64->128 + relu full image, 16 px/thread, fused stats ----------------
#define SMEM_CONVC ((64 * 128 + 128 * 65) * 4)
__global__ __launch_bounds__(256) void convc_kernel(const float* __restrict__ x,
                                                    const float* __restrict__ wc,
                                                    const float* __restrict__ bc,
                                                    float* __restrict__ out) {
    extern __shared__ float sm[];
    float* xs = sm;                 // [64 ic][128 px]
    float* ws = sm + 64 * 128;      // [128 oc][65]
    int b  = blockIdx.x >> 9;
    int p0 = (blockIdx.x & 511) << 7;
    int t  = threadIdx.x;

    for (int i = t; i < 128 * 64; i += 256) {
        int oc = i >> 6, ic = i & 63;
        ws[oc * 65 + ic] = wc[i];
    }
    for (int i = t; i < 2048; i += 256) {
        int ic = i >> 5, q = i & 31;
        float4 v = *reinterpret_cast<const float4*>(x + (((size_t)(b * CIN + ic)) << 16) + p0 + q * 4);
        *reinterpret_cast<float4*>(xs + ic * 128 + q * 4) = v;
    }
    __syncthreads();

    int px0 = (t & 7) * 16;
    int oc0 = (t >> 3) * 4;
    float acc[4][16];
    #pragma unroll
    for (int j = 0; j < 4; j++)
        #pragma unroll
        for (int c = 0; c < 16; c++) acc[j][c] = 0.0f;

    for (int ic = 0; ic < 64; ic++) {
        float xv[16];
        #pragma unroll
        for (int q = 0; q < 4; q++) {
            float4 v = *reinterpret_cast<float4*>(xs + ic * 128 + px0 + q * 4);
            xv[q * 4 + 0] = v.x; xv[q * 4 + 1] = v.y; xv[q * 4 + 2] = v.z; xv[q * 4 + 3] = v.w;
        }
        #pragma unroll
        for (int j = 0; j < 4; j++) {
            float w = ws[(oc0 + j) * 65 + ic];
            #pragma unroll
            for (int c = 0; c < 16; c++) acc[j][c] += w * xv[c];
        }
    }
    float* dstb = out + (((size_t)(b * COUT)) << 16) + p0;
    float sj[4], qj[4];
    #pragma unroll
    for (int j = 0; j < 4; j++) {
        int oc = oc0 + j;
        float bb = bc[oc];
        float s = 0.f, q2 = 0.f;
        #pragma unroll
        for (int q = 0; q < 4; q++) {
            float4 o;
            o.x = fmaxf(acc[j][q * 4 + 0] + bb, 0.f);
            o.y = fmaxf(acc[j][q * 4 + 1] + bb, 0.f);
            o.z = fmaxf(acc[j][q * 4 + 2] + bb, 0.f);
            o.w = fmaxf(acc[j][q * 4 + 3] + bb, 0.f);
            s  += o.x + o.y + o.z + o.w;
            q2 += o.x * o.x + o.y * o.y + o.z * o.z + o.w * o.w;
            *reinterpret_cast<float4*>(dstb + (((size_t)oc) << 16) + px0 + q * 4) = o;
        }
        sj[j] = s; qj[j] = q2;
    }
    // reduce over the 8 lanes sharing oc0 (low 3 lane bits), then atomics
    #pragma unroll
    for (int j = 0; j < 4; j++) {
        float s = sj[j], q2 = qj[j];
        s  += __shfl_xor_sync(0xffffffffu, s, 1);
        s  += __shfl_xor_sync(0xffffffffu, s, 2);
        s  += __shfl_xor_sync(0xffffffffu, s, 4);
        q2 += __shfl_xor_sync(0xffffffffu, q2, 1);
        q2 += __shfl_xor_sync(0xffffffffu, q2, 2);
        q2 += __shfl_xor_sync(0xffffffffu, q2, 4);
        if ((t & 7) == 0) {
            atomicAdd(&d_sum0[oc0 + j], (double)s);
            atomicAdd(&d_sq0[oc0 + j],  (double)q2);
        }
    }
}

__global__ __launch_bounds__(256) void bnapply_kernel(float* __restrict__ y) {
    int nth = gridDim.x * blockDim.x;
    int total = (B_ * COUT * HW) / 4;
    for (int i = blockIdx.x * blockDim.x + threadIdx.x; i < total; i += nth) {
        int c = (i >> 14) & 127;
        float4 v = reinterpret_cast<float4*>(y)[i];
        float a = d_a0[c], bb = d_b0[c];
        v.x = a * v.x + bb; v.y = a * v.y + bb;
        v.z = a * v.z + bb; v.w = a * v.w + bb;
        reinterpret_cast<float4*>(y)[i] = v;
    }
}

// ---------------- conv1: gather + 1x1 128->256 via HMMA, 2 blocks/CTA, fused stats ----------------
#define X1STR  144
#define X1PART 9216
#define X1BLK  18432
#define W1OFF  36864
#define W1PART 36864
#define SMEM_C1M (W1OFF + 2 * W1PART)
__global__ __launch_bounds__(256, 1) void conv1m_kernel(const float* __restrict__ xbn,
                                                        const int* __restrict__ abi,
                                                        const float* __restrict__ b1) {
    extern __shared__ float smf[];
    char* smem = (char*)smf;
    int t = threadIdx.x, w = t >> 5, lane = t & 31;
    int g = lane >> 2, tg = lane & 3;
    int blk0 = blockIdx.x * 2;
    int mblk = w >> 2;
    int ocb  = (w & 3) * 64;

    float acc[4][8][4];
    #pragma unroll
    for (int mt = 0; mt < 4; mt++)
        #pragma unroll
        for (int nt = 0; nt < 8; nt++)
            #pragma unroll
            for (int e = 0; e < 4; e++) acc[mt][nt][e] = 0.0f;

    int brow = t >> 1, bsub = t & 1;
    int xblk = brow >> 6, xic = brow & 63;
    int n_  = abi[(blk0 + xblk) * 3 + 0];
    int bi_ = abi[(blk0 + xblk) * 3 + 1];
    int bj_ = abi[(blk0 + xblk) * 3 + 2];
    const float* gsrc0 = xbn + (((size_t)(n_ * COUT)) << 16) + bi_ * 2048 + bj_ * 8;

    for (int chunk = 0; chunk < 2; chunk++) {
        __syncthreads();
        {
            int icg = chunk * 64 + xic;
            const float* src = gsrc0 + (((size_t)icg) << 16) + bsub * 4 * 256;
            char* xb = smem + xblk * X1BLK + xic * 2;
            #pragma unroll
            for (int r4 = 0; r4 < 4; r4++) {
                float4 u  = *reinterpret_cast<const float4*>(src + r4 * 256);
                float4 v2 = *reinterpret_cast<const float4*>(src + r4 * 256 + 4);
                float vals[8] = {u.x, u.y, u.z, u.w, v2.x, v2.y, v2.z, v2.w};
                int px0 = bsub * 32 + r4 * 8;
                #pragma unroll
                for (int e = 0; e < 8; e++) {
                    float xv = vals[e];
                    __nv_bfloat16 h = __float2bfloat16(xv);
                    __nv_bfloat16 l = __float2bfloat16(xv - __bfloat162float(h));
                    *(__nv_bfloat16*)(xb + (px0 + e) * X1STR) = h;
                    *(__nv_bfloat16*)(xb + X1PART + (px0 + e) * X1STR) = l;
                }
            }
        }
        #pragma unroll
        for (int rr = 0; rr < 2; rr++) {
            int r = t + rr * 256;
            int part = r >> 8, oc = r & 255;
            const __nv_bfloat16* ws = (part ? w1l : w1h) + (size_t)chunk * 16384 + oc * 64;
            const uint4* s = (const uint4*)ws;
            uint4* d = (uint4*)(smem + W1OFF + part * W1PART + oc * X1STR);
            #pragma unroll
            for (int q = 0; q < 8; q++) d[q] = s[q];
        }
        __syncthreads();

        #pragma unroll 1
        for (int pass = 0; pass < 3; pass++) {
            const char* A  = smem + W1OFF + ((pass == 1) ? W1PART : 0);
            const char* Bp = smem + mblk * X1BLK + ((pass == 2) ? X1PART : 0);
            #pragma unroll
            for (int k4 = 0; k4 < 4; k4++) {
                int kb = (k4 * 16 + 2 * tg) * 2;
                unsigned af[4][4];
                #pragma unroll
                for (int mt = 0; mt < 4; mt++) {
                    const char* ar = A + (ocb + mt * 16 + g) * X1STR + kb;
                    af[mt][0] = *(const unsigned*)ar;
                    af[mt][1] = *(const unsigned*)(ar + 8 * X1STR);
                    af[mt][2] = *(const unsigned*)(ar + 16);
                    af[mt][3] = *(const unsigned*)(ar + 8 * X1STR + 16);
                }
                #pragma unroll
                for (int nt = 0; nt < 8; nt++) {
                    const char* br = Bp + (nt * 8 + g) * X1STR + kb;
                    unsigned b0 = *(const unsigned*)br;
                    unsigned b1v = *(const unsigned*)(br + 16);
                    #pragma unroll
                    for (int mt = 0; mt < 4; mt++)
                        mma16816(acc[mt][nt], af[mt], b0, b1v);
                }
            }
        }
    }

    #pragma unroll
    for (int mt = 0; mt < 4; mt++) {
        int oc_a = ocb + mt * 16 + g;
        int oc_b = oc_a + 8;
        float ba = b1[oc_a], bbv = b1[oc_b];
        float* da = g1buf + ((size_t)(blk0 + mblk) * C2 + oc_a) * 64;
        float* db = g1buf + ((size_t)(blk0 + mblk) * C2 + oc_b) * 64;
        float sa = 0.f, qa = 0.f, sb = 0.f, qb = 0.f;
        #pragma unroll
        for (int nt = 0; nt < 8; nt++) {
            int n0 = nt * 8 + tg * 2;
            float2 e0, e1;
            e0.x = fmaxf(acc[mt][nt][0] + ba, 0.f);
            e0.y = fmaxf(acc[mt][nt][1] + ba, 0.f);
            e1.x = fmaxf(acc[mt][nt][2] + bbv, 0.f);
            e1.y = fmaxf(acc[mt][nt][3] + bbv, 0.f);
            sa += e0.x + e0.y; qa += e0.x * e0.x + e0.y * e0.y;
            sb += e1.x + e1.y; qb += e1.x * e1.x + e1.y * e1.y;
            *(float2*)(da + n0) = e0;
            *(float2*)(db + n0) = e1;
        }
        quad_stats(sa, qa, tg, &d_sum1[oc_a], &d_sq1[oc_a]);
        quad_stats(sb, qb, tg, &d_sum1[oc_b], &d_sq1[oc_b]);
    }
}

// ---------------- conv2: 3x3 via HMMA, padded-2D X (all taps = address offsets) ----------------
// X per block: hi[100 rows][72 ic] + lo = 2*14400; rows = (r+1)*10 + (c+1), zero halo.
// W @57600: [part2][oc 256][72] bf16 = 73728
#define X2ARR  14400
#define X2BLK  28800
#define W2OFF  57600
#define W2PART 36864
#define SMEM_C2M (W2OFF + 2 * W2PART)
__global__ __launch_bounds__(256, 1) void conv2m_kernel(const float* __restrict__ b2) {
    extern __shared__ float smf[];
    char* smem = (char*)smf;
    int t = threadIdx.x, w = t >> 5, lane = t & 31;
    int g = lane >> 2, tg = lane & 3;
    int blk0 = blockIdx.x * 2;
    int mblk = w >> 2;
    int ocb  = (w & 3) * 64;

    float acc[4][8][4];
    #pragma unroll
    for (int mt = 0; mt < 4; mt++)
        #pragma unroll
        for (int nt = 0; nt < 8; nt++)
            #pragma unroll
            for (int e = 0; e < 4; e++) acc[mt][nt][e] = 0.0f;

    // zero X region once (halo rows stay zero; interior rewritten every chunk)
    for (int i = t; i < (2 * X2BLK) / 16; i += 256) ((uint4*)smem)[i] = make_uint4(0, 0, 0, 0);

    int xblk = t >> 7;              // X build: 2 blk x 32 ic-pairs x 4 px-groups
    int icp  = (t >> 2) & 31;
    int pxg  = t & 3;

    for (int chunk = 0; chunk < 4; chunk++) {
        __syncthreads();            // prior-tap MMA X reads done (and initial zero)
        {
            int ic0 = chunk * 64 + icp * 2;
            const float* s0 = g1buf + ((size_t)(blk0 + xblk) * C2 + ic0) * 64 + pxg * 16;
            const float* s1 = s0 + 64;
            float a0 = d_a1[ic0],     c0 = d_b1[ic0];
            float a1 = d_a1[ic0 + 1], c1 = d_b1[ic0 + 1];
            char* xb = smem + xblk * X2BLK + icp * 4;
            #pragma unroll
            for (int q = 0; q < 4; q++) {
                float4 u0 = ((const float4*)s0)[q];
                float4 u1 = ((const float4*)s1)[q];
                float v0[4] = {u0.x, u0.y, u0.z, u0.w};
                float v1[4] = {u1.x, u1.y, u1.z, u1.w};
                #pragma unroll
                for (int e = 0; e < 4; e++) {
                    int p = pxg * 16 + q * 4 + e;
                    int row = ((p >> 3) + 1) * 10 + (p & 7) + 1;
                    float x0 = a0 * v0[e] + c0;
                    float x1 = a1 * v1[e] + c1;
                    __nv_bfloat16 h0 = __float2bfloat16(x0);
                    __nv_bfloat16 h1 = __float2bfloat16(x1);
                    __nv_bfloat16 l0 = __float2bfloat16(x0 - __bfloat162float(h0));
                    __nv_bfloat16 l1 = __float2bfloat16(x1 - __bfloat162float(h1));
                    *(unsigned*)(xb + row * X1STR) =
                        PKU(__bfloat16_as_ushort(h0), __bfloat16_as_ushort(h1));
                    *(unsigned*)(xb + X2ARR + row * X1STR) =
                        PKU(__bfloat16_as_ushort(l0), __bfloat16_as_ushort(l1));
                }
            }
        }

        for (int tap = 0; tap < 9; tap++) {
            __syncthreads();        // X build done / prior W reads done
            {
                int tc = tap * 4 + chunk;
                #pragma unroll
                for (int rr = 0; rr < 2; rr++) {
                    int r = t + rr * 256;
                    int part = r >> 8, oc = r & 255;
                    const __nv_bfloat16* gsrc = (part ? w2l : w2h) + (size_t)tc * 16384 + oc * 64;
                    const uint4* s = (const uint4*)gsrc;
                    uint4* d = (uint4*)(smem + W2OFF + part * W2PART + oc * X1STR);
                    #pragma unroll
                    for (int q = 0; q < 8; q++) d[q] = s[q];
                }
            }
            __syncthreads();

            int dr = tap / 3, dc = tap % 3;
            int rowc = dr * 10 + dc + g;
            #pragma unroll 1
            for (int pass = 0; pass < 3; pass++) {
                const char* A  = smem + W2OFF + ((pass == 1) ? W2PART : 0);
                const char* Bp = smem + mblk * X2BLK + ((pass == 2) ? X2ARR : 0);
                #pragma unroll
                for (int k4 = 0; k4 < 4; k4++) {
                    int kb = (k4 * 16 + 2 * tg) * 2;
                    unsigned af[4][4];
                    #pragma unroll
                    for (int mt = 0; mt < 4; mt++) {
                        const char* ar = A + (ocb + mt * 16 + g) * X1STR + kb;
                        af[mt][0] = *(const unsigned*)ar;
                        af[mt][1] = *(const unsigned*)(ar + 8 * X1STR);
                        af[mt][2] = *(const unsigned*)(ar + 16);
                        af[mt][3] = *(const unsigned*)(ar + 8 * X1STR + 16);
                    }
                    #pragma unroll
                    for (int nt = 0; nt < 8; nt++) {
                        const char* br = Bp + (rowc + nt * 10) * X1STR + kb;
                        unsigned b0 = *(const unsigned*)br;
                        unsigned b1 = *(const unsigned*)(br + 16);
                        #pragma unroll
                        for (int mt = 0; mt < 4; mt++)
                            mma16816(acc[mt][nt], af[mt], b0, b1);
                    }
                }
            }
        }
    }

    #pragma unroll
    for (int mt = 0; mt < 4; mt++) {
        int oc_a = ocb + mt * 16 + g;
        int oc_b = oc_a + 8;
        float ba = b2[oc_a], bbv = b2[oc_b];
        float* da = g2buf + ((size_t)(blk0 + mblk) * C2 + oc_a) * 64;
        float* db = g2buf + ((size_t)(blk0 + mblk) * C2 + oc_b) * 64;
        float sa = 0.f, qa = 0.f, sb = 0.f, qb = 0.f;
        #pragma unroll
        for (int nt = 0; nt < 8; nt++) {
            int n0 = nt * 8 + tg * 2;
            float2 e0, e1;
            e0.x = fmaxf(acc[mt][nt][0] + ba, 0.f);
            e0.y = fmaxf(acc[mt][nt][1] + ba, 0.f);
            e1.x = fmaxf(acc[mt][nt][2] + bbv, 0.f);
            e1.y = fmaxf(acc[mt][nt][3] + bbv, 0.f);
            sa += e0.x + e0.y; qa += e0.x * e0.x + e0.y * e0.y;
            sb += e1.x + e1.y; qb += e1.x * e1.x + e1.y * e1.y;
            *(float2*)(da + n0) = e0;
            *(float2*)(db + n0) = e1;
        }
        quad_stats(sa, qa, tg, &d_sum2[oc_a], &d_sq2[oc_a]);
        quad_stats(sb, qb, tg, &d_sum2[oc_b], &d_sq2[oc_b]);
    }
}

// ---------------- conv3: 1x1 256->128 via HMMA, 4 blocks/CTA, BN2 folded, fused stats ----------------
#define X3BLK  18432
#define W3OFF  73728
#define W3PART 18432
#define SMEM_C3M (W3OFF + 2 * W3PART)
__global__ __launch_bounds__(256, 1) void conv3m_kernel(const float* __restrict__ b3) {
    extern __shared__ float smf[];
    char* smem = (char*)smf;
    int t = threadIdx.x, w = t >> 5, lane = t & 31;
    int g = lane >> 2, tg = lane & 3;
    int blk0 = blockIdx.x * 4;
    int mblk = w >> 1;
    int ocb  = (w & 1) * 64;

    float acc[4][8][4];
    #pragma unroll
    for (int mt = 0; mt < 4; mt++)
        #pragma unroll
        for (int nt = 0; nt < 8; nt++)
            #pragma unroll
            for (int e = 0; e < 4; e++) acc[mt][nt][e] = 0.0f;

    int xblk = t >> 6, xic = t & 63;

    for (int chunk = 0; chunk < 4; chunk++) {
        __syncthreads();
        {
            int icg = chunk * 64 + xic;
            const float* src = g2buf + ((size_t)(blk0 + xblk) * C2 + icg) * 64;
            float a = d_a2[icg], bb = d_b2[icg];
            char* xb = smem + xblk * X3BLK + xic * 2;
            #pragma unroll
            for (int j = 0; j < 16; j++) {
                float4 v4 = ((const float4*)src)[j];
                float vals[4] = {v4.x, v4.y, v4.z, v4.w};
                #pragma unroll
                for (int e = 0; e < 4; e++) {
                    int px = j * 4 + e;
                    float xv = a * vals[e] + bb;
                    __nv_bfloat16 h = __float2bfloat16(xv);
                    __nv_bfloat16 l = __float2bfloat16(xv - __bfloat162float(h));
                    *(__nv_bfloat16*)(xb + px * X1STR) = h;
                    *(__nv_bfloat16*)(xb + X1PART + px * X1STR) = l;
                }
            }
        }
        {
            int part = t >> 7, oc = t & 127;
            const __nv_bfloat16* ws = (part ? w3l : w3h) + (size_t)chunk * 8192 + oc * 64;
            const uint4* s = (const uint4*)ws;
            uint4* d = (uint4*)(smem + W3OFF + part * W3PART + oc * X1STR);
            #pragma unroll
            for (int q = 0; q < 8; q++) d[q] = s[q];
        }
        __syncthreads();

        #pragma unroll 1
        for (int pass = 0; pass < 3; pass++) {
            const char* A  = smem + W3OFF + ((pass == 1) ? W3PART : 0);
            const char* Bp = smem + mblk * X3BLK + ((pass == 2) ? X1PART : 0);
            #pragma unroll
            for (int k4 = 0; k4 < 4; k4++) {
                int kb = (k4 * 16 + 2 * tg) * 2;
                unsigned af[4][4];
                #pragma unroll
                for (int mt = 0; mt < 4; mt++) {
                    const char* ar = A + (ocb + mt * 16 + g) * X1STR + kb;
                    af[mt][0] = *(const unsigned*)ar;
                    af[mt][1] = *(const unsigned*)(ar + 8 * X1STR);
                    af[mt][2] = *(const unsigned*)(ar + 16);
                    af[mt][3] = *(const unsigned*)(ar + 8 * X1STR + 16);
                }
                #pragma unroll
                for (int nt = 0; nt < 8; nt++) {
                    const char* br = Bp + (nt * 8 + g) * X1STR + kb;
                    unsigned b0 = *(const unsigned*)br;
                    unsigned b1v = *(const unsigned*)(br + 16);
                    #pragma unroll
                    for (int mt = 0; mt < 4; mt++)
                        mma16816(acc[mt][nt], af[mt], b0, b1v);
                }
            }
        }
    }

    #pragma unroll
    for (int mt = 0; mt < 4; mt++) {
        int oc_a = ocb + mt * 16 + g;
        int oc_b = oc_a + 8;
        float ba = b3[oc_a], bbv = b3[oc_b];
        float* da = g3buf + ((size_t)(blk0 + mblk) * COUT + oc_a) * 64;
        float* db = g3buf + ((size_t)(blk0 + mblk) * COUT + oc_b) * 64;
        float sa = 0.f, qa = 0.f, sb = 0.f, qb = 0.f;
        #pragma unroll
        for (int nt = 0; nt < 8; nt++) {
            int n0 = nt * 8 + tg * 2;
            float2 e0, e1;
            e0.x = fmaxf(acc[mt][nt][0] + ba, 0.f);
            e0.y = fmaxf(acc[mt][nt][1] + ba, 0.f);
            e1.x = fmaxf(acc[mt][nt][2] + bbv, 0.f);
            e1.y = fmaxf(acc[mt][nt][3] + bbv, 0.f);
            sa += e0.x + e0.y; qa += e0.x * e0.x + e0.y * e0.y;
            sb += e1.x + e1.y; qb += e1.x * e1.x + e1.y * e1.y;
            *(float2*)(da + n0) = e0;
            *(float2*)(db + n0) = e1;
        }
        quad_stats(sa, qa, tg, &d_sum3[oc_a], &d_sq3[oc_a]);
        quad_stats(sb, qb, tg, &d_sum3[oc_b], &d_sq3[oc_b]);
    }
}

// ---------------- scatter: BN3(g3) -> image ----------------
__global__ __launch_bounds__(256) void scatter_kernel(const int* __restrict__ abi,
                                                      float* __restrict__ out) {
    int blk = blockIdx.x;
    int n  = abi[blk * 3 + 0];
    int bi = abi[blk * 3 + 1];
    int bj = abi[blk * 3 + 2];
    const float* src = g3buf + (size_t)blk * COUT * 64;
    float* dst = out + (((size_t)(n * COUT)) << 16) + bi * 8 * 256 + bj * 8;
    for (int i = threadIdx.x; i < 2048; i += 256) {
        int c = i >> 4, q = i & 15;
        int r = q >> 1, c4 = (q & 1) * 4;
        float4 v = *reinterpret_cast<const float4*>(src + c * 64 + q * 4);
        float a = d_a3[c], bb = d_b3[c];
        v.x = a * v.x + bb; v.y = a * v.y + bb;
        v.z = a * v.z + bb; v.w = a * v.w + bb;
        *reinterpret_cast<float4*>(dst + (((size_t)c) << 16) + r * 256 + c4) = v;
    }
}

// ---------------- launch ----------------
extern "C" void kernel_launch(void* const* d_in, const int* in_sizes, int n_in,
                              void* d_out, int out_size) {
    const float* x    = (const float*)d_in[0];
    const int*   abi  = (const int*)  d_in[1];
    const float* w_c  = (const float*)d_in[2];
    const float* b_c  = (const float*)d_in[3];
    const float* gm_c = (const float*)d_in[4];
    const float* be_c = (const float*)d_in[5];
    const float* w1   = (const float*)d_in[6];
    const float* b1   = (const float*)d_in[7];
    const float* gm1  = (const float*)d_in[8];
    const float* be1  = (const float*)d_in[9];
    const float* w2   = (const float*)d_in[10];
    const float* b2   = (const float*)d_in[11];
    const float* gm2  = (const float*)d_in[12];
    const float* be2  = (const float*)d_in[13];
    const float* w3   = (const float*)d_in[14];
    const float* b3   = (const float*)d_in[15];
    const float* gm3  = (const float*)d_in[16];
    const float* be3  = (const float*)d_in[17];
    float* out = (float*)d_out;

    cudaFuncSetAttribute(convc_kernel,  cudaFuncAttributeMaxDynamicSharedMemorySize, SMEM_CONVC);
    cudaFuncSetAttribute(conv1m_kernel, cudaFuncAttributeMaxDynamicSharedMemorySize, SMEM_C1M);
    cudaFuncSetAttribute(conv2m_kernel, cudaFuncAttributeMaxDynamicSharedMemorySize, SMEM_C2M);
    cudaFuncSetAttribute(conv3m_kernel, cudaFuncAttributeMaxDynamicSharedMemorySize, SMEM_C3M);

    zero_stats_kernel<<<1, 256>>>();
    w2cvt_kernel<<<576, 256>>>(w2);
    w13cvt_kernel<<<64, 256>>>(w1, w3);

    convc_kernel<<<4096, 256, SMEM_CONVC>>>(x, w_c, b_c, out);
    finalize_kernel<<<1, 256>>>(0, gm_c, be_c, 1.0 / 524288.0);
    bnapply_kernel<<<16384, 256>>>(out);

    conv1m_kernel<<<2048, 256, SMEM_C1M>>>(out, abi, b1);
    finalize_kernel<<<1, 256>>>(1, gm1, be1, 1.0 / 262144.0);

    conv2m_kernel<<<2048, 256, SMEM_C2M>>>(b2);
    finalize_kernel<<<1, 256>>>(2, gm2, be2, 1.0 / 262144.0);

    conv3m_kernel<<<1024, 256, SMEM_C3M>>>(b3);
    finalize_kernel<<<1, 256>>>(3, gm3, be3, 1.0 / 262144.0);

    scatter_kernel<<<4096, 256>>>(abi, out);
}

// round 8
// speedup vs baseline: 2.1437x; 1.0800x over previous
#include <cuda_runtime.h>
#include <cuda_bf16.h>
#include <math.h>
#include <stdint.h>

#define B_    8
#define CIN   64
#define COUT  128
#define C2    256
#define HW    65536
#define NBLK  4096
#define EPSV  1e-5f

// ---------------- scratch ----------------
__device__ float g1buf[(size_t)NBLK * C2 * 64];
__device__ float g2buf[(size_t)NBLK * C2 * 64];
__device__ float g3buf[(size_t)NBLK * COUT * 64];

// bf16 hi/lo weights
__device__ __nv_bfloat16 w2h[36 * 16384];   // [tap*4+chunk][oc 256][ic 64]
__device__ __nv_bfloat16 w2l[36 * 16384];
__device__ __nv_bfloat16 w1h[2 * 16384];    // [chunk2][oc 256][ic 64]
__device__ __nv_bfloat16 w1l[2 * 16384];
__device__ __nv_bfloat16 w3h[4 * 8192];     // [chunk4][oc 128][ic 64]
__device__ __nv_bfloat16 w3l[4 * 8192];
__device__ __nv_bfloat16 wch[8192];         // [oc 128][ic 64]
__device__ __nv_bfloat16 wcl[8192];

__device__ double d_sum0[COUT], d_sq0[COUT];
__device__ double d_sum1[C2],   d_sq1[C2];
__device__ double d_sum2[C2],   d_sq2[C2];
__device__ double d_sum3[COUT], d_sq3[COUT];
__device__ float  d_a0[COUT], d_b0[COUT];
__device__ float  d_a1[C2],   d_b1[C2];
__device__ float  d_a2[C2],   d_b2[C2];
__device__ float  d_a3[COUT], d_b3[COUT];

#define PKU(x, y) ((unsigned)(x) | ((unsigned)(y) << 16))

// ---------------- bf16 HMMA helper ----------------
__device__ __forceinline__ void mma16816(float* d, const unsigned* a, unsigned b0, unsigned b1) {
    asm volatile(
        "mma.sync.aligned.m16n8k16.row.col.f32.bf16.bf16.f32 "
        "{%0,%1,%2,%3}, {%4,%5,%6,%7}, {%8,%9}, {%0,%1,%2,%3};"
        : "+f"(d[0]), "+f"(d[1]), "+f"(d[2]), "+f"(d[3])
        : "r"(a[0]), "r"(a[1]), "r"(a[2]), "r"(a[3]), "r"(b0), "r"(b1));
}

__device__ __forceinline__ void quad_stats(float s, float s2, int tg,
                                           double* gsum, double* gsq) {
    s  += __shfl_xor_sync(0xffffffffu, s, 1);
    s  += __shfl_xor_sync(0xffffffffu, s, 2);
    s2 += __shfl_xor_sync(0xffffffffu, s2, 1);
    s2 += __shfl_xor_sync(0xffffffffu, s2, 2);
    if (tg == 0) { atomicAdd(gsum, (double)s); atomicAdd(gsq, (double)s2); }
}

// ---------------- utility ----------------
__global__ void zero_stats_kernel() {
    int t = threadIdx.x;
    if (t < COUT) { d_sum0[t] = 0.0; d_sq0[t] = 0.0; d_sum3[t] = 0.0; d_sq3[t] = 0.0; }
    d_sum1[t] = 0.0; d_sq1[t] = 0.0; d_sum2[t] = 0.0; d_sq2[t] = 0.0;
}

__global__ void finalize_kernel(int stage, const float* __restrict__ gamma,
                                const float* __restrict__ beta, double invN) {
    int t = threadIdx.x;
    const double *sum, *sq; float *a, *bsh; int C;
    if (stage == 0)      { sum = d_sum0; sq = d_sq0; a = d_a0; bsh = d_b0; C = COUT; }
    else if (stage == 1) { sum = d_sum1; sq = d_sq1; a = d_a1; bsh = d_b1; C = C2; }
    else if (stage == 2) { sum = d_sum2; sq = d_sq2; a = d_a2; bsh = d_b2; C = C2; }
    else                 { sum = d_sum3; sq = d_sq3; a = d_a3; bsh = d_b3; C = COUT; }
    if (t < C) {
        double mean = sum[t] * invN;
        double var  = sq[t] * invN - mean * mean;
        float v = fmaxf((float)var, 0.0f);
        float av = gamma[t] * rsqrtf(v + EPSV);
        a[t] = av;
        bsh[t] = beta[t] - av * (float)mean;
    }
}

// ---------------- weight converts ----------------
__global__ __launch_bounds__(256) void w2cvt_kernel(const float* __restrict__ w2) {
    int i4 = blockIdx.x * 256 + threadIdx.x;
    int ic0 = (i4 & 15) * 4;
    int oc  = (i4 >> 4) & 255;
    int tc  = i4 >> 12;
    int tap = tc >> 2, chunk = tc & 3;
    #pragma unroll
    for (int e = 0; e < 4; e++) {
        int ic = ic0 + e;
        float v = w2[(size_t)oc * 2304 + (chunk * 64 + ic) * 9 + tap];
        __nv_bfloat16 h = __float2bfloat16(v);
        w2h[(size_t)tc * 16384 + oc * 64 + ic] = h;
        w2l[(size_t)tc * 16384 + oc * 64 + ic] = __float2bfloat16(v - __bfloat162float(h));
    }
}

__global__ __launch_bounds__(256) void w13cvt_kernel(const float* __restrict__ w1,
                                                     const float* __restrict__ w3,
                                                     const float* __restrict__ wc) {
    int i = blockIdx.x * 256 + threadIdx.x;   // 0..16383
    {
        #pragma unroll
        for (int e = 0; e < 2; e++) {
            int idx = i * 2 + e;
            int ic = idx & 63, oc = (idx >> 6) & 255, ch = idx >> 14;
            float v = w1[(size_t)oc * 128 + ch * 64 + ic];
            __nv_bfloat16 h = __float2bfloat16(v);
            w1h[idx] = h;
            w1l[idx] = __float2bfloat16(v - __bfloat162float(h));
        }
    }
    {
        #pragma unroll
        for (int e = 0; e < 2; e++) {
            int idx = i * 2 + e;
            int ic = idx & 63, oc = (idx >> 6) & 127, ch = idx >> 13;
            float v = w3[(size_t)oc * 256 + ch * 64 + ic];
            __nv_bfloat16 h = __float2bfloat16(v);
            w3h[idx] = h;
            w3l[idx] = __float2bfloat16(v - __bfloat162float(h));
        }
    }
    if (i < 8192) {
        float v = wc[i];
        __nv_bfloat16 h = __float2bfloat16(v);
        wch[i] = h;
        wcl[i] = __float2bfloat16(v - __bfloat162float(h));
    }
}

// ---------------- convc: 1x1 64->128 + relu via HMMA, 128 px/CTA, fused stats ----------------
// X: [px 128][ic 72] hi @0, lo @18432 ; W @36864: [part2][oc128][72]
#define XCSTR  144
#define XCPART 18432
#define WCOFF  36864
#define WCPART 18432
#define SMEM_CCM (WCOFF + 2 * WCPART)
__global__ __launch_bounds__(256, 2) void convcm_kernel(const float* __restrict__ x,
                                                        const float* __restrict__ bc,
                                                        float* __restrict__ out) {
    extern __shared__ float smf[];
    char* smem = (char*)smf;
    int t = threadIdx.x, w = t >> 5, lane = t & 31;
    int g = lane >> 2, tg = lane & 3;
    int b  = blockIdx.x >> 9;
    int p0 = (blockIdx.x & 511) << 7;
    int ocb = (w & 1) * 64;
    int pxb = (w >> 1) * 32;

    // ---- X build: thread = (icp 32, pxg 8), 16 px each, packed u32 (2 ic) ----
    {
        int icp = t & 31, pxg = t >> 5;
        const float* s0 = x + (((size_t)(b * CIN + icp * 2)) << 16) + p0 + pxg * 16;
        const float* s1 = s0 + HW;
        char* xb = smem + icp * 4;
        #pragma unroll
        for (int q = 0; q < 4; q++) {
            float4 u0 = ((const float4*)s0)[q];
            float4 u1 = ((const float4*)s1)[q];
            float v0[4] = {u0.x, u0.y, u0.z, u0.w};
            float v1[4] = {u1.x, u1.y, u1.z, u1.w};
            #pragma unroll
            for (int e = 0; e < 4; e++) {
                int px = pxg * 16 + q * 4 + e;
                __nv_bfloat16 h0 = __float2bfloat16(v0[e]);
                __nv_bfloat16 h1 = __float2bfloat16(v1[e]);
                __nv_bfloat16 l0 = __float2bfloat16(v0[e] - __bfloat162float(h0));
                __nv_bfloat16 l1 = __float2bfloat16(v1[e] - __bfloat162float(h1));
                *(unsigned*)(xb + px * XCSTR) =
                    PKU(__bfloat16_as_ushort(h0), __bfloat16_as_ushort(h1));
                *(unsigned*)(xb + XCPART + px * XCSTR) =
                    PKU(__bfloat16_as_ushort(l0), __bfloat16_as_ushort(l1));
            }
        }
    }
    // ---- W copy ----
    {
        int part = t >> 7, oc = t & 127;
        const __nv_bfloat16* ws = (part ? wcl : wch) + oc * 64;
        const uint4* s = (const uint4*)ws;
        uint4* d = (uint4*)(smem + WCOFF + part * WCPART + oc * XCSTR);
        #pragma unroll
        for (int q = 0; q < 8; q++) d[q] = s[q];
    }
    __syncthreads();

    float acc[4][4][4];
    #pragma unroll
    for (int mt = 0; mt < 4; mt++)
        #pragma unroll
        for (int nt = 0; nt < 4; nt++)
            #pragma unroll
            for (int e = 0; e < 4; e++) acc[mt][nt][e] = 0.0f;

    #pragma unroll 1
    for (int pass = 0; pass < 3; pass++) {
        const char* A  = smem + WCOFF + ((pass == 1) ? WCPART : 0);
        const char* Bp = smem + ((pass == 2) ? XCPART : 0);
        #pragma unroll
        for (int k4 = 0; k4 < 4; k4++) {
            int kb = (k4 * 16 + 2 * tg) * 2;
            unsigned af[4][4];
            #pragma unroll
            for (int mt = 0; mt < 4; mt++) {
                const char* ar = A + (ocb + mt * 16 + g) * XCSTR + kb;
                af[mt][0] = *(const unsigned*)ar;
                af[mt][1] = *(const unsigned*)(ar + 8 * XCSTR);
                af[mt][2] = *(const unsigned*)(ar + 16);
                af[mt][3] = *(const unsigned*)(ar + 8 * XCSTR + 16);
            }
            #pragma unroll
            for (int nt = 0; nt < 4; nt++) {
                const char* br = Bp + (pxb + nt * 8 + g) * XCSTR + kb;
                unsigned b0 = *(const unsigned*)br;
                unsigned b1v = *(const unsigned*)(br + 16);
                #pragma unroll
                for (int mt = 0; mt < 4; mt++)
                    mma16816(acc[mt][nt], af[mt], b0, b1v);
            }
        }
    }

    float* dstb = out + (((size_t)(b * COUT)) << 16) + p0;
    #pragma unroll
    for (int mt = 0; mt < 4; mt++) {
        int oc_a = ocb + mt * 16 + g;
        int oc_b = oc_a + 8;
        float ba = bc[oc_a], bbv = bc[oc_b];
        float* da = dstb + (((size_t)oc_a) << 16) + pxb;
        float* db = dstb + (((size_t)oc_b) << 16) + pxb;
        float sa = 0.f, qa = 0.f, sb = 0.f, qb = 0.f;
        #pragma unroll
        for (int nt = 0; nt < 4; nt++) {
            int n0 = nt * 8 + tg * 2;
            float2 e0, e1;
            e0.x = fmaxf(acc[mt][nt][0] + ba, 0.f);
            e0.y = fmaxf(acc[mt][nt][1] + ba, 0.f);
            e1.x = fmaxf(acc[mt][nt][2] + bbv, 0.f);
            e1.y = fmaxf(acc[mt][nt][3] + bbv, 0.f);
            sa += e0.x + e0.y; qa += e0.x * e0.x + e0.y * e0.y;
            sb += e1.x + e1.y; qb += e1.x * e1.x + e1.y * e1.y;
            *(float2*)(da + n0) = e0;
            *(float2*)(db + n0) = e1;
        }
        quad_stats(sa, qa, tg, &d_sum0[oc_a], &d_sq0[oc_a]);
        quad_stats(sb, qb, tg, &d_sum0[oc_b], &d_sq0[oc_b]);
    }
}

__global__ __launch_bounds__(256) void bnapply_kernel(float* __restrict__ y) {
    int nth = gridDim.x * blockDim.x;
    int total = (B_ * COUT * HW) / 4;
    for (int i = blockIdx.x * blockDim.x + threadIdx.x; i < total; i += nth) {
        int c = (i >> 14) & 127;
        float4 v = reinterpret_cast<float4*>(y)[i];
        float a = d_a0[c], bb = d_b0[c];
        v.x = a * v.x + bb; v.y = a * v.y + bb;
        v.z = a * v.z + bb; v.w = a * v.w + bb;
        reinterpret_cast<float4*>(y)[i] = v;
    }
}

// ---------------- conv1: gather + 1x1 128->256 via HMMA, 2 blocks/CTA, fused stats ----------------
#define X1STR  144
#define X1PART 9216
#define X1BLK  18432
#define W1OFF  36864
#define W1PART 36864
#define SMEM_C1M (W1OFF + 2 * W1PART)
__global__ __launch_bounds__(256, 1) void conv1m_kernel(const float* __restrict__ xbn,
                                                        const int* __restrict__ abi,
                                                        const float* __restrict__ b1) {
    extern __shared__ float smf[];
    char* smem = (char*)smf;
    int t = threadIdx.x, w = t >> 5, lane = t & 31;
    int g = lane >> 2, tg = lane & 3;
    int blk0 = blockIdx.x * 2;
    int mblk = w >> 2;
    int ocb  = (w & 3) * 64;

    float acc[4][8][4];
    #pragma unroll
    for (int mt = 0; mt < 4; mt++)
        #pragma unroll
        for (int nt = 0; nt < 8; nt++)
            #pragma unroll
            for (int e = 0; e < 4; e++) acc[mt][nt][e] = 0.0f;

    int brow = t >> 1, bsub = t & 1;
    int xblk = brow >> 6, xic = brow & 63;
    int n_  = abi[(blk0 + xblk) * 3 + 0];
    int bi_ = abi[(blk0 + xblk) * 3 + 1];
    int bj_ = abi[(blk0 + xblk) * 3 + 2];
    const float* gsrc0 = xbn + (((size_t)(n_ * COUT)) << 16) + bi_ * 2048 + bj_ * 8;

    for (int chunk = 0; chunk < 2; chunk++) {
        __syncthreads();
        {
            int icg = chunk * 64 + xic;
            const float* src = gsrc0 + (((size_t)icg) << 16) + bsub * 4 * 256;
            char* xb = smem + xblk * X1BLK + xic * 2;
            #pragma unroll
            for (int r4 = 0; r4 < 4; r4++) {
                float4 u  = *reinterpret_cast<const float4*>(src + r4 * 256);
                float4 v2 = *reinterpret_cast<const float4*>(src + r4 * 256 + 4);
                float vals[8] = {u.x, u.y, u.z, u.w, v2.x, v2.y, v2.z, v2.w};
                int px0 = bsub * 32 + r4 * 8;
                #pragma unroll
                for (int e = 0; e < 8; e++) {
                    float xv = vals[e];
                    __nv_bfloat16 h = __float2bfloat16(xv);
                    __nv_bfloat16 l = __float2bfloat16(xv - __bfloat162float(h));
                    *(__nv_bfloat16*)(xb + (px0 + e) * X1STR) = h;
                    *(__nv_bfloat16*)(xb + X1PART + (px0 + e) * X1STR) = l;
                }
            }
        }
        #pragma unroll
        for (int rr = 0; rr < 2; rr++) {
            int r = t + rr * 256;
            int part = r >> 8, oc = r & 255;
            const __nv_bfloat16* ws = (part ? w1l : w1h) + (size_t)chunk * 16384 + oc * 64;
            const uint4* s = (const uint4*)ws;
            uint4* d = (uint4*)(smem + W1OFF + part * W1PART + oc * X1STR);
            #pragma unroll
            for (int q = 0; q < 8; q++) d[q] = s[q];
        }
        __syncthreads();

        #pragma unroll 1
        for (int pass = 0; pass < 3; pass++) {
            const char* A  = smem + W1OFF + ((pass == 1) ? W1PART : 0);
            const char* Bp = smem + mblk * X1BLK + ((pass == 2) ? X1PART : 0);
            #pragma unroll
            for (int k4 = 0; k4 < 4; k4++) {
                int kb = (k4 * 16 + 2 * tg) * 2;
                unsigned af[4][4];
                #pragma unroll
                for (int mt = 0; mt < 4; mt++) {
                    const char* ar = A + (ocb + mt * 16 + g) * X1STR + kb;
                    af[mt][0] = *(const unsigned*)ar;
                    af[mt][1] = *(const unsigned*)(ar + 8 * X1STR);
                    af[mt][2] = *(const unsigned*)(ar + 16);
                    af[mt][3] = *(const unsigned*)(ar + 8 * X1STR + 16);
                }
                #pragma unroll
                for (int nt = 0; nt < 8; nt++) {
                    const char* br = Bp + (nt * 8 + g) * X1STR + kb;
                    unsigned b0 = *(const unsigned*)br;
                    unsigned b1v = *(const unsigned*)(br + 16);
                    #pragma unroll
                    for (int mt = 0; mt < 4; mt++)
                        mma16816(acc[mt][nt], af[mt], b0, b1v);
                }
            }
        }
    }

    #pragma unroll
    for (int mt = 0; mt < 4; mt++) {
        int oc_a = ocb + mt * 16 + g;
        int oc_b = oc_a + 8;
        float ba = b1[oc_a], bbv = b1[oc_b];
        float* da = g1buf + ((size_t)(blk0 + mblk) * C2 + oc_a) * 64;
        float* db = g1buf + ((size_t)(blk0 + mblk) * C2 + oc_b) * 64;
        float sa = 0.f, qa = 0.f, sb = 0.f, qb = 0.f;
        #pragma unroll
        for (int nt = 0; nt < 8; nt++) {
            int n0 = nt * 8 + tg * 2;
            float2 e0, e1;
            e0.x = fmaxf(acc[mt][nt][0] + ba, 0.f);
            e0.y = fmaxf(acc[mt][nt][1] + ba, 0.f);
            e1.x = fmaxf(acc[mt][nt][2] + bbv, 0.f);
            e1.y = fmaxf(acc[mt][nt][3] + bbv, 0.f);
            sa += e0.x + e0.y; qa += e0.x * e0.x + e0.y * e0.y;
            sb += e1.x + e1.y; qb += e1.x * e1.x + e1.y * e1.y;
            *(float2*)(da + n0) = e0;
            *(float2*)(db + n0) = e1;
        }
        quad_stats(sa, qa, tg, &d_sum1[oc_a], &d_sq1[oc_a]);
        quad_stats(sb, qb, tg, &d_sum1[oc_b], &d_sq1[oc_b]);
    }
}

// ---------------- conv2: 3x3 via HMMA, padded-2D X ----------------
#define X2ARR  14400
#define X2BLK  28800
#define W2OFF  57600
#define W2PART 36864
#define SMEM_C2M (W2OFF + 2 * W2PART)
__global__ __launch_bounds__(256, 1) void conv2m_kernel(const float* __restrict__ b2) {
    extern __shared__ float smf[];
    char* smem = (char*)smf;
    int t = threadIdx.x, w = t >> 5, lane = t & 31;
    int g = lane >> 2, tg = lane & 3;
    int blk0 = blockIdx.x * 2;
    int mblk = w >> 2;
    int ocb  = (w & 3) * 64;

    float acc[4][8][4];
    #pragma unroll
    for (int mt = 0; mt < 4; mt++)
        #pragma unroll
        for (int nt = 0; nt < 8; nt++)
            #pragma unroll
            for (int e = 0; e < 4; e++) acc[mt][nt][e] = 0.0f;

    for (int i = t; i < (2 * X2BLK) / 16; i += 256) ((uint4*)smem)[i] = make_uint4(0, 0, 0, 0);

    int xblk = t >> 7;
    int icp  = (t >> 2) & 31;
    int pxg  = t & 3;

    for (int chunk = 0; chunk < 4; chunk++) {
        __syncthreads();
        {
            int ic0 = chunk * 64 + icp * 2;
            const float* s0 = g1buf + ((size_t)(blk0 + xblk) * C2 + ic0) * 64 + pxg * 16;
            const float* s1 = s0 + 64;
            float a0 = d_a1[ic0],     c0 = d_b1[ic0];
            float a1 = d_a1[ic0 + 1], c1 = d_b1[ic0 + 1];
            char* xb = smem + xblk * X2BLK + icp * 4;
            #pragma unroll
            for (int q = 0; q < 4; q++) {
                float4 u0 = ((const float4*)s0)[q];
                float4 u1 = ((const float4*)s1)[q];
                float v0[4] = {u0.x, u0.y, u0.z, u0.w};
                float v1[4] = {u1.x, u1.y, u1.z, u1.w};
                #pragma unroll
                for (int e = 0; e < 4; e++) {
                    int p = pxg * 16 + q * 4 + e;
                    int row = ((p >> 3) + 1) * 10 + (p & 7) + 1;
                    float x0 = a0 * v0[e] + c0;
                    float x1 = a1 * v1[e] + c1;
                    __nv_bfloat16 h0 = __float2bfloat16(x0);
                    __nv_bfloat16 h1 = __float2bfloat16(x1);
                    __nv_bfloat16 l0 = __float2bfloat16(x0 - __bfloat162float(h0));
                    __nv_bfloat16 l1 = __float2bfloat16(x1 - __bfloat162float(h1));
                    *(unsigned*)(xb + row * X1STR) =
                        PKU(__bfloat16_as_ushort(h0), __bfloat16_as_ushort(h1));
                    *(unsigned*)(xb + X2ARR + row * X1STR) =
                        PKU(__bfloat16_as_ushort(l0), __bfloat16_as_ushort(l1));
                }
            }
        }

        for (int tap = 0; tap < 9; tap++) {
            __syncthreads();
            {
                int tc = tap * 4 + chunk;
                #pragma unroll
                for (int rr = 0; rr < 2; rr++) {
                    int r = t + rr * 256;
                    int part = r >> 8, oc = r & 255;
                    const __nv_bfloat16* gsrc = (part ? w2l : w2h) + (size_t)tc * 16384 + oc * 64;
                    const uint4* s = (const uint4*)gsrc;
                    uint4* d = (uint4*)(smem + W2OFF + part * W2PART + oc * X1STR);
                    #pragma unroll
                    for (int q = 0; q < 8; q++) d[q] = s[q];
                }
            }
            __syncthreads();

            int dr = tap / 3, dc = tap % 3;
            int rowc = dr * 10 + dc + g;
            #pragma unroll 1
            for (int pass = 0; pass < 3; pass++) {
                const char* A  = smem + W2OFF + ((pass == 1) ? W2PART : 0);
                const char* Bp = smem + mblk * X2BLK + ((pass == 2) ? X2ARR : 0);
                #pragma unroll
                for (int k4 = 0; k4 < 4; k4++) {
                    int kb = (k4 * 16 + 2 * tg) * 2;
                    unsigned af[4][4];
                    #pragma unroll
                    for (int mt = 0; mt < 4; mt++) {
                        const char* ar = A + (ocb + mt * 16 + g) * X1STR + kb;
                        af[mt][0] = *(const unsigned*)ar;
                        af[mt][1] = *(const unsigned*)(ar + 8 * X1STR);
                        af[mt][2] = *(const unsigned*)(ar + 16);
                        af[mt][3] = *(const unsigned*)(ar + 8 * X1STR + 16);
                    }
                    #pragma unroll
                    for (int nt = 0; nt < 8; nt++) {
                        const char* br = Bp + (rowc + nt * 10) * X1STR + kb;
                        unsigned b0 = *(const unsigned*)br;
                        unsigned b1 = *(const unsigned*)(br + 16);
                        #pragma unroll
                        for (int mt = 0; mt < 4; mt++)
                            mma16816(acc[mt][nt], af[mt], b0, b1);
                    }
                }
            }
        }
    }

    #pragma unroll
    for (int mt = 0; mt < 4; mt++) {
        int oc_a = ocb + mt * 16 + g;
        int oc_b = oc_a + 8;
        float ba = b2[oc_a], bbv = b2[oc_b];
        float* da = g2buf + ((size_t)(blk0 + mblk) * C2 + oc_a) * 64;
        float* db = g2buf + ((size_t)(blk0 + mblk) * C2 + oc_b) * 64;
        float sa = 0.f, qa = 0.f, sb = 0.f, qb = 0.f;
        #pragma unroll
        for (int nt = 0; nt < 8; nt++) {
            int n0 = nt * 8 + tg * 2;
            float2 e0, e1;
            e0.x = fmaxf(acc[mt][nt][0] + ba, 0.f);
            e0.y = fmaxf(acc[mt][nt][1] + ba, 0.f);
            e1.x = fmaxf(acc[mt][nt][2] + bbv, 0.f);
            e1.y = fmaxf(acc[mt][nt][3] + bbv, 0.f);
            sa += e0.x + e0.y; qa += e0.x * e0.x + e0.y * e0.y;
            sb += e1.x + e1.y; qb += e1.x * e1.x + e1.y * e1.y;
            *(float2*)(da + n0) = e0;
            *(float2*)(db + n0) = e1;
        }
        quad_stats(sa, qa, tg, &d_sum2[oc_a], &d_sq2[oc_a]);
        quad_stats(sb, qb, tg, &d_sum2[oc_b], &d_sq2[oc_b]);
    }
}

// ---------------- conv3: 1x1 256->128 via HMMA, 4 blocks/CTA, BN2 folded, fused stats ----------------
#define X3BLK  18432
#define W3OFF  73728
#define W3PART 18432
#define SMEM_C3M (W3OFF + 2 * W3PART)
__global__ __launch_bounds__(256, 1) void conv3m_kernel(const float* __restrict__ b3) {
    extern __shared__ float smf[];
    char* smem = (char*)smf;
    int t = threadIdx.x, w = t >> 5, lane = t & 31;
    int g = lane >> 2, tg = lane & 3;
    int blk0 = blockIdx.x * 4;
    int mblk = w >> 1;
    int ocb  = (w & 1) * 64;

    float acc[4][8][4];
    #pragma unroll
    for (int mt = 0; mt < 4; mt++)
        #pragma unroll
        for (int nt = 0; nt < 8; nt++)
            #pragma unroll
            for (int e = 0; e < 4; e++) acc[mt][nt][e] = 0.0f;

    int xblk = t >> 6, xic = t & 63;

    for (int chunk = 0; chunk < 4; chunk++) {
        __syncthreads();
        {
            int icg = chunk * 64 + xic;
            const float* src = g2buf + ((size_t)(blk0 + xblk) * C2 + icg) * 64;
            float a = d_a2[icg], bb = d_b2[icg];
            char* xb = smem + xblk * X3BLK + xic * 2;
            #pragma unroll
            for (int j = 0; j < 16; j++) {
                float4 v4 = ((const float4*)src)[j];
                float vals[4] = {v4.x, v4.y, v4.z, v4.w};
                #pragma unroll
                for (int e = 0; e < 4; e++) {
                    int px = j * 4 + e;
                    float xv = a * vals[e] + bb;
                    __nv_bfloat16 h = __float2bfloat16(xv);
                    __nv_bfloat16 l = __float2bfloat16(xv - __bfloat162float(h));
                    *(__nv_bfloat16*)(xb + px * X1STR) = h;
                    *(__nv_bfloat16*)(xb + X1PART + px * X1STR) = l;
                }
            }
        }
        {
            int part = t >> 7, oc = t & 127;
            const __nv_bfloat16* ws = (part ? w3l : w3h) + (size_t)chunk * 8192 + oc * 64;
            const uint4* s = (const uint4*)ws;
            uint4* d = (uint4*)(smem + W3OFF + part * W3PART + oc * X1STR);
            #pragma unroll
            for (int q = 0; q < 8; q++) d[q] = s[q];
        }
        __syncthreads();

        #pragma unroll 1
        for (int pass = 0; pass < 3; pass++) {
            const char* A  = smem + W3OFF + ((pass == 1) ? W3PART : 0);
            const char* Bp = smem + mblk * X3BLK + ((pass == 2) ? X1PART : 0);
            #pragma unroll
            for (int k4 = 0; k4 < 4; k4++) {
                int kb = (k4 * 16 + 2 * tg) * 2;
                unsigned af[4][4];
                #pragma unroll
                for (int mt = 0; mt < 4; mt++) {
                    const char* ar = A + (ocb + mt * 16 + g) * X1STR + kb;
                    af[mt][0] = *(const unsigned*)ar;
                    af[mt][1] = *(const unsigned*)(ar + 8 * X1STR);
                    af[mt][2] = *(const unsigned*)(ar + 16);
                    af[mt][3] = *(const unsigned*)(ar + 8 * X1STR + 16);
                }
                #pragma unroll
                for (int nt = 0; nt < 8; nt++) {
                    const char* br = Bp + (nt * 8 + g) * X1STR + kb;
                    unsigned b0 = *(const unsigned*)br;
                    unsigned b1v = *(const unsigned*)(br + 16);
                    #pragma unroll
                    for (int mt = 0; mt < 4; mt++)
                        mma16816(acc[mt][nt], af[mt], b0, b1v);
                }
            }
        }
    }

    #pragma unroll
    for (int mt = 0; mt < 4; mt++) {
        int oc_a = ocb + mt * 16 + g;
        int oc_b = oc_a + 8;
        float ba = b3[oc_a], bbv = b3[oc_b];
        float* da = g3buf + ((size_t)(blk0 + mblk) * COUT + oc_a) * 64;
        float* db = g3buf + ((size_t)(blk0 + mblk) * COUT + oc_b) * 64;
        float sa = 0.f, qa = 0.f, sb = 0.f, qb = 0.f;
        #pragma unroll
        for (int nt = 0; nt < 8; nt++) {
            int n0 = nt * 8 + tg * 2;
            float2 e0, e1;
            e0.x = fmaxf(acc[mt][nt][0] + ba, 0.f);
            e0.y = fmaxf(acc[mt][nt][1] + ba, 0.f);
            e1.x = fmaxf(acc[mt][nt][2] + bbv, 0.f);
            e1.y = fmaxf(acc[mt][nt][3] + bbv, 0.f);
            sa += e0.x + e0.y; qa += e0.x * e0.x + e0.y * e0.y;
            sb += e1.x + e1.y; qb += e1.x * e1.x + e1.y * e1.y;
            *(float2*)(da + n0) = e0;
            *(float2*)(db + n0) = e1;
        }
        quad_stats(sa, qa, tg, &d_sum3[oc_a], &d_sq3[oc_a]);
        quad_stats(sb, qb, tg, &d_sum3[oc_b], &d_sq3[oc_b]);
    }
}

// ---------------- scatter: BN3(g3) -> image ----------------
__global__ __launch_bounds__(256) void scatter_kernel(const int* __restrict__ abi,
                                                      float* __restrict__ out) {
    int blk = blockIdx.x;
    int n  = abi[blk * 3 + 0];
    int bi = abi[blk * 3 + 1];
    int bj = abi[blk * 3 + 2];
    const float* src = g3buf + (size_t)blk * COUT * 64;
    float* dst = out + (((size_t)(n * COUT)) << 16) + bi * 8 * 256 + bj * 8;
    for (int i = threadIdx.x; i < 2048; i += 256) {
        int c = i >> 4, q = i & 15;
        int r = q >> 1, c4 = (q & 1) * 4;
        float4 v = *reinterpret_cast<const float4*>(src + c * 64 + q * 4);
        float a = d_a3[c], bb = d_b3[c];
        v.x = a * v.x + bb; v.y = a * v.y + bb;
        v.z = a * v.z + bb; v.w = a * v.w + bb;
        *reinterpret_cast<float4*>(dst + (((size_t)c) << 16) + r * 256 + c4) = v;
    }
}

// ---------------- launch ----------------
extern "C" void kernel_launch(void* const* d_in, const int* in_sizes, int n_in,
                              void* d_out, int out_size) {
    const float* x    = (const float*)d_in[0];
    const int*   abi  = (const int*)  d_in[1];
    const float* w_c  = (const float*)d_in[2];
    const float* b_c  = (const float*)d_in[3];
    const float* gm_c = (const float*)d_in[4];
    const float* be_c = (const float*)d_in[5];
    const float* w1   = (const float*)d_in[6];
    const float* b1   = (const float*)d_in[7];
    const float* gm1  = (const float*)d_in[8];
    const float* be1  = (const float*)d_in[9];
    const float* w2   = (const float*)d_in[10];
    const float* b2   = (const float*)d_in[11];
    const float* gm2  = (const float*)d_in[12];
    const float* be2  = (const float*)d_in[13];
    const float* w3   = (const float*)d_in[14];
    const float* b3   = (const float*)d_in[15];
    const float* gm3  = (const float*)d_in[16];
    const float* be3  = (const float*)d_in[17];
    float* out = (float*)d_out;

    cudaFuncSetAttribute(convcm_kernel, cudaFuncAttributeMaxDynamicSharedMemorySize, SMEM_CCM);
    cudaFuncSetAttribute(conv1m_kernel, cudaFuncAttributeMaxDynamicSharedMemorySize, SMEM_C1M);
    cudaFuncSetAttribute(conv2m_kernel, cudaFuncAttributeMaxDynamicSharedMemorySize, SMEM_C2M);
    cudaFuncSetAttribute(conv3m_kernel, cudaFuncAttributeMaxDynamicSharedMemorySize, SMEM_C3M);

    zero_stats_kernel<<<1, 256>>>();
    w2cvt_kernel<<<576, 256>>>(w2);
    w13cvt_kernel<<<64, 256>>>(w1, w3, w_c);

    convcm_kernel<<<4096, 256, SMEM_CCM>>>(x, b_c, out);
    finalize_kernel<<<1, 256>>>(0, gm_c, be_c, 1.0 / 524288.0);
    bnapply_kernel<<<16384, 256>>>(out);

    conv1m_kernel<<<2048, 256, SMEM_C1M>>>(out, abi, b1);
    finalize_kernel<<<1, 256>>>(1, gm1, be1, 1.0 / 262144.0);

    conv2m_kernel<<<2048, 256, SMEM_C2M>>>(b2);
    finalize_kernel<<<1, 256>>>(2, gm2, be2, 1.0 / 262144.0);

    conv3m_kernel<<<1024, 256, SMEM_C3M>>>(b3);
    finalize_kernel<<<1, 256>>>(3, gm3, be3, 1.0 / 262144.0);

    scatter_kernel<<<4096, 256>>>(abi, out);
}

// round 9
// speedup vs baseline: 2.7749x; 1.2945x over previous
#include <cuda_runtime.h>
#include <cuda_bf16.h>
#include <math.h>
#include <stdint.h>

#define B_    8
#define CIN   64
#define COUT  128
#define C2    256
#define HW    65536
#define NBLK  4096
#define EPSV  1e-5f

// ---------------- scratch ----------------
__device__ float g1buf[(size_t)NBLK * C2 * 64];
__device__ float g2buf[(size_t)NBLK * C2 * 64];
__device__ float g3buf[(size_t)NBLK * COUT * 64];

// bf16 hi/lo weights
__device__ __nv_bfloat16 w2h[36 * 16384];   // [tap*4+chunk][oc 256][ic 64]
__device__ __nv_bfloat16 w2l[36 * 16384];
__device__ __nv_bfloat16 w1h[2 * 16384];    // [chunk2][oc 256][ic 64]
__device__ __nv_bfloat16 w1l[2 * 16384];
__device__ __nv_bfloat16 w3h[4 * 8192];     // [chunk4][oc 128][ic 64]
__device__ __nv_bfloat16 w3l[4 * 8192];
__device__ __nv_bfloat16 wch[8192];         // [oc 128][ic 64]
__device__ __nv_bfloat16 wcl[8192];

__device__ double d_sum0[COUT], d_sq0[COUT];
__device__ double d_sum1[C2],   d_sq1[C2];
__device__ double d_sum2[C2],   d_sq2[C2];
__device__ double d_sum3[COUT], d_sq3[COUT];
__device__ float  d_a0[COUT], d_b0[COUT];
__device__ float  d_a1[C2],   d_b1[C2];
__device__ float  d_a2[C2],   d_b2[C2];
__device__ float  d_a3[COUT], d_b3[COUT];

#define PKU(x, y) ((unsigned)(x) | ((unsigned)(y) << 16))

// ---------------- bf16 HMMA helper ----------------
__device__ __forceinline__ void mma16816(float* d, const unsigned* a, unsigned b0, unsigned b1) {
    asm volatile(
        "mma.sync.aligned.m16n8k16.row.col.f32.bf16.bf16.f32 "
        "{%0,%1,%2,%3}, {%4,%5,%6,%7}, {%8,%9}, {%0,%1,%2,%3};"
        : "+f"(d[0]), "+f"(d[1]), "+f"(d[2]), "+f"(d[3])
        : "r"(a[0]), "r"(a[1]), "r"(a[2]), "r"(a[3]), "r"(b0), "r"(b1));
}

// cp.async 16B (L1-bypass)
__device__ __forceinline__ void cp_async16(uint32_t sdst, const void* gsrc) {
    asm volatile("cp.async.cg.shared.global [%0], [%1], 16;" :: "r"(sdst), "l"(gsrc));
}
#define CP_COMMIT() asm volatile("cp.async.commit_group;" ::: "memory")
#define CP_WAIT0()  asm volatile("cp.async.wait_group 0;" ::: "memory")

__device__ __forceinline__ void quad_stats(float s, float s2, int tg,
                                           double* gsum, double* gsq) {
    s  += __shfl_xor_sync(0xffffffffu, s, 1);
    s  += __shfl_xor_sync(0xffffffffu, s, 2);
    s2 += __shfl_xor_sync(0xffffffffu, s2, 1);
    s2 += __shfl_xor_sync(0xffffffffu, s2, 2);
    if (tg == 0) { atomicAdd(gsum, (double)s); atomicAdd(gsq, (double)s2); }
}

// ---------------- utility ----------------
__global__ void zero_stats_kernel() {
    int t = threadIdx.x;
    if (t < COUT) { d_sum0[t] = 0.0; d_sq0[t] = 0.0; d_sum3[t] = 0.0; d_sq3[t] = 0.0; }
    d_sum1[t] = 0.0; d_sq1[t] = 0.0; d_sum2[t] = 0.0; d_sq2[t] = 0.0;
}

__global__ void finalize_kernel(int stage, const float* __restrict__ gamma,
                                const float* __restrict__ beta, double invN) {
    int t = threadIdx.x;
    const double *sum, *sq; float *a, *bsh; int C;
    if (stage == 0)      { sum = d_sum0; sq = d_sq0; a = d_a0; bsh = d_b0; C = COUT; }
    else if (stage == 1) { sum = d_sum1; sq = d_sq1; a = d_a1; bsh = d_b1; C = C2; }
    else if (stage == 2) { sum = d_sum2; sq = d_sq2; a = d_a2; bsh = d_b2; C = C2; }
    else                 { sum = d_sum3; sq = d_sq3; a = d_a3; bsh = d_b3; C = COUT; }
    if (t < C) {
        double mean = sum[t] * invN;
        double var  = sq[t] * invN - mean * mean;
        float v = fmaxf((float)var, 0.0f);
        float av = gamma[t] * rsqrtf(v + EPSV);
        a[t] = av;
        bsh[t] = beta[t] - av * (float)mean;
    }
}

// ---------------- weight converts ----------------
__global__ __launch_bounds__(256) void w2cvt_kernel(const float* __restrict__ w2) {
    int i4 = blockIdx.x * 256 + threadIdx.x;
    int ic0 = (i4 & 15) * 4;
    int oc  = (i4 >> 4) & 255;
    int tc  = i4 >> 12;
    int tap = tc >> 2, chunk = tc & 3;
    #pragma unroll
    for (int e = 0; e < 4; e++) {
        int ic = ic0 + e;
        float v = w2[(size_t)oc * 2304 + (chunk * 64 + ic) * 9 + tap];
        __nv_bfloat16 h = __float2bfloat16(v);
        w2h[(size_t)tc * 16384 + oc * 64 + ic] = h;
        w2l[(size_t)tc * 16384 + oc * 64 + ic] = __float2bfloat16(v - __bfloat162float(h));
    }
}

__global__ __launch_bounds__(256) void w13cvt_kernel(const float* __restrict__ w1,
                                                     const float* __restrict__ w3,
                                                     const float* __restrict__ wc) {
    int i = blockIdx.x * 256 + threadIdx.x;   // 0..16383
    {
        #pragma unroll
        for (int e = 0; e < 2; e++) {
            int idx = i * 2 + e;
            int ic = idx & 63, oc = (idx >> 6) & 255, ch = idx >> 14;
            float v = w1[(size_t)oc * 128 + ch * 64 + ic];
            __nv_bfloat16 h = __float2bfloat16(v);
            w1h[idx] = h;
            w1l[idx] = __float2bfloat16(v - __bfloat162float(h));
        }
    }
    {
        #pragma unroll
        for (int e = 0; e < 2; e++) {
            int idx = i * 2 + e;
            int ic = idx & 63, oc = (idx >> 6) & 127, ch = idx >> 13;
            float v = w3[(size_t)oc * 256 + ch * 64 + ic];
            __nv_bfloat16 h = __float2bfloat16(v);
            w3h[idx] = h;
            w3l[idx] = __float2bfloat16(v - __bfloat162float(h));
        }
    }
    if (i < 8192) {
        float v = wc[i];
        __nv_bfloat16 h = __float2bfloat16(v);
        wch[i] = h;
        wcl[i] = __float2bfloat16(v - __bfloat162float(h));
    }
}

// ---------------- convc: 1x1 64->128 + relu via HMMA, 128 px/CTA, fused stats ----------------
#define XCSTR  144
#define XCPART 18432
#define WCOFF  36864
#define WCPART 18432
#define SMEM_CCM (WCOFF + 2 * WCPART)
__global__ __launch_bounds__(256, 2) void convcm_kernel(const float* __restrict__ x,
                                                        const float* __restrict__ bc,
                                                        float* __restrict__ out) {
    extern __shared__ float smf[];
    char* smem = (char*)smf;
    int t = threadIdx.x, w = t >> 5, lane = t & 31;
    int g = lane >> 2, tg = lane & 3;
    int b  = blockIdx.x >> 9;
    int p0 = (blockIdx.x & 511) << 7;
    int ocb = (w & 1) * 64;
    int pxb = (w >> 1) * 32;

    {
        int icp = t & 31, pxg = t >> 5;
        const float* s0 = x + (((size_t)(b * CIN + icp * 2)) << 16) + p0 + pxg * 16;
        const float* s1 = s0 + HW;
        char* xb = smem + icp * 4;
        #pragma unroll
        for (int q = 0; q < 4; q++) {
            float4 u0 = ((const float4*)s0)[q];
            float4 u1 = ((const float4*)s1)[q];
            float v0[4] = {u0.x, u0.y, u0.z, u0.w};
            float v1[4] = {u1.x, u1.y, u1.z, u1.w};
            #pragma unroll
            for (int e = 0; e < 4; e++) {
                int px = pxg * 16 + q * 4 + e;
                __nv_bfloat16 h0 = __float2bfloat16(v0[e]);
                __nv_bfloat16 h1 = __float2bfloat16(v1[e]);
                __nv_bfloat16 l0 = __float2bfloat16(v0[e] - __bfloat162float(h0));
                __nv_bfloat16 l1 = __float2bfloat16(v1[e] - __bfloat162float(h1));
                *(unsigned*)(xb + px * XCSTR) =
                    PKU(__bfloat16_as_ushort(h0), __bfloat16_as_ushort(h1));
                *(unsigned*)(xb + XCPART + px * XCSTR) =
                    PKU(__bfloat16_as_ushort(l0), __bfloat16_as_ushort(l1));
            }
        }
    }
    {
        int part = t >> 7, oc = t & 127;
        const __nv_bfloat16* ws = (part ? wcl : wch) + oc * 64;
        const uint4* s = (const uint4*)ws;
        uint4* d = (uint4*)(smem + WCOFF + part * WCPART + oc * XCSTR);
        #pragma unroll
        for (int q = 0; q < 8; q++) d[q] = s[q];
    }
    __syncthreads();

    float acc[4][4][4];
    #pragma unroll
    for (int mt = 0; mt < 4; mt++)
        #pragma unroll
        for (int nt = 0; nt < 4; nt++)
            #pragma unroll
            for (int e = 0; e < 4; e++) acc[mt][nt][e] = 0.0f;

    #pragma unroll 1
    for (int pass = 0; pass < 3; pass++) {
        const char* A  = smem + WCOFF + ((pass == 1) ? WCPART : 0);
        const char* Bp = smem + ((pass == 2) ? XCPART : 0);
        #pragma unroll
        for (int k4 = 0; k4 < 4; k4++) {
            int kb = (k4 * 16 + 2 * tg) * 2;
            unsigned af[4][4];
            #pragma unroll
            for (int mt = 0; mt < 4; mt++) {
                const char* ar = A + (ocb + mt * 16 + g) * XCSTR + kb;
                af[mt][0] = *(const unsigned*)ar;
                af[mt][1] = *(const unsigned*)(ar + 8 * XCSTR);
                af[mt][2] = *(const unsigned*)(ar + 16);
                af[mt][3] = *(const unsigned*)(ar + 8 * XCSTR + 16);
            }
            #pragma unroll
            for (int nt = 0; nt < 4; nt++) {
                const char* br = Bp + (pxb + nt * 8 + g) * XCSTR + kb;
                unsigned b0 = *(const unsigned*)br;
                unsigned b1v = *(const unsigned*)(br + 16);
                #pragma unroll
                for (int mt = 0; mt < 4; mt++)
                    mma16816(acc[mt][nt], af[mt], b0, b1v);
            }
        }
    }

    float* dstb = out + (((size_t)(b * COUT)) << 16) + p0;
    #pragma unroll
    for (int mt = 0; mt < 4; mt++) {
        int oc_a = ocb + mt * 16 + g;
        int oc_b = oc_a + 8;
        float ba = bc[oc_a], bbv = bc[oc_b];
        float* da = dstb + (((size_t)oc_a) << 16) + pxb;
        float* db = dstb + (((size_t)oc_b) << 16) + pxb;
        float sa = 0.f, qa = 0.f, sb = 0.f, qb = 0.f;
        #pragma unroll
        for (int nt = 0; nt < 4; nt++) {
            int n0 = nt * 8 + tg * 2;
            float2 e0, e1;
            e0.x = fmaxf(acc[mt][nt][0] + ba, 0.f);
            e0.y = fmaxf(acc[mt][nt][1] + ba, 0.f);
            e1.x = fmaxf(acc[mt][nt][2] + bbv, 0.f);
            e1.y = fmaxf(acc[mt][nt][3] + bbv, 0.f);
            sa += e0.x + e0.y; qa += e0.x * e0.x + e0.y * e0.y;
            sb += e1.x + e1.y; qb += e1.x * e1.x + e1.y * e1.y;
            *(float2*)(da + n0) = e0;
            *(float2*)(db + n0) = e1;
        }
        quad_stats(sa, qa, tg, &d_sum0[oc_a], &d_sq0[oc_a]);
        quad_stats(sb, qb, tg, &d_sum0[oc_b], &d_sq0[oc_b]);
    }
}

__global__ __launch_bounds__(256) void bnapply_kernel(float* __restrict__ y) {
    int nth = gridDim.x * blockDim.x;
    int total = (B_ * COUT * HW) / 4;
    for (int i = blockIdx.x * blockDim.x + threadIdx.x; i < total; i += nth) {
        int c = (i >> 14) & 127;
        float4 v = reinterpret_cast<float4*>(y)[i];
        float a = d_a0[c], bb = d_b0[c];
        v.x = a * v.x + bb; v.y = a * v.y + bb;
        v.z = a * v.z + bb; v.w = a * v.w + bb;
        reinterpret_cast<float4*>(y)[i] = v;
    }
}

// ---------------- conv1: gather + 1x1 128->256 via HMMA, 2 blocks/CTA, fused stats ----------------
#define X1STR  144
#define X1PART 9216
#define X1BLK  18432
#define W1OFF  36864
#define W1PART 36864
#define SMEM_C1M (W1OFF + 2 * W1PART)
__global__ __launch_bounds__(256, 1) void conv1m_kernel(const float* __restrict__ xbn,
                                                        const int* __restrict__ abi,
                                                        const float* __restrict__ b1) {
    extern __shared__ float smf[];
    char* smem = (char*)smf;
    int t = threadIdx.x, w = t >> 5, lane = t & 31;
    int g = lane >> 2, tg = lane & 3;
    int blk0 = blockIdx.x * 2;
    int mblk = w >> 2;
    int ocb  = (w & 3) * 64;

    float acc[4][8][4];
    #pragma unroll
    for (int mt = 0; mt < 4; mt++)
        #pragma unroll
        for (int nt = 0; nt < 8; nt++)
            #pragma unroll
            for (int e = 0; e < 4; e++) acc[mt][nt][e] = 0.0f;

    int brow = t >> 1, bsub = t & 1;
    int xblk = brow >> 6, xic = brow & 63;
    int n_  = abi[(blk0 + xblk) * 3 + 0];
    int bi_ = abi[(blk0 + xblk) * 3 + 1];
    int bj_ = abi[(blk0 + xblk) * 3 + 2];
    const float* gsrc0 = xbn + (((size_t)(n_ * COUT)) << 16) + bi_ * 2048 + bj_ * 8;

    for (int chunk = 0; chunk < 2; chunk++) {
        __syncthreads();
        {
            int icg = chunk * 64 + xic;
            const float* src = gsrc0 + (((size_t)icg) << 16) + bsub * 4 * 256;
            char* xb = smem + xblk * X1BLK + xic * 2;
            #pragma unroll
            for (int r4 = 0; r4 < 4; r4++) {
                float4 u  = *reinterpret_cast<const float4*>(src + r4 * 256);
                float4 v2 = *reinterpret_cast<const float4*>(src + r4 * 256 + 4);
                float vals[8] = {u.x, u.y, u.z, u.w, v2.x, v2.y, v2.z, v2.w};
                int px0 = bsub * 32 + r4 * 8;
                #pragma unroll
                for (int e = 0; e < 8; e++) {
                    float xv = vals[e];
                    __nv_bfloat16 h = __float2bfloat16(xv);
                    __nv_bfloat16 l = __float2bfloat16(xv - __bfloat162float(h));
                    *(__nv_bfloat16*)(xb + (px0 + e) * X1STR) = h;
                    *(__nv_bfloat16*)(xb + X1PART + (px0 + e) * X1STR) = l;
                }
            }
        }
        #pragma unroll
        for (int rr = 0; rr < 2; rr++) {
            int r = t + rr * 256;
            int part = r >> 8, oc = r & 255;
            const __nv_bfloat16* ws = (part ? w1l : w1h) + (size_t)chunk * 16384 + oc * 64;
            const uint4* s = (const uint4*)ws;
            uint4* d = (uint4*)(smem + W1OFF + part * W1PART + oc * X1STR);
            #pragma unroll
            for (int q = 0; q < 8; q++) d[q] = s[q];
        }
        __syncthreads();

        #pragma unroll 1
        for (int pass = 0; pass < 3; pass++) {
            const char* A  = smem + W1OFF + ((pass == 1) ? W1PART : 0);
            const char* Bp = smem + mblk * X1BLK + ((pass == 2) ? X1PART : 0);
            #pragma unroll
            for (int k4 = 0; k4 < 4; k4++) {
                int kb = (k4 * 16 + 2 * tg) * 2;
                unsigned af[4][4];
                #pragma unroll
                for (int mt = 0; mt < 4; mt++) {
                    const char* ar = A + (ocb + mt * 16 + g) * X1STR + kb;
                    af[mt][0] = *(const unsigned*)ar;
                    af[mt][1] = *(const unsigned*)(ar + 8 * X1STR);
                    af[mt][2] = *(const unsigned*)(ar + 16);
                    af[mt][3] = *(const unsigned*)(ar + 8 * X1STR + 16);
                }
                #pragma unroll
                for (int nt = 0; nt < 8; nt++) {
                    const char* br = Bp + (nt * 8 + g) * X1STR + kb;
                    unsigned b0 = *(const unsigned*)br;
                    unsigned b1v = *(const unsigned*)(br + 16);
                    #pragma unroll
                    for (int mt = 0; mt < 4; mt++)
                        mma16816(acc[mt][nt], af[mt], b0, b1v);
                }
            }
        }
    }

    #pragma unroll
    for (int mt = 0; mt < 4; mt++) {
        int oc_a = ocb + mt * 16 + g;
        int oc_b = oc_a + 8;
        float ba = b1[oc_a], bbv = b1[oc_b];
        float* da = g1buf + ((size_t)(blk0 + mblk) * C2 + oc_a) * 64;
        float* db = g1buf + ((size_t)(blk0 + mblk) * C2 + oc_b) * 64;
        float sa = 0.f, qa = 0.f, sb = 0.f, qb = 0.f;
        #pragma unroll
        for (int nt = 0; nt < 8; nt++) {
            int n0 = nt * 8 + tg * 2;
            float2 e0, e1;
            e0.x = fmaxf(acc[mt][nt][0] + ba, 0.f);
            e0.y = fmaxf(acc[mt][nt][1] + ba, 0.f);
            e1.x = fmaxf(acc[mt][nt][2] + bbv, 0.f);
            e1.y = fmaxf(acc[mt][nt][3] + bbv, 0.f);
            sa += e0.x + e0.y; qa += e0.x * e0.x + e0.y * e0.y;
            sb += e1.x + e1.y; qb += e1.x * e1.x + e1.y * e1.y;
            *(float2*)(da + n0) = e0;
            *(float2*)(db + n0) = e1;
        }
        quad_stats(sa, qa, tg, &d_sum1[oc_a], &d_sq1[oc_a]);
        quad_stats(sb, qb, tg, &d_sum1[oc_b], &d_sq1[oc_b]);
    }
}

// ---------------- conv2: 3x3 via HMMA, padded-2D X, cp.async double-buffered W ----------------
#define X2ARR  14400
#define X2BLK  28800
#define W2OFF  57600
#define W2PART 36864
#define W2BUF  73728
#define SMEM_C2M (W2OFF + 2 * W2BUF)
__global__ __launch_bounds__(256, 1) void conv2m_kernel(const float* __restrict__ b2) {
    extern __shared__ float smf[];
    char* smem = (char*)smf;
    uint32_t sbase = (uint32_t)__cvta_generic_to_shared(smem);
    int t = threadIdx.x, w = t >> 5, lane = t & 31;
    int g = lane >> 2, tg = lane & 3;
    int blk0 = blockIdx.x * 2;
    int mblk = w >> 2;
    int ocb  = (w & 3) * 64;

    float acc[4][8][4];
    #pragma unroll
    for (int mt = 0; mt < 4; mt++)
        #pragma unroll
        for (int nt = 0; nt < 8; nt++)
            #pragma unroll
            for (int e = 0; e < 4; e++) acc[mt][nt][e] = 0.0f;

    // zero X region once (halo stays zero)
    for (int i = t; i < W2OFF / 16; i += 256) ((uint4*)smem)[i] = make_uint4(0, 0, 0, 0);

    int xblk = t >> 7;
    int icp  = (t >> 2) & 31;
    int pxg  = t & 3;

    // W prefetch helper indices: thread copies 16x16B; idx = t + j*256 over 4096
    // row = idx>>3 (0..511), q = idx&7 ; part = row>>8, oc = row&255
    for (int chunk = 0; chunk < 4; chunk++) {
        __syncthreads();            // prior chunk MMA reads done (X and W buf0)
        // prefetch W(tap0) -> buf0, overlapped with X build
        {
            int tc = chunk;         // tap0*4 + chunk
            #pragma unroll
            for (int j = 0; j < 16; j++) {
                int idx = t + j * 256;
                int row = idx >> 3, q = idx & 7;
                int part = row >> 8, oc = row & 255;
                const __nv_bfloat16* gs = (part ? w2l : w2h) + (size_t)tc * 16384 + oc * 64 + q * 8;
                uint32_t sd = sbase + W2OFF + part * W2PART + oc * X1STR + q * 16;
                cp_async16(sd, gs);
            }
            CP_COMMIT();
        }
        // X build
        {
            int ic0 = chunk * 64 + icp * 2;
            const float* s0 = g1buf + ((size_t)(blk0 + xblk) * C2 + ic0) * 64 + pxg * 16;
            const float* s1 = s0 + 64;
            float a0 = d_a1[ic0],     c0 = d_b1[ic0];
            float a1 = d_a1[ic0 + 1], c1 = d_b1[ic0 + 1];
            char* xb = smem + xblk * X2BLK + icp * 4;
            #pragma unroll
            for (int q = 0; q < 4; q++) {
                float4 u0 = ((const float4*)s0)[q];
                float4 u1 = ((const float4*)s1)[q];
                float v0[4] = {u0.x, u0.y, u0.z, u0.w};
                float v1[4] = {u1.x, u1.y, u1.z, u1.w};
                #pragma unroll
                for (int e = 0; e < 4; e++) {
                    int p = pxg * 16 + q * 4 + e;
                    int row = ((p >> 3) + 1) * 10 + (p & 7) + 1;
                    float x0 = a0 * v0[e] + c0;
                    float x1 = a1 * v1[e] + c1;
                    __nv_bfloat16 h0 = __float2bfloat16(x0);
                    __nv_bfloat16 h1 = __float2bfloat16(x1);
                    __nv_bfloat16 l0 = __float2bfloat16(x0 - __bfloat162float(h0));
                    __nv_bfloat16 l1 = __float2bfloat16(x1 - __bfloat162float(h1));
                    *(unsigned*)(xb + row * X1STR) =
                        PKU(__bfloat16_as_ushort(h0), __bfloat16_as_ushort(h1));
                    *(unsigned*)(xb + X2ARR + row * X1STR) =
                        PKU(__bfloat16_as_ushort(l0), __bfloat16_as_ushort(l1));
                }
            }
        }

        for (int tap = 0; tap < 9; tap++) {
            CP_WAIT0();
            __syncthreads();        // W(tap) visible + X build done + tap-1 MMA reads done
            int buf = tap & 1;
            if (tap < 8) {          // prefetch W(tap+1) -> other buffer
                int tc = (tap + 1) * 4 + chunk;
                int ob = buf ^ 1;
                #pragma unroll
                for (int j = 0; j < 16; j++) {
                    int idx = t + j * 256;
                    int row = idx >> 3, q = idx & 7;
                    int part = row >> 8, oc = row & 255;
                    const __nv_bfloat16* gs = (part ? w2l : w2h) + (size_t)tc * 16384 + oc * 64 + q * 8;
                    uint32_t sd = sbase + W2OFF + ob * W2BUF + part * W2PART + oc * X1STR + q * 16;
                    cp_async16(sd, gs);
                }
                CP_COMMIT();
            }

            int dr = tap / 3, dc = tap % 3;
            int rowc = dr * 10 + dc + g;
            #pragma unroll 1
            for (int pass = 0; pass < 3; pass++) {
                const char* A  = smem + W2OFF + buf * W2BUF + ((pass == 1) ? W2PART : 0);
                const char* Bp = smem + mblk * X2BLK + ((pass == 2) ? X2ARR : 0);
                #pragma unroll
                for (int k4 = 0; k4 < 4; k4++) {
                    int kb = (k4 * 16 + 2 * tg) * 2;
                    unsigned af[4][4];
                    #pragma unroll
                    for (int mt = 0; mt < 4; mt++) {
                        const char* ar = A + (ocb + mt * 16 + g) * X1STR + kb;
                        af[mt][0] = *(const unsigned*)ar;
                        af[mt][1] = *(const unsigned*)(ar + 8 * X1STR);
                        af[mt][2] = *(const unsigned*)(ar + 16);
                        af[mt][3] = *(const unsigned*)(ar + 8 * X1STR + 16);
                    }
                    #pragma unroll
                    for (int nt = 0; nt < 8; nt++) {
                        const char* br = Bp + (rowc + nt * 10) * X1STR + kb;
                        unsigned b0 = *(const unsigned*)br;
                        unsigned b1 = *(const unsigned*)(br + 16);
                        #pragma unroll
                        for (int mt = 0; mt < 4; mt++)
                            mma16816(acc[mt][nt], af[mt], b0, b1);
                    }
                }
            }
        }
    }

    #pragma unroll
    for (int mt = 0; mt < 4; mt++) {
        int oc_a = ocb + mt * 16 + g;
        int oc_b = oc_a + 8;
        float ba = b2[oc_a], bbv = b2[oc_b];
        float* da = g2buf + ((size_t)(blk0 + mblk) * C2 + oc_a) * 64;
        float* db = g2buf + ((size_t)(blk0 + mblk) * C2 + oc_b) * 64;
        float sa = 0.f, qa = 0.f, sb = 0.f, qb = 0.f;
        #pragma unroll
        for (int nt = 0; nt < 8; nt++) {
            int n0 = nt * 8 + tg * 2;
            float2 e0, e1;
            e0.x = fmaxf(acc[mt][nt][0] + ba, 0.f);
            e0.y = fmaxf(acc[mt][nt][1] + ba, 0.f);
            e1.x = fmaxf(acc[mt][nt][2] + bbv, 0.f);
            e1.y = fmaxf(acc[mt][nt][3] + bbv, 0.f);
            sa += e0.x + e0.y; qa += e0.x * e0.x + e0.y * e0.y;
            sb += e1.x + e1.y; qb += e1.x * e1.x + e1.y * e1.y;
            *(float2*)(da + n0) = e0;
            *(float2*)(db + n0) = e1;
        }
        quad_stats(sa, qa, tg, &d_sum2[oc_a], &d_sq2[oc_a]);
        quad_stats(sb, qb, tg, &d_sum2[oc_b], &d_sq2[oc_b]);
    }
}

// ---------------- conv3: 1x1 256->128 via HMMA, 4 blocks/CTA, BN2 folded, fused stats ----------------
#define X3BLK  18432
#define W3OFF  73728
#define W3PART 18432
#define SMEM_C3M (W3OFF + 2 * W3PART)
__global__ __launch_bounds__(256, 1) void conv3m_kernel(const float* __restrict__ b3) {
    extern __shared__ float smf[];
    char* smem = (char*)smf;
    int t = threadIdx.x, w = t >> 5, lane = t & 31;
    int g = lane >> 2, tg = lane & 3;
    int blk0 = blockIdx.x * 4;
    int mblk = w >> 1;
    int ocb  = (w & 1) * 64;

    float acc[4][8][4];
    #pragma unroll
    for (int mt = 0; mt < 4; mt++)
        #pragma unroll
        for (int nt = 0; nt < 8; nt++)
            #pragma unroll
            for (int e = 0; e < 4; e++) acc[mt][nt][e] = 0.0f;

    int xblk = t >> 6, xic = t & 63;

    for (int chunk = 0; chunk < 4; chunk++) {
        __syncthreads();
        {
            int icg = chunk * 64 + xic;
            const float* src = g2buf + ((size_t)(blk0 + xblk) * C2 + icg) * 64;
            float a = d_a2[icg], bb = d_b2[icg];
            char* xb = smem + xblk * X3BLK + xic * 2;
            #pragma unroll
            for (int j = 0; j < 16; j++) {
                float4 v4 = ((const float4*)src)[j];
                float vals[4] = {v4.x, v4.y, v4.z, v4.w};
                #pragma unroll
                for (int e = 0; e < 4; e++) {
                    int px = j * 4 + e;
                    float xv = a * vals[e] + bb;
                    __nv_bfloat16 h = __float2bfloat16(xv);
                    __nv_bfloat16 l = __float2bfloat16(xv - __bfloat162float(h));
                    *(__nv_bfloat16*)(xb + px * X1STR) = h;
                    *(__nv_bfloat16*)(xb + X1PART + px * X1STR) = l;
                }
            }
        }
        {
            int part = t >> 7, oc = t & 127;
            const __nv_bfloat16* ws = (part ? w3l : w3h) + (size_t)chunk * 8192 + oc * 64;
            const uint4* s = (const uint4*)ws;
            uint4* d = (uint4*)(smem + W3OFF + part * W3PART + oc * X1STR);
            #pragma unroll
            for (int q = 0; q < 8; q++) d[q] = s[q];
        }
        __syncthreads();

        #pragma unroll 1
        for (int pass = 0; pass < 3; pass++) {
            const char* A  = smem + W3OFF + ((pass == 1) ? W3PART : 0);
            const char* Bp = smem + mblk * X3BLK + ((pass == 2) ? X1PART : 0);
            #pragma unroll
            for (int k4 = 0; k4 < 4; k4++) {
                int kb = (k4 * 16 + 2 * tg) * 2;
                unsigned af[4][4];
                #pragma unroll
                for (int mt = 0; mt < 4; mt++) {
                    const char* ar = A + (ocb + mt * 16 + g) * X1STR + kb;
                    af[mt][0] = *(const unsigned*)ar;
                    af[mt][1] = *(const unsigned*)(ar + 8 * X1STR);
                    af[mt][2] = *(const unsigned*)(ar + 16);
                    af[mt][3] = *(const unsigned*)(ar + 8 * X1STR + 16);
                }
                #pragma unroll
                for (int nt = 0; nt < 8; nt++) {
                    const char* br = Bp + (nt * 8 + g) * X1STR + kb;
                    unsigned b0 = *(const unsigned*)br;
                    unsigned b1v = *(const unsigned*)(br + 16);
                    #pragma unroll
                    for (int mt = 0; mt < 4; mt++)
                        mma16816(acc[mt][nt], af[mt], b0, b1v);
                }
            }
        }
    }

    #pragma unroll
    for (int mt = 0; mt < 4; mt++) {
        int oc_a = ocb + mt * 16 + g;
        int oc_b = oc_a + 8;
        float ba = b3[oc_a], bbv = b3[oc_b];
        float* da = g3buf + ((size_t)(blk0 + mblk) * COUT + oc_a) * 64;
        float* db = g3buf + ((size_t)(blk0 + mblk) * COUT + oc_b) * 64;
        float sa = 0.f, qa = 0.f, sb = 0.f, qb = 0.f;
        #pragma unroll
        for (int nt = 0; nt < 8; nt++) {
            int n0 = nt * 8 + tg * 2;
            float2 e0, e1;
            e0.x = fmaxf(acc[mt][nt][0] + ba, 0.f);
            e0.y = fmaxf(acc[mt][nt][1] + ba, 0.f);
            e1.x = fmaxf(acc[mt][nt][2] + bbv, 0.f);
            e1.y = fmaxf(acc[mt][nt][3] + bbv, 0.f);
            sa += e0.x + e0.y; qa += e0.x * e0.x + e0.y * e0.y;
            sb += e1.x + e1.y; qb += e1.x * e1.x + e1.y * e1.y;
            *(float2*)(da + n0) = e0;
            *(float2*)(db + n0) = e1;
        }
        quad_stats(sa, qa, tg, &d_sum3[oc_a], &d_sq3[oc_a]);
        quad_stats(sb, qb, tg, &d_sum3[oc_b], &d_sq3[oc_b]);
    }
}

// ---------------- scatter: BN3(g3) -> image ----------------
__global__ __launch_bounds__(256) void scatter_kernel(const int* __restrict__ abi,
                                                      float* __restrict__ out) {
    int blk = blockIdx.x;
    int n  = abi[blk * 3 + 0];
    int bi = abi[blk * 3 + 1];
    int bj = abi[blk * 3 + 2];
    const float* src = g3buf + (size_t)blk * COUT * 64;
    float* dst = out + (((size_t)(n * COUT)) << 16) + bi * 8 * 256 + bj * 8;
    for (int i = threadIdx.x; i < 2048; i += 256) {
        int c = i >> 4, q = i & 15;
        int r = q >> 1, c4 = (q & 1) * 4;
        float4 v = *reinterpret_cast<const float4*>(src + c * 64 + q * 4);
        float a = d_a3[c], bb = d_b3[c];
        v.x = a * v.x + bb; v.y = a * v.y + bb;
        v.z = a * v.z + bb; v.w = a * v.w + bb;
        *reinterpret_cast<float4*>(dst + (((size_t)c) << 16) + r * 256 + c4) = v;
    }
}

// ---------------- launch ----------------
extern "C" void kernel_launch(void* const* d_in, const int* in_sizes, int n_in,
                              void* d_out, int out_size) {
    const float* x    = (const float*)d_in[0];
    const int*   abi  = (const int*)  d_in[1];
    const float* w_c  = (const float*)d_in[2];
    const float* b_c  = (const float*)d_in[3];
    const float* gm_c = (const float*)d_in[4];
    const float* be_c = (const float*)d_in[5];
    const float* w1   = (const float*)d_in[6];
    const float* b1   = (const float*)d_in[7];
    const float* gm1  = (const float*)d_in[8];
    const float* be1  = (const float*)d_in[9];
    const float* w2   = (const float*)d_in[10];
    const float* b2   = (const float*)d_in[11];
    const float* gm2  = (const float*)d_in[12];
    const float* be2  = (const float*)d_in[13];
    const float* w3   = (const float*)d_in[14];
    const float* b3   = (const float*)d_in[15];
    const float* gm3  = (const float*)d_in[16];
    const float* be3  = (const float*)d_in[17];
    float* out = (float*)d_out;

    cudaFuncSetAttribute(convcm_kernel, cudaFuncAttributeMaxDynamicSharedMemorySize, SMEM_CCM);
    cudaFuncSetAttribute(conv1m_kernel, cudaFuncAttributeMaxDynamicSharedMemorySize, SMEM_C1M);
    cudaFuncSetAttribute(conv2m_kernel, cudaFuncAttributeMaxDynamicSharedMemorySize, SMEM_C2M);
    cudaFuncSetAttribute(conv3m_kernel, cudaFuncAttributeMaxDynamicSharedMemorySize, SMEM_C3M);

    zero_stats_kernel<<<1, 256>>>();
    w2cvt_kernel<<<576, 256>>>(w2);
    w13cvt_kernel<<<64, 256>>>(w1, w3, w_c);

    convcm_kernel<<<4096, 256, SMEM_CCM>>>(x, b_c, out);
    finalize_kernel<<<1, 256>>>(0, gm_c, be_c, 1.0 / 524288.0);
    bnapply_kernel<<<16384, 256>>>(out);

    conv1m_kernel<<<2048, 256, SMEM_C1M>>>(out, abi, b1);
    finalize_kernel<<<1, 256>>>(1, gm1, be1, 1.0 / 262144.0);

    conv2m_kernel<<<2048, 256, SMEM_C2M>>>(b2);
    finalize_kernel<<<1, 256>>>(2, gm2, be2, 1.0 / 262144.0);

    conv3m_kernel<<<1024, 256, SMEM_C3M>>>(b3);
    finalize_kernel<<<1, 256>>>(3, gm3, be3, 1.0 / 262144.0);

    scatter_kernel<<<4096, 256>>>(abi, out);
}

// round 10
// speedup vs baseline: 2.8249x; 1.0180x over previous
#include <cuda_runtime.h>
#include <cuda_bf16.h>
#include <math.h>
#include <stdint.h>

#define B_    8
#define CIN   64
#define COUT  128
#define C2    256
#define HW    65536
#define NBLK  4096
#define EPSV  1e-5f

// ---------------- scratch ----------------
__device__ float g1buf[(size_t)NBLK * C2 * 64];
__device__ float g2buf[(size_t)NBLK * C2 * 64];
__device__ float g3buf[(size_t)NBLK * COUT * 64];

// bf16 hi/lo weights
__device__ __nv_bfloat16 w2h[36 * 16384];   // [tap*4+chunk][oc 256][ic 64]
__device__ __nv_bfloat16 w2l[36 * 16384];
__device__ __nv_bfloat16 w1h[2 * 16384];    // [chunk2][oc 256][ic 64]
__device__ __nv_bfloat16 w1l[2 * 16384];
__device__ __nv_bfloat16 w3h[4 * 8192];     // [chunk4][oc 128][ic 64]
__device__ __nv_bfloat16 w3l[4 * 8192];
__device__ __nv_bfloat16 wch[8192];         // [oc 128][ic 64]
__device__ __nv_bfloat16 wcl[8192];

__device__ double d_sum0[COUT], d_sq0[COUT];
__device__ double d_sum1[C2],   d_sq1[C2];
__device__ double d_sum2[C2],   d_sq2[C2];
__device__ double d_sum3[COUT], d_sq3[COUT];
__device__ float  d_a0[COUT], d_b0[COUT];
__device__ float  d_a1[C2],   d_b1[C2];
__device__ float  d_a2[C2],   d_b2[C2];
__device__ float  d_a3[COUT], d_b3[COUT];

#define PKU(x, y) ((unsigned)(x) | ((unsigned)(y) << 16))

// ---------------- bf16 HMMA helper ----------------
__device__ __forceinline__ void mma16816(float* d, const unsigned* a, unsigned b0, unsigned b1) {
    asm volatile(
        "mma.sync.aligned.m16n8k16.row.col.f32.bf16.bf16.f32 "
        "{%0,%1,%2,%3}, {%4,%5,%6,%7}, {%8,%9}, {%0,%1,%2,%3};"
        : "+f"(d[0]), "+f"(d[1]), "+f"(d[2]), "+f"(d[3])
        : "r"(a[0]), "r"(a[1]), "r"(a[2]), "r"(a[3]), "r"(b0), "r"(b1));
}

__device__ __forceinline__ void cp_async16(uint32_t sdst, const void* gsrc) {
    asm volatile("cp.async.cg.shared.global [%0], [%1], 16;" :: "r"(sdst), "l"(gsrc));
}
#define CP_COMMIT() asm volatile("cp.async.commit_group;" ::: "memory")
#define CP_WAIT0()  asm volatile("cp.async.wait_group 0;" ::: "memory")

__device__ __forceinline__ void quad_stats(float s, float s2, int tg,
                                           double* gsum, double* gsq) {
    s  += __shfl_xor_sync(0xffffffffu, s, 1);
    s  += __shfl_xor_sync(0xffffffffu, s, 2);
    s2 += __shfl_xor_sync(0xffffffffu, s2, 1);
    s2 += __shfl_xor_sync(0xffffffffu, s2, 2);
    if (tg == 0) { atomicAdd(gsum, (double)s); atomicAdd(gsq, (double)s2); }
}

// ---------------- utility ----------------
__global__ void zero_stats_kernel() {
    int t = threadIdx.x;
    if (t < COUT) { d_sum0[t] = 0.0; d_sq0[t] = 0.0; d_sum3[t] = 0.0; d_sq3[t] = 0.0; }
    d_sum1[t] = 0.0; d_sq1[t] = 0.0; d_sum2[t] = 0.0; d_sq2[t] = 0.0;
}

__global__ void finalize_kernel(int stage, const float* __restrict__ gamma,
                                const float* __restrict__ beta, double invN) {
    int t = threadIdx.x;
    const double *sum, *sq; float *a, *bsh; int C;
    if (stage == 0)      { sum = d_sum0; sq = d_sq0; a = d_a0; bsh = d_b0; C = COUT; }
    else if (stage == 1) { sum = d_sum1; sq = d_sq1; a = d_a1; bsh = d_b1; C = C2; }
    else if (stage == 2) { sum = d_sum2; sq = d_sq2; a = d_a2; bsh = d_b2; C = C2; }
    else                 { sum = d_sum3; sq = d_sq3; a = d_a3; bsh = d_b3; C = COUT; }
    if (t < C) {
        double mean = sum[t] * invN;
        double var  = sq[t] * invN - mean * mean;
        float v = fmaxf((float)var, 0.0f);
        float av = gamma[t] * rsqrtf(v + EPSV);
        a[t] = av;
        bsh[t] = beta[t] - av * (float)mean;
    }
}

// ---------------- weight converts ----------------
__global__ __launch_bounds__(256) void w2cvt_kernel(const float* __restrict__ w2) {
    int i4 = blockIdx.x * 256 + threadIdx.x;
    int ic0 = (i4 & 15) * 4;
    int oc  = (i4 >> 4) & 255;
    int tc  = i4 >> 12;
    int tap = tc >> 2, chunk = tc & 3;
    #pragma unroll
    for (int e = 0; e < 4; e++) {
        int ic = ic0 + e;
        float v = w2[(size_t)oc * 2304 + (chunk * 64 + ic) * 9 + tap];
        __nv_bfloat16 h = __float2bfloat16(v);
        w2h[(size_t)tc * 16384 + oc * 64 + ic] = h;
        w2l[(size_t)tc * 16384 + oc * 64 + ic] = __float2bfloat16(v - __bfloat162float(h));
    }
}

__global__ __launch_bounds__(256) void w13cvt_kernel(const float* __restrict__ w1,
                                                     const float* __restrict__ w3,
                                                     const float* __restrict__ wc) {
    int i = blockIdx.x * 256 + threadIdx.x;   // 0..16383
    {
        #pragma unroll
        for (int e = 0; e < 2; e++) {
            int idx = i * 2 + e;
            int ic = idx & 63, oc = (idx >> 6) & 255, ch = idx >> 14;
            float v = w1[(size_t)oc * 128 + ch * 64 + ic];
            __nv_bfloat16 h = __float2bfloat16(v);
            w1h[idx] = h;
            w1l[idx] = __float2bfloat16(v - __bfloat162float(h));
        }
    }
    {
        #pragma unroll
        for (int e = 0; e < 2; e++) {
            int idx = i * 2 + e;
            int ic = idx & 63, oc = (idx >> 6) & 127, ch = idx >> 13;
            float v = w3[(size_t)oc * 256 + ch * 64 + ic];
            __nv_bfloat16 h = __float2bfloat16(v);
            w3h[idx] = h;
            w3l[idx] = __float2bfloat16(v - __bfloat162float(h));
        }
    }
    if (i < 8192) {
        float v = wc[i];
        __nv_bfloat16 h = __float2bfloat16(v);
        wch[i] = h;
        wcl[i] = __float2bfloat16(v - __bfloat162float(h));
    }
}

// ---------------- convc: 1x1 64->128 + relu via HMMA, 128 px/CTA, fused stats ----------------
#define XCSTR  144
#define XCPART 18432
#define WCOFF  36864
#define WCPART 18432
#define SMEM_CCM (WCOFF + 2 * WCPART)
__global__ __launch_bounds__(256, 3) void convcm_kernel(const float* __restrict__ x,
                                                        const float* __restrict__ bc,
                                                        float* __restrict__ out) {
    extern __shared__ float smf[];
    char* smem = (char*)smf;
    uint32_t sbase = (uint32_t)__cvta_generic_to_shared(smem);
    int t = threadIdx.x, w = t >> 5, lane = t & 31;
    int g = lane >> 2, tg = lane & 3;
    int b  = blockIdx.x >> 9;
    int p0 = (blockIdx.x & 511) << 7;
    int ocb = (w & 1) * 64;
    int pxb = (w >> 1) * 32;

    // W via cp.async (overlaps with X build)
    {
        int part = t >> 7, oc = t & 127;
        const __nv_bfloat16* ws = (part ? wcl : wch) + oc * 64;
        uint32_t d = sbase + WCOFF + part * WCPART + oc * XCSTR;
        #pragma unroll
        for (int q = 0; q < 8; q++) cp_async16(d + q * 16, ws + q * 8);
        CP_COMMIT();
    }
    {
        int icp = t & 31, pxg = t >> 5;
        const float* s0 = x + (((size_t)(b * CIN + icp * 2)) << 16) + p0 + pxg * 16;
        const float* s1 = s0 + HW;
        char* xb = smem + icp * 4;
        #pragma unroll
        for (int q = 0; q < 4; q++) {
            float4 u0 = ((const float4*)s0)[q];
            float4 u1 = ((const float4*)s1)[q];
            float v0[4] = {u0.x, u0.y, u0.z, u0.w};
            float v1[4] = {u1.x, u1.y, u1.z, u1.w};
            #pragma unroll
            for (int e = 0; e < 4; e++) {
                int px = pxg * 16 + q * 4 + e;
                __nv_bfloat16 h0 = __float2bfloat16(v0[e]);
                __nv_bfloat16 h1 = __float2bfloat16(v1[e]);
                __nv_bfloat16 l0 = __float2bfloat16(v0[e] - __bfloat162float(h0));
                __nv_bfloat16 l1 = __float2bfloat16(v1[e] - __bfloat162float(h1));
                *(unsigned*)(xb + px * XCSTR) =
                    PKU(__bfloat16_as_ushort(h0), __bfloat16_as_ushort(h1));
                *(unsigned*)(xb + XCPART + px * XCSTR) =
                    PKU(__bfloat16_as_ushort(l0), __bfloat16_as_ushort(l1));
            }
        }
    }
    CP_WAIT0();
    __syncthreads();

    float acc[4][4][4];
    #pragma unroll
    for (int mt = 0; mt < 4; mt++)
        #pragma unroll
        for (int nt = 0; nt < 4; nt++)
            #pragma unroll
            for (int e = 0; e < 4; e++) acc[mt][nt][e] = 0.0f;

    #pragma unroll 1
    for (int pass = 0; pass < 3; pass++) {
        const char* A  = smem + WCOFF + ((pass == 1) ? WCPART : 0);
        const char* Bp = smem + ((pass == 2) ? XCPART : 0);
        #pragma unroll
        for (int k4 = 0; k4 < 4; k4++) {
            int kb = (k4 * 16 + 2 * tg) * 2;
            unsigned af[4][4];
            #pragma unroll
            for (int mt = 0; mt < 4; mt++) {
                const char* ar = A + (ocb + mt * 16 + g) * XCSTR + kb;
                af[mt][0] = *(const unsigned*)ar;
                af[mt][1] = *(const unsigned*)(ar + 8 * XCSTR);
                af[mt][2] = *(const unsigned*)(ar + 16);
                af[mt][3] = *(const unsigned*)(ar + 8 * XCSTR + 16);
            }
            #pragma unroll
            for (int nt = 0; nt < 4; nt++) {
                const char* br = Bp + (pxb + nt * 8 + g) * XCSTR + kb;
                unsigned b0 = *(const unsigned*)br;
                unsigned b1v = *(const unsigned*)(br + 16);
                #pragma unroll
                for (int mt = 0; mt < 4; mt++)
                    mma16816(acc[mt][nt], af[mt], b0, b1v);
            }
        }
    }

    float* dstb = out + (((size_t)(b * COUT)) << 16) + p0;
    #pragma unroll
    for (int mt = 0; mt < 4; mt++) {
        int oc_a = ocb + mt * 16 + g;
        int oc_b = oc_a + 8;
        float ba = bc[oc_a], bbv = bc[oc_b];
        float* da = dstb + (((size_t)oc_a) << 16) + pxb;
        float* db = dstb + (((size_t)oc_b) << 16) + pxb;
        float sa = 0.f, qa = 0.f, sb = 0.f, qb = 0.f;
        #pragma unroll
        for (int nt = 0; nt < 4; nt++) {
            int n0 = nt * 8 + tg * 2;
            float2 e0, e1;
            e0.x = fmaxf(acc[mt][nt][0] + ba, 0.f);
            e0.y = fmaxf(acc[mt][nt][1] + ba, 0.f);
            e1.x = fmaxf(acc[mt][nt][2] + bbv, 0.f);
            e1.y = fmaxf(acc[mt][nt][3] + bbv, 0.f);
            sa += e0.x + e0.y; qa += e0.x * e0.x + e0.y * e0.y;
            sb += e1.x + e1.y; qb += e1.x * e1.x + e1.y * e1.y;
            *(float2*)(da + n0) = e0;
            *(float2*)(db + n0) = e1;
        }
        quad_stats(sa, qa, tg, &d_sum0[oc_a], &d_sq0[oc_a]);
        quad_stats(sb, qb, tg, &d_sum0[oc_b], &d_sq0[oc_b]);
    }
}

__global__ __launch_bounds__(256) void bnapply_kernel(float* __restrict__ y) {
    int nth = gridDim.x * blockDim.x;
    int total = (B_ * COUT * HW) / 4;
    for (int i = blockIdx.x * blockDim.x + threadIdx.x; i < total; i += nth) {
        int c = (i >> 14) & 127;
        float4 v = reinterpret_cast<float4*>(y)[i];
        float a = d_a0[c], bb = d_b0[c];
        v.x = a * v.x + bb; v.y = a * v.y + bb;
        v.z = a * v.z + bb; v.w = a * v.w + bb;
        reinterpret_cast<float4*>(y)[i] = v;
    }
}

// ---------------- conv1: gather + 1x1 128->256 via HMMA, 2 blocks/CTA, cp.async W ----------------
#define X1STR  144
#define X1PART 9216
#define X1BLK  18432
#define W1OFF  36864
#define W1PART 36864
#define SMEM_C1M (W1OFF + 2 * W1PART)
__global__ __launch_bounds__(256, 1) void conv1m_kernel(const float* __restrict__ xbn,
                                                        const int* __restrict__ abi,
                                                        const float* __restrict__ b1) {
    extern __shared__ float smf[];
    char* smem = (char*)smf;
    uint32_t sbase = (uint32_t)__cvta_generic_to_shared(smem);
    int t = threadIdx.x, w = t >> 5, lane = t & 31;
    int g = lane >> 2, tg = lane & 3;
    int blk0 = blockIdx.x * 2;
    int mblk = w >> 2;
    int ocb  = (w & 3) * 64;

    float acc[4][8][4];
    #pragma unroll
    for (int mt = 0; mt < 4; mt++)
        #pragma unroll
        for (int nt = 0; nt < 8; nt++)
            #pragma unroll
            for (int e = 0; e < 4; e++) acc[mt][nt][e] = 0.0f;

    int brow = t >> 1, bsub = t & 1;
    int xblk = brow >> 6, xic = brow & 63;
    int n_  = abi[(blk0 + xblk) * 3 + 0];
    int bi_ = abi[(blk0 + xblk) * 3 + 1];
    int bj_ = abi[(blk0 + xblk) * 3 + 2];
    const float* gsrc0 = xbn + (((size_t)(n_ * COUT)) << 16) + bi_ * 2048 + bj_ * 8;

    for (int chunk = 0; chunk < 2; chunk++) {
        __syncthreads();                 // prior MMA reads of X and W done
        // W(chunk) via cp.async, overlapped with X build (single buffer: safe post-barrier)
        {
            #pragma unroll
            for (int j = 0; j < 16; j++) {
                int idx = t + j * 256;
                int row = idx >> 3, q = idx & 7;
                int part = row >> 8, oc = row & 255;
                const __nv_bfloat16* gs = (part ? w1l : w1h) + (size_t)chunk * 16384 + oc * 64 + q * 8;
                uint32_t sd = sbase + W1OFF + part * W1PART + oc * X1STR + q * 16;
                cp_async16(sd, gs);
            }
            CP_COMMIT();
        }
        {
            int icg = chunk * 64 + xic;
            const float* src = gsrc0 + (((size_t)icg) << 16) + bsub * 4 * 256;
            char* xb = smem + xblk * X1BLK + xic * 2;
            #pragma unroll
            for (int r4 = 0; r4 < 4; r4++) {
                float4 u  = *reinterpret_cast<const float4*>(src + r4 * 256);
                float4 v2 = *reinterpret_cast<const float4*>(src + r4 * 256 + 4);
                float vals[8] = {u.x, u.y, u.z, u.w, v2.x, v2.y, v2.z, v2.w};
                int px0 = bsub * 32 + r4 * 8;
                #pragma unroll
                for (int e = 0; e < 8; e++) {
                    float xv = vals[e];
                    __nv_bfloat16 h = __float2bfloat16(xv);
                    __nv_bfloat16 l = __float2bfloat16(xv - __bfloat162float(h));
                    *(__nv_bfloat16*)(xb + (px0 + e) * X1STR) = h;
                    *(__nv_bfloat16*)(xb + X1PART + (px0 + e) * X1STR) = l;
                }
            }
        }
        CP_WAIT0();
        __syncthreads();

        #pragma unroll 1
        for (int pass = 0; pass < 3; pass++) {
            const char* A  = smem + W1OFF + ((pass == 1) ? W1PART : 0);
            const char* Bp = smem + mblk * X1BLK + ((pass == 2) ? X1PART : 0);
            #pragma unroll
            for (int k4 = 0; k4 < 4; k4++) {
                int kb = (k4 * 16 + 2 * tg) * 2;
                unsigned af[4][4];
                #pragma unroll
                for (int mt = 0; mt < 4; mt++) {
                    const char* ar = A + (ocb + mt * 16 + g) * X1STR + kb;
                    af[mt][0] = *(const unsigned*)ar;
                    af[mt][1] = *(const unsigned*)(ar + 8 * X1STR);
                    af[mt][2] = *(const unsigned*)(ar + 16);
                    af[mt][3] = *(const unsigned*)(ar + 8 * X1STR + 16);
                }
                #pragma unroll
                for (int nt = 0; nt < 8; nt++) {
                    const char* br = Bp + (nt * 8 + g) * X1STR + kb;
                    unsigned b0 = *(const unsigned*)br;
                    unsigned b1v = *(const unsigned*)(br + 16);
                    #pragma unroll
                    for (int mt = 0; mt < 4; mt++)
                        mma16816(acc[mt][nt], af[mt], b0, b1v);
                }
            }
        }
    }

    #pragma unroll
    for (int mt = 0; mt < 4; mt++) {
        int oc_a = ocb + mt * 16 + g;
        int oc_b = oc_a + 8;
        float ba = b1[oc_a], bbv = b1[oc_b];
        float* da = g1buf + ((size_t)(blk0 + mblk) * C2 + oc_a) * 64;
        float* db = g1buf + ((size_t)(blk0 + mblk) * C2 + oc_b) * 64;
        float sa = 0.f, qa = 0.f, sb = 0.f, qb = 0.f;
        #pragma unroll
        for (int nt = 0; nt < 8; nt++) {
            int n0 = nt * 8 + tg * 2;
            float2 e0, e1;
            e0.x = fmaxf(acc[mt][nt][0] + ba, 0.f);
            e0.y = fmaxf(acc[mt][nt][1] + ba, 0.f);
            e1.x = fmaxf(acc[mt][nt][2] + bbv, 0.f);
            e1.y = fmaxf(acc[mt][nt][3] + bbv, 0.f);
            sa += e0.x + e0.y; qa += e0.x * e0.x + e0.y * e0.y;
            sb += e1.x + e1.y; qb += e1.x * e1.x + e1.y * e1.y;
            *(float2*)(da + n0) = e0;
            *(float2*)(db + n0) = e1;
        }
        quad_stats(sa, qa, tg, &d_sum1[oc_a], &d_sq1[oc_a]);
        quad_stats(sb, qb, tg, &d_sum1[oc_b], &d_sq1[oc_b]);
    }
}

// ---------------- conv2: 3x3 via HMMA, padded-2D X, cp.async double-buffered W ----------------
#define X2ARR  14400
#define X2BLK  28800
#define W2OFF  57600
#define W2PART 36864
#define W2BUF  73728
#define SMEM_C2M (W2OFF + 2 * W2BUF)
__global__ __launch_bounds__(256, 1) void conv2m_kernel(const float* __restrict__ b2) {
    extern __shared__ float smf[];
    char* smem = (char*)smf;
    uint32_t sbase = (uint32_t)__cvta_generic_to_shared(smem);
    int t = threadIdx.x, w = t >> 5, lane = t & 31;
    int g = lane >> 2, tg = lane & 3;
    int blk0 = blockIdx.x * 2;
    int mblk = w >> 2;
    int ocb  = (w & 3) * 64;

    float acc[4][8][4];
    #pragma unroll
    for (int mt = 0; mt < 4; mt++)
        #pragma unroll
        for (int nt = 0; nt < 8; nt++)
            #pragma unroll
            for (int e = 0; e < 4; e++) acc[mt][nt][e] = 0.0f;

    for (int i = t; i < W2OFF / 16; i += 256) ((uint4*)smem)[i] = make_uint4(0, 0, 0, 0);

    int xblk = t >> 7;
    int icp  = (t >> 2) & 31;
    int pxg  = t & 3;

    for (int chunk = 0; chunk < 4; chunk++) {
        __syncthreads();
        {
            int tc = chunk;
            #pragma unroll
            for (int j = 0; j < 16; j++) {
                int idx = t + j * 256;
                int row = idx >> 3, q = idx & 7;
                int part = row >> 8, oc = row & 255;
                const __nv_bfloat16* gs = (part ? w2l : w2h) + (size_t)tc * 16384 + oc * 64 + q * 8;
                uint32_t sd = sbase + W2OFF + part * W2PART + oc * X1STR + q * 16;
                cp_async16(sd, gs);
            }
            CP_COMMIT();
        }
        {
            int ic0 = chunk * 64 + icp * 2;
            const float* s0 = g1buf + ((size_t)(blk0 + xblk) * C2 + ic0) * 64 + pxg * 16;
            const float* s1 = s0 + 64;
            float a0 = d_a1[ic0],     c0 = d_b1[ic0];
            float a1 = d_a1[ic0 + 1], c1 = d_b1[ic0 + 1];
            char* xb = smem + xblk * X2BLK + icp * 4;
            #pragma unroll
            for (int q = 0; q < 4; q++) {
                float4 u0 = ((const float4*)s0)[q];
                float4 u1 = ((const float4*)s1)[q];
                float v0[4] = {u0.x, u0.y, u0.z, u0.w};
                float v1[4] = {u1.x, u1.y, u1.z, u1.w};
                #pragma unroll
                for (int e = 0; e < 4; e++) {
                    int p = pxg * 16 + q * 4 + e;
                    int row = ((p >> 3) + 1) * 10 + (p & 7) + 1;
                    float x0 = a0 * v0[e] + c0;
                    float x1 = a1 * v1[e] + c1;
                    __nv_bfloat16 h0 = __float2bfloat16(x0);
                    __nv_bfloat16 h1 = __float2bfloat16(x1);
                    __nv_bfloat16 l0 = __float2bfloat16(x0 - __bfloat162float(h0));
                    __nv_bfloat16 l1 = __float2bfloat16(x1 - __bfloat162float(h1));
                    *(unsigned*)(xb + row * X1STR) =
                        PKU(__bfloat16_as_ushort(h0), __bfloat16_as_ushort(h1));
                    *(unsigned*)(xb + X2ARR + row * X1STR) =
                        PKU(__bfloat16_as_ushort(l0), __bfloat16_as_ushort(l1));
                }
            }
        }

        for (int tap = 0; tap < 9; tap++) {
            CP_WAIT0();
            __syncthreads();
            int buf = tap & 1;
            if (tap < 8) {
                int tc = (tap + 1) * 4 + chunk;
                int ob = buf ^ 1;
                #pragma unroll
                for (int j = 0; j < 16; j++) {
                    int idx = t + j * 256;
                    int row = idx >> 3, q = idx & 7;
                    int part = row >> 8, oc = row & 255;
                    const __nv_bfloat16* gs = (part ? w2l : w2h) + (size_t)tc * 16384 + oc * 64 + q * 8;
                    uint32_t sd = sbase + W2OFF + ob * W2BUF + part * W2PART + oc * X1STR + q * 16;
                    cp_async16(sd, gs);
                }
                CP_COMMIT();
            }

            int dr = tap / 3, dc = tap % 3;
            int rowc = dr * 10 + dc + g;
            #pragma unroll 1
            for (int pass = 0; pass < 3; pass++) {
                const char* A  = smem + W2OFF + buf * W2BUF + ((pass == 1) ? W2PART : 0);
                const char* Bp = smem + mblk * X2BLK + ((pass == 2) ? X2ARR : 0);
                #pragma unroll
                for (int k4 = 0; k4 < 4; k4++) {
                    int kb = (k4 * 16 + 2 * tg) * 2;
                    unsigned af[4][4];
                    #pragma unroll
                    for (int mt = 0; mt < 4; mt++) {
                        const char* ar = A + (ocb + mt * 16 + g) * X1STR + kb;
                        af[mt][0] = *(const unsigned*)ar;
                        af[mt][1] = *(const unsigned*)(ar + 8 * X1STR);
                        af[mt][2] = *(const unsigned*)(ar + 16);
                        af[mt][3] = *(const unsigned*)(ar + 8 * X1STR + 16);
                    }
                    #pragma unroll
                    for (int nt = 0; nt < 8; nt++) {
                        const char* br = Bp + (rowc + nt * 10) * X1STR + kb;
                        unsigned b0 = *(const unsigned*)br;
                        unsigned b1 = *(const unsigned*)(br + 16);
                        #pragma unroll
                        for (int mt = 0; mt < 4; mt++)
                            mma16816(acc[mt][nt], af[mt], b0, b1);
                    }
                }
            }
        }
    }

    #pragma unroll
    for (int mt = 0; mt < 4; mt++) {
        int oc_a = ocb + mt * 16 + g;
        int oc_b = oc_a + 8;
        float ba = b2[oc_a], bbv = b2[oc_b];
        float* da = g2buf + ((size_t)(blk0 + mblk) * C2 + oc_a) * 64;
        float* db = g2buf + ((size_t)(blk0 + mblk) * C2 + oc_b) * 64;
        float sa = 0.f, qa = 0.f, sb = 0.f, qb = 0.f;
        #pragma unroll
        for (int nt = 0; nt < 8; nt++) {
            int n0 = nt * 8 + tg * 2;
            float2 e0, e1;
            e0.x = fmaxf(acc[mt][nt][0] + ba, 0.f);
            e0.y = fmaxf(acc[mt][nt][1] + ba, 0.f);
            e1.x = fmaxf(acc[mt][nt][2] + bbv, 0.f);
            e1.y = fmaxf(acc[mt][nt][3] + bbv, 0.f);
            sa += e0.x + e0.y; qa += e0.x * e0.x + e0.y * e0.y;
            sb += e1.x + e1.y; qb += e1.x * e1.x + e1.y * e1.y;
            *(float2*)(da + n0) = e0;
            *(float2*)(db + n0) = e1;
        }
        quad_stats(sa, qa, tg, &d_sum2[oc_a], &d_sq2[oc_a]);
        quad_stats(sb, qb, tg, &d_sum2[oc_b], &d_sq2[oc_b]);
    }
}

// ---------------- conv3: 1x1 256->128 via HMMA, 4 blocks/CTA, cp.async W ----------------
#define X3BLK  18432
#define W3OFF  73728
#define W3PART 18432
#define SMEM_C3M (W3OFF + 2 * W3PART)
__global__ __launch_bounds__(256, 1) void conv3m_kernel(const float* __restrict__ b3) {
    extern __shared__ float smf[];
    char* smem = (char*)smf;
    uint32_t sbase = (uint32_t)__cvta_generic_to_shared(smem);
    int t = threadIdx.x, w = t >> 5, lane = t & 31;
    int g = lane >> 2, tg = lane & 3;
    int blk0 = blockIdx.x * 4;
    int mblk = w >> 1;
    int ocb  = (w & 1) * 64;

    float acc[4][8][4];
    #pragma unroll
    for (int mt = 0; mt < 4; mt++)
        #pragma unroll
        for (int nt = 0; nt < 8; nt++)
            #pragma unroll
            for (int e = 0; e < 4; e++) acc[mt][nt][e] = 0.0f;

    int xblk = t >> 6, xic = t & 63;

    for (int chunk = 0; chunk < 4; chunk++) {
        __syncthreads();
        // W(chunk) via cp.async overlapped with X build (single buffer, post-barrier)
        {
            #pragma unroll
            for (int j = 0; j < 8; j++) {
                int idx = t + j * 256;
                int row = idx >> 3, q = idx & 7;
                int part = row >> 7, oc = row & 127;
                const __nv_bfloat16* gs = (part ? w3l : w3h) + (size_t)chunk * 8192 + oc * 64 + q * 8;
                uint32_t sd = sbase + W3OFF + part * W3PART + oc * X1STR + q * 16;
                cp_async16(sd, gs);
            }
            CP_COMMIT();
        }
        {
            int icg = chunk * 64 + xic;
            const float* src = g2buf + ((size_t)(blk0 + xblk) * C2 + icg) * 64;
            float a = d_a2[icg], bb = d_b2[icg];
            char* xb = smem + xblk * X3BLK + xic * 2;
            #pragma unroll
            for (int j = 0; j < 16; j++) {
                float4 v4 = ((const float4*)src)[j];
                float vals[4] = {v4.x, v4.y, v4.z, v4.w};
                #pragma unroll
                for (int e = 0; e < 4; e++) {
                    int px = j * 4 + e;
                    float xv = a * vals[e] + bb;
                    __nv_bfloat16 h = __float2bfloat16(xv);
                    __nv_bfloat16 l = __float2bfloat16(xv - __bfloat162float(h));
                    *(__nv_bfloat16*)(xb + px * X1STR) = h;
                    *(__nv_bfloat16*)(xb + X1PART + px * X1STR) = l;
                }
            }
        }
        CP_WAIT0();
        __syncthreads();

        #pragma unroll 1
        for (int pass = 0; pass < 3; pass++) {
            const char* A  = smem + W3OFF + ((pass == 1) ? W3PART : 0);
            const char* Bp = smem + mblk * X3BLK + ((pass == 2) ? X1PART : 0);
            #pragma unroll
            for (int k4 = 0; k4 < 4; k4++) {
                int kb = (k4 * 16 + 2 * tg) * 2;
                unsigned af[4][4];
                #pragma unroll
                for (int mt = 0; mt < 4; mt++) {
                    const char* ar = A + (ocb + mt * 16 + g) * X1STR + kb;
                    af[mt][0] = *(const unsigned*)ar;
                    af[mt][1] = *(const unsigned*)(ar + 8 * X1STR);
                    af[mt][2] = *(const unsigned*)(ar + 16);
                    af[mt][3] = *(const unsigned*)(ar + 8 * X1STR + 16);
                }
                #pragma unroll
                for (int nt = 0; nt < 8; nt++) {
                    const char* br = Bp + (nt * 8 + g) * X1STR + kb;
                    unsigned b0 = *(const unsigned*)br;
                    unsigned b1v = *(const unsigned*)(br + 16);
                    #pragma unroll
                    for (int mt = 0; mt < 4; mt++)
                        mma16816(acc[mt][nt], af[mt], b0, b1v);
                }
            }
        }
    }

    #pragma unroll
    for (int mt = 0; mt < 4; mt++) {
        int oc_a = ocb + mt * 16 + g;
        int oc_b = oc_a + 8;
        float ba = b3[oc_a], bbv = b3[oc_b];
        float* da = g3buf + ((size_t)(blk0 + mblk) * COUT + oc_a) * 64;
        float* db = g3buf + ((size_t)(blk0 + mblk) * COUT + oc_b) * 64;
        float sa = 0.f, qa = 0.f, sb = 0.f, qb = 0.f;
        #pragma unroll
        for (int nt = 0; nt < 8; nt++) {
            int n0 = nt * 8 + tg * 2;
            float2 e0, e1;
            e0.x = fmaxf(acc[mt][nt][0] + ba, 0.f);
            e0.y = fmaxf(acc[mt][nt][1] + ba, 0.f);
            e1.x = fmaxf(acc[mt][nt][2] + bbv, 0.f);
            e1.y = fmaxf(acc[mt][nt][3] + bbv, 0.f);
            sa += e0.x + e0.y; qa += e0.x * e0.x + e0.y * e0.y;
            sb += e1.x + e1.y; qb += e1.x * e1.x + e1.y * e1.y;
            *(float2*)(da + n0) = e0;
            *(float2*)(db + n0) = e1;
        }
        quad_stats(sa, qa, tg, &d_sum3[oc_a], &d_sq3[oc_a]);
        quad_stats(sb, qb, tg, &d_sum3[oc_b], &d_sq3[oc_b]);
    }
}

// ---------------- scatter: BN3(g3) -> image ----------------
__global__ __launch_bounds__(256) void scatter_kernel(const int* __restrict__ abi,
                                                      float* __restrict__ out) {
    int blk = blockIdx.x;
    int n  = abi[blk * 3 + 0];
    int bi = abi[blk * 3 + 1];
    int bj = abi[blk * 3 + 2];
    const float* src = g3buf + (size_t)blk * COUT * 64;
    float* dst = out + (((size_t)(n * COUT)) << 16) + bi * 8 * 256 + bj * 8;
    for (int i = threadIdx.x; i < 2048; i += 256) {
        int c = i >> 4, q = i & 15;
        int r = q >> 1, c4 = (q & 1) * 4;
        float4 v = *reinterpret_cast<const float4*>(src + c * 64 + q * 4);
        float a = d_a3[c], bb = d_b3[c];
        v.x = a * v.x + bb; v.y = a * v.y + bb;
        v.z = a * v.z + bb; v.w = a * v.w + bb;
        *reinterpret_cast<float4*>(dst + (((size_t)c) << 16) + r * 256 + c4) = v;
    }
}

// ---------------- launch ----------------
extern "C" void kernel_launch(void* const* d_in, const int* in_sizes, int n_in,
                              void* d_out, int out_size) {
    const float* x    = (const float*)d_in[0];
    const int*   abi  = (const int*)  d_in[1];
    const float* w_c  = (const float*)d_in[2];
    const float* b_c  = (const float*)d_in[3];
    const float* gm_c = (const float*)d_in[4];
    const float* be_c = (const float*)d_in[5];
    const float* w1   = (const float*)d_in[6];
    const float* b1   = (const float*)d_in[7];
    const float* gm1  = (const float*)d_in[8];
    const float* be1  = (const float*)d_in[9];
    const float* w2   = (const float*)d_in[10];
    const float* b2   = (const float*)d_in[11];
    const float* gm2  = (const float*)d_in[12];
    const float* be2  = (const float*)d_in[13];
    const float* w3   = (const float*)d_in[14];
    const float* b3   = (const float*)d_in[15];
    const float* gm3  = (const float*)d_in[16];
    const float* be3  = (const float*)d_in[17];
    float* out = (float*)d_out;

    cudaFuncSetAttribute(convcm_kernel, cudaFuncAttributeMaxDynamicSharedMemorySize, SMEM_CCM);
    cudaFuncSetAttribute(conv1m_kernel, cudaFuncAttributeMaxDynamicSharedMemorySize, SMEM_C1M);
    cudaFuncSetAttribute(conv2m_kernel, cudaFuncAttributeMaxDynamicSharedMemorySize, SMEM_C2M);
    cudaFuncSetAttribute(conv3m_kernel, cudaFuncAttributeMaxDynamicSharedMemorySize, SMEM_C3M);

    zero_stats_kernel<<<1, 256>>>();
    w2cvt_kernel<<<576, 256>>>(w2);
    w13cvt_kernel<<<64, 256>>>(w1, w3, w_c);

    convcm_kernel<<<4096, 256, SMEM_CCM>>>(x, b_c, out);
    finalize_kernel<<<1, 256>>>(0, gm_c, be_c, 1.0 / 524288.0);
    bnapply_kernel<<<16384, 256>>>(out);

    conv1m_kernel<<<2048, 256, SMEM_C1M>>>(out, abi, b1);
    finalize_kernel<<<1, 256>>>(1, gm1, be1, 1.0 / 262144.0);

    conv2m_kernel<<<2048, 256, SMEM_C2M>>>(b2);
    finalize_kernel<<<1, 256>>>(2, gm2, be2, 1.0 / 262144.0);

    conv3m_kernel<<<1024, 256, SMEM_C3M>>>(b3);
    finalize_kernel<<<1, 256>>>(3, gm3, be3, 1.0 / 262144.0);

    scatter_kernel<<<4096, 256>>>(abi, out);
}

// round 11
// speedup vs baseline: 3.8065x; 1.3475x over previous
#include <cuda_runtime.h>
#include <cuda_bf16.h>
#include <cuda_fp16.h>
#include <math.h>
#include <stdint.h>

#define B_    8
#define CIN   64
#define COUT  128
#define C2    256
#define HW    65536
#define NBLK  4096
#define EPSV  1e-5f

// ---------------- scratch ----------------
__device__ float g1buf[(size_t)NBLK * C2 * 64];
__device__ float g2buf[(size_t)NBLK * C2 * 64];
__device__ float g3buf[(size_t)NBLK * COUT * 64];

// weights: conv2 = fp16 single plane; others bf16 hi/lo
__device__ __half        w216[36 * 16384];  // [tap*4+chunk][oc 256][ic 64]
__device__ __nv_bfloat16 w1h[2 * 16384];    // [chunk2][oc 256][ic 64]
__device__ __nv_bfloat16 w1l[2 * 16384];
__device__ __nv_bfloat16 w3h[4 * 8192];     // [chunk4][oc 128][ic 64]
__device__ __nv_bfloat16 w3l[4 * 8192];
__device__ __nv_bfloat16 wch[8192];         // [oc 128][ic 64]
__device__ __nv_bfloat16 wcl[8192];

__device__ double d_sum0[COUT], d_sq0[COUT];
__device__ double d_sum1[C2],   d_sq1[C2];
__device__ double d_sum2[C2],   d_sq2[C2];
__device__ double d_sum3[COUT], d_sq3[COUT];
__device__ float  d_a0[COUT], d_b0[COUT];
__device__ float  d_a1[C2],   d_b1[C2];
__device__ float  d_a2[C2],   d_b2[C2];
__device__ float  d_a3[COUT], d_b3[COUT];

#define PKU(x, y) ((unsigned)(x) | ((unsigned)(y) << 16))

// ---------------- MMA helpers ----------------
__device__ __forceinline__ void mma16816(float* d, const unsigned* a, unsigned b0, unsigned b1) {
    asm volatile(
        "mma.sync.aligned.m16n8k16.row.col.f32.bf16.bf16.f32 "
        "{%0,%1,%2,%3}, {%4,%5,%6,%7}, {%8,%9}, {%0,%1,%2,%3};"
        : "+f"(d[0]), "+f"(d[1]), "+f"(d[2]), "+f"(d[3])
        : "r"(a[0]), "r"(a[1]), "r"(a[2]), "r"(a[3]), "r"(b0), "r"(b1));
}
__device__ __forceinline__ void mma16816h(float* d, const unsigned* a, unsigned b0, unsigned b1) {
    asm volatile(
        "mma.sync.aligned.m16n8k16.row.col.f32.f16.f16.f32 "
        "{%0,%1,%2,%3}, {%4,%5,%6,%7}, {%8,%9}, {%0,%1,%2,%3};"
        : "+f"(d[0]), "+f"(d[1]), "+f"(d[2]), "+f"(d[3])
        : "r"(a[0]), "r"(a[1]), "r"(a[2]), "r"(a[3]), "r"(b0), "r"(b1));
}

__device__ __forceinline__ void cp_async16(uint32_t sdst, const void* gsrc) {
    asm volatile("cp.async.cg.shared.global [%0], [%1], 16;" :: "r"(sdst), "l"(gsrc));
}
#define CP_COMMIT() asm volatile("cp.async.commit_group;" ::: "memory")
#define CP_WAIT0()  asm volatile("cp.async.wait_group 0;" ::: "memory")

__device__ __forceinline__ void quad_stats(float s, float s2, int tg,
                                           double* gsum, double* gsq) {
    s  += __shfl_xor_sync(0xffffffffu, s, 1);
    s  += __shfl_xor_sync(0xffffffffu, s, 2);
    s2 += __shfl_xor_sync(0xffffffffu, s2, 1);
    s2 += __shfl_xor_sync(0xffffffffu, s2, 2);
    if (tg == 0) { atomicAdd(gsum, (double)s); atomicAdd(gsq, (double)s2); }
}

// ---------------- utility ----------------
__global__ void zero_stats_kernel() {
    int t = threadIdx.x;
    if (t < COUT) { d_sum0[t] = 0.0; d_sq0[t] = 0.0; d_sum3[t] = 0.0; d_sq3[t] = 0.0; }
    d_sum1[t] = 0.0; d_sq1[t] = 0.0; d_sum2[t] = 0.0; d_sq2[t] = 0.0;
}

__global__ void finalize_kernel(int stage, const float* __restrict__ gamma,
                                const float* __restrict__ beta, double invN) {
    int t = threadIdx.x;
    const double *sum, *sq; float *a, *bsh; int C;
    if (stage == 0)      { sum = d_sum0; sq = d_sq0; a = d_a0; bsh = d_b0; C = COUT; }
    else if (stage == 1) { sum = d_sum1; sq = d_sq1; a = d_a1; bsh = d_b1; C = C2; }
    else if (stage == 2) { sum = d_sum2; sq = d_sq2; a = d_a2; bsh = d_b2; C = C2; }
    else                 { sum = d_sum3; sq = d_sq3; a = d_a3; bsh = d_b3; C = COUT; }
    if (t < C) {
        double mean = sum[t] * invN;
        double var  = sq[t] * invN - mean * mean;
        float v = fmaxf((float)var, 0.0f);
        float av = gamma[t] * rsqrtf(v + EPSV);
        a[t] = av;
        bsh[t] = beta[t] - av * (float)mean;
    }
}

// ---------------- weight converts ----------------
__global__ __launch_bounds__(256) void w2cvt_kernel(const float* __restrict__ w2) {
    int i4 = blockIdx.x * 256 + threadIdx.x;
    int ic0 = (i4 & 15) * 4;
    int oc  = (i4 >> 4) & 255;
    int tc  = i4 >> 12;
    int tap = tc >> 2, chunk = tc & 3;
    #pragma unroll
    for (int e = 0; e < 4; e++) {
        int ic = ic0 + e;
        float v = w2[(size_t)oc * 2304 + (chunk * 64 + ic) * 9 + tap];
        w216[(size_t)tc * 16384 + oc * 64 + ic] = __float2half(v);
    }
}

__global__ __launch_bounds__(256) void w13cvt_kernel(const float* __restrict__ w1,
                                                     const float* __restrict__ w3,
                                                     const float* __restrict__ wc) {
    int i = blockIdx.x * 256 + threadIdx.x;   // 0..16383
    {
        #pragma unroll
        for (int e = 0; e < 2; e++) {
            int idx = i * 2 + e;
            int ic = idx & 63, oc = (idx >> 6) & 255, ch = idx >> 14;
            float v = w1[(size_t)oc * 128 + ch * 64 + ic];
            __nv_bfloat16 h = __float2bfloat16(v);
            w1h[idx] = h;
            w1l[idx] = __float2bfloat16(v - __bfloat162float(h));
        }
    }
    {
        #pragma unroll
        for (int e = 0; e < 2; e++) {
            int idx = i * 2 + e;
            int ic = idx & 63, oc = (idx >> 6) & 127, ch = idx >> 13;
            float v = w3[(size_t)oc * 256 + ch * 64 + ic];
            __nv_bfloat16 h = __float2bfloat16(v);
            w3h[idx] = h;
            w3l[idx] = __float2bfloat16(v - __bfloat162float(h));
        }
    }
    if (i < 8192) {
        float v = wc[i];
        __nv_bfloat16 h = __float2bfloat16(v);
        wch[i] = h;
        wcl[i] = __float2bfloat16(v - __bfloat162float(h));
    }
}

// ---------------- convc: 1x1 64->128 + relu via HMMA (R8 form), fused stats ----------------
#define XCSTR  144
#define XCPART 18432
#define WCOFF  36864
#define WCPART 18432
#define SMEM_CCM (WCOFF + 2 * WCPART)
__global__ __launch_bounds__(256, 2) void convcm_kernel(const float* __restrict__ x,
                                                        const float* __restrict__ bc,
                                                        float* __restrict__ out) {
    extern __shared__ float smf[];
    char* smem = (char*)smf;
    int t = threadIdx.x, w = t >> 5, lane = t & 31;
    int g = lane >> 2, tg = lane & 3;
    int b  = blockIdx.x >> 9;
    int p0 = (blockIdx.x & 511) << 7;
    int ocb = (w & 1) * 64;
    int pxb = (w >> 1) * 32;

    {
        int icp = t & 31, pxg = t >> 5;
        const float* s0 = x + (((size_t)(b * CIN + icp * 2)) << 16) + p0 + pxg * 16;
        const float* s1 = s0 + HW;
        char* xb = smem + icp * 4;
        #pragma unroll
        for (int q = 0; q < 4; q++) {
            float4 u0 = ((const float4*)s0)[q];
            float4 u1 = ((const float4*)s1)[q];
            float v0[4] = {u0.x, u0.y, u0.z, u0.w};
            float v1[4] = {u1.x, u1.y, u1.z, u1.w};
            #pragma unroll
            for (int e = 0; e < 4; e++) {
                int px = pxg * 16 + q * 4 + e;
                __nv_bfloat16 h0 = __float2bfloat16(v0[e]);
                __nv_bfloat16 h1 = __float2bfloat16(v1[e]);
                __nv_bfloat16 l0 = __float2bfloat16(v0[e] - __bfloat162float(h0));
                __nv_bfloat16 l1 = __float2bfloat16(v1[e] - __bfloat162float(h1));
                *(unsigned*)(xb + px * XCSTR) =
                    PKU(__bfloat16_as_ushort(h0), __bfloat16_as_ushort(h1));
                *(unsigned*)(xb + XCPART + px * XCSTR) =
                    PKU(__bfloat16_as_ushort(l0), __bfloat16_as_ushort(l1));
            }
        }
    }
    {
        int part = t >> 7, oc = t & 127;
        const __nv_bfloat16* ws = (part ? wcl : wch) + oc * 64;
        const uint4* s = (const uint4*)ws;
        uint4* d = (uint4*)(smem + WCOFF + part * WCPART + oc * XCSTR);
        #pragma unroll
        for (int q = 0; q < 8; q++) d[q] = s[q];
    }
    __syncthreads();

    float acc[4][4][4];
    #pragma unroll
    for (int mt = 0; mt < 4; mt++)
        #pragma unroll
        for (int nt = 0; nt < 4; nt++)
            #pragma unroll
            for (int e = 0; e < 4; e++) acc[mt][nt][e] = 0.0f;

    #pragma unroll 1
    for (int pass = 0; pass < 3; pass++) {
        const char* A  = smem + WCOFF + ((pass == 1) ? WCPART : 0);
        const char* Bp = smem + ((pass == 2) ? XCPART : 0);
        #pragma unroll
        for (int k4 = 0; k4 < 4; k4++) {
            int kb = (k4 * 16 + 2 * tg) * 2;
            unsigned af[4][4];
            #pragma unroll
            for (int mt = 0; mt < 4; mt++) {
                const char* ar = A + (ocb + mt * 16 + g) * XCSTR + kb;
                af[mt][0] = *(const unsigned*)ar;
                af[mt][1] = *(const unsigned*)(ar + 8 * XCSTR);
                af[mt][2] = *(const unsigned*)(ar + 16);
                af[mt][3] = *(const unsigned*)(ar + 8 * XCSTR + 16);
            }
            #pragma unroll
            for (int nt = 0; nt < 4; nt++) {
                const char* br = Bp + (pxb + nt * 8 + g) * XCSTR + kb;
                unsigned b0 = *(const unsigned*)br;
                unsigned b1v = *(const unsigned*)(br + 16);
                #pragma unroll
                for (int mt = 0; mt < 4; mt++)
                    mma16816(acc[mt][nt], af[mt], b0, b1v);
            }
        }
    }

    float* dstb = out + (((size_t)(b * COUT)) << 16) + p0;
    #pragma unroll
    for (int mt = 0; mt < 4; mt++) {
        int oc_a = ocb + mt * 16 + g;
        int oc_b = oc_a + 8;
        float ba = bc[oc_a], bbv = bc[oc_b];
        float* da = dstb + (((size_t)oc_a) << 16) + pxb;
        float* db = dstb + (((size_t)oc_b) << 16) + pxb;
        float sa = 0.f, qa = 0.f, sb = 0.f, qb = 0.f;
        #pragma unroll
        for (int nt = 0; nt < 4; nt++) {
            int n0 = nt * 8 + tg * 2;
            float2 e0, e1;
            e0.x = fmaxf(acc[mt][nt][0] + ba, 0.f);
            e0.y = fmaxf(acc[mt][nt][1] + ba, 0.f);
            e1.x = fmaxf(acc[mt][nt][2] + bbv, 0.f);
            e1.y = fmaxf(acc[mt][nt][3] + bbv, 0.f);
            sa += e0.x + e0.y; qa += e0.x * e0.x + e0.y * e0.y;
            sb += e1.x + e1.y; qb += e1.x * e1.x + e1.y * e1.y;
            *(float2*)(da + n0) = e0;
            *(float2*)(db + n0) = e1;
        }
        quad_stats(sa, qa, tg, &d_sum0[oc_a], &d_sq0[oc_a]);
        quad_stats(sb, qb, tg, &d_sum0[oc_b], &d_sq0[oc_b]);
    }
}

__global__ __launch_bounds__(256) void bnapply_kernel(float* __restrict__ y) {
    int nth = gridDim.x * blockDim.x;
    int total = (B_ * COUT * HW) / 4;
    for (int i = blockIdx.x * blockDim.x + threadIdx.x; i < total; i += nth) {
        int c = (i >> 14) & 127;
        float4 v = reinterpret_cast<float4*>(y)[i];
        float a = d_a0[c], bb = d_b0[c];
        v.x = a * v.x + bb; v.y = a * v.y + bb;
        v.z = a * v.z + bb; v.w = a * v.w + bb;
        reinterpret_cast<float4*>(y)[i] = v;
    }
}

// ---------------- conv1: gather + 1x1 128->256 via HMMA, 2 blocks/CTA, cp.async W ----------------
#define X1STR  144
#define X1PART 9216
#define X1BLK  18432
#define W1OFF  36864
#define W1PART 36864
#define SMEM_C1M (W1OFF + 2 * W1PART)
__global__ __launch_bounds__(256, 1) void conv1m_kernel(const float* __restrict__ xbn,
                                                        const int* __restrict__ abi,
                                                        const float* __restrict__ b1) {
    extern __shared__ float smf[];
    char* smem = (char*)smf;
    uint32_t sbase = (uint32_t)__cvta_generic_to_shared(smem);
    int t = threadIdx.x, w = t >> 5, lane = t & 31;
    int g = lane >> 2, tg = lane & 3;
    int blk0 = blockIdx.x * 2;
    int mblk = w >> 2;
    int ocb  = (w & 3) * 64;

    float acc[4][8][4];
    #pragma unroll
    for (int mt = 0; mt < 4; mt++)
        #pragma unroll
        for (int nt = 0; nt < 8; nt++)
            #pragma unroll
            for (int e = 0; e < 4; e++) acc[mt][nt][e] = 0.0f;

    int brow = t >> 1, bsub = t & 1;
    int xblk = brow >> 6, xic = brow & 63;
    int n_  = abi[(blk0 + xblk) * 3 + 0];
    int bi_ = abi[(blk0 + xblk) * 3 + 1];
    int bj_ = abi[(blk0 + xblk) * 3 + 2];
    const float* gsrc0 = xbn + (((size_t)(n_ * COUT)) << 16) + bi_ * 2048 + bj_ * 8;

    for (int chunk = 0; chunk < 2; chunk++) {
        __syncthreads();
        {
            #pragma unroll
            for (int j = 0; j < 16; j++) {
                int idx = t + j * 256;
                int row = idx >> 3, q = idx & 7;
                int part = row >> 8, oc = row & 255;
                const __nv_bfloat16* gs = (part ? w1l : w1h) + (size_t)chunk * 16384 + oc * 64 + q * 8;
                uint32_t sd = sbase + W1OFF + part * W1PART + oc * X1STR + q * 16;
                cp_async16(sd, gs);
            }
            CP_COMMIT();
        }
        {
            int icg = chunk * 64 + xic;
            const float* src = gsrc0 + (((size_t)icg) << 16) + bsub * 4 * 256;
            char* xb = smem + xblk * X1BLK + xic * 2;
            #pragma unroll
            for (int r4 = 0; r4 < 4; r4++) {
                float4 u  = *reinterpret_cast<const float4*>(src + r4 * 256);
                float4 v2 = *reinterpret_cast<const float4*>(src + r4 * 256 + 4);
                float vals[8] = {u.x, u.y, u.z, u.w, v2.x, v2.y, v2.z, v2.w};
                int px0 = bsub * 32 + r4 * 8;
                #pragma unroll
                for (int e = 0; e < 8; e++) {
                    float xv = vals[e];
                    __nv_bfloat16 h = __float2bfloat16(xv);
                    __nv_bfloat16 l = __float2bfloat16(xv - __bfloat162float(h));
                    *(__nv_bfloat16*)(xb + (px0 + e) * X1STR) = h;
                    *(__nv_bfloat16*)(xb + X1PART + (px0 + e) * X1STR) = l;
                }
            }
        }
        CP_WAIT0();
        __syncthreads();

        #pragma unroll 1
        for (int pass = 0; pass < 3; pass++) {
            const char* A  = smem + W1OFF + ((pass == 1) ? W1PART : 0);
            const char* Bp = smem + mblk * X1BLK + ((pass == 2) ? X1PART : 0);
            #pragma unroll
            for (int k4 = 0; k4 < 4; k4++) {
                int kb = (k4 * 16 + 2 * tg) * 2;
                unsigned af[4][4];
                #pragma unroll
                for (int mt = 0; mt < 4; mt++) {
                    const char* ar = A + (ocb + mt * 16 + g) * X1STR + kb;
                    af[mt][0] = *(const unsigned*)ar;
                    af[mt][1] = *(const unsigned*)(ar + 8 * X1STR);
                    af[mt][2] = *(const unsigned*)(ar + 16);
                    af[mt][3] = *(const unsigned*)(ar + 8 * X1STR + 16);
                }
                #pragma unroll
                for (int nt = 0; nt < 8; nt++) {
                    const char* br = Bp + (nt * 8 + g) * X1STR + kb;
                    unsigned b0 = *(const unsigned*)br;
                    unsigned b1v = *(const unsigned*)(br + 16);
                    #pragma unroll
                    for (int mt = 0; mt < 4; mt++)
                        mma16816(acc[mt][nt], af[mt], b0, b1v);
                }
            }
        }
    }

    #pragma unroll
    for (int mt = 0; mt < 4; mt++) {
        int oc_a = ocb + mt * 16 + g;
        int oc_b = oc_a + 8;
        float ba = b1[oc_a], bbv = b1[oc_b];
        float* da = g1buf + ((size_t)(blk0 + mblk) * C2 + oc_a) * 64;
        float* db = g1buf + ((size_t)(blk0 + mblk) * C2 + oc_b) * 64;
        float sa = 0.f, qa = 0.f, sb = 0.f, qb = 0.f;
        #pragma unroll
        for (int nt = 0; nt < 8; nt++) {
            int n0 = nt * 8 + tg * 2;
            float2 e0, e1;
            e0.x = fmaxf(acc[mt][nt][0] + ba, 0.f);
            e0.y = fmaxf(acc[mt][nt][1] + ba, 0.f);
            e1.x = fmaxf(acc[mt][nt][2] + bbv, 0.f);
            e1.y = fmaxf(acc[mt][nt][3] + bbv, 0.f);
            sa += e0.x + e0.y; qa += e0.x * e0.x + e0.y * e0.y;
            sb += e1.x + e1.y; qb += e1.x * e1.x + e1.y * e1.y;
            *(float2*)(da + n0) = e0;
            *(float2*)(db + n0) = e1;
        }
        quad_stats(sa, qa, tg, &d_sum1[oc_a], &d_sq1[oc_a]);
        quad_stats(sb, qb, tg, &d_sum1[oc_b], &d_sq1[oc_b]);
    }
}

// ---------------- conv2: 3x3 via fp16 HMMA 2-pass, padded-2D X, cp.async dbuf W ----------------
#define X2ARR  14400
#define X2BLK  28800
#define W2OFF  57600
#define W2BUF  36864
#define SMEM_C2M (W2OFF + 2 * W2BUF)
__global__ __launch_bounds__(256, 1) void conv2m_kernel(const float* __restrict__ b2) {
    extern __shared__ float smf[];
    char* smem = (char*)smf;
    uint32_t sbase = (uint32_t)__cvta_generic_to_shared(smem);
    int t = threadIdx.x, w = t >> 5, lane = t & 31;
    int g = lane >> 2, tg = lane & 3;
    int blk0 = blockIdx.x * 2;
    int mblk = w >> 2;
    int ocb  = (w & 3) * 64;

    float acc[4][8][4];
    #pragma unroll
    for (int mt = 0; mt < 4; mt++)
        #pragma unroll
        for (int nt = 0; nt < 8; nt++)
            #pragma unroll
            for (int e = 0; e < 4; e++) acc[mt][nt][e] = 0.0f;

    // zero X once (halo stays zero)
    for (int i = t; i < W2OFF / 16; i += 256) ((uint4*)smem)[i] = make_uint4(0, 0, 0, 0);

    int xblk = t >> 7;
    int icp  = (t >> 2) & 31;
    int pxg  = t & 3;

    for (int chunk = 0; chunk < 4; chunk++) {
        __syncthreads();
        // prefetch W(tap0, chunk) -> buf0 (fp16, 8 ops/thread)
        {
            int tc = chunk;
            #pragma unroll
            for (int j = 0; j < 8; j++) {
                int idx = t + j * 256;
                int row = idx >> 3, q = idx & 7;
                const __half* gs = w216 + (size_t)tc * 16384 + row * 64 + q * 8;
                uint32_t sd = sbase + W2OFF + row * X1STR + q * 16;
                cp_async16(sd, gs);
            }
            CP_COMMIT();
        }
        // X build: fp16 hi/lo planes
        {
            int ic0 = chunk * 64 + icp * 2;
            const float* s0 = g1buf + ((size_t)(blk0 + xblk) * C2 + ic0) * 64 + pxg * 16;
            const float* s1 = s0 + 64;
            float a0 = d_a1[ic0],     c0 = d_b1[ic0];
            float a1 = d_a1[ic0 + 1], c1 = d_b1[ic0 + 1];
            char* xb = smem + xblk * X2BLK + icp * 4;
            #pragma unroll
            for (int q = 0; q < 4; q++) {
                float4 u0 = ((const float4*)s0)[q];
                float4 u1 = ((const float4*)s1)[q];
                float v0[4] = {u0.x, u0.y, u0.z, u0.w};
                float v1[4] = {u1.x, u1.y, u1.z, u1.w};
                #pragma unroll
                for (int e = 0; e < 4; e++) {
                    int p = pxg * 16 + q * 4 + e;
                    int row = ((p >> 3) + 1) * 10 + (p & 7) + 1;
                    float x0 = a0 * v0[e] + c0;
                    float x1 = a1 * v1[e] + c1;
                    __half h0 = __float2half(x0);
                    __half h1 = __float2half(x1);
                    __half l0 = __float2half(x0 - __half2float(h0));
                    __half l1 = __float2half(x1 - __half2float(h1));
                    *(unsigned*)(xb + row * X1STR) =
                        PKU(__half_as_ushort(h0), __half_as_ushort(h1));
                    *(unsigned*)(xb + X2ARR + row * X1STR) =
                        PKU(__half_as_ushort(l0), __half_as_ushort(l1));
                }
            }
        }

        for (int tap = 0; tap < 9; tap++) {
            CP_WAIT0();
            __syncthreads();
            int buf = tap & 1;
            if (tap < 8) {
                int tc = (tap + 1) * 4 + chunk;
                int ob = buf ^ 1;
                #pragma unroll
                for (int j = 0; j < 8; j++) {
                    int idx = t + j * 256;
                    int row = idx >> 3, q = idx & 7;
                    const __half* gs = w216 + (size_t)tc * 16384 + row * 64 + q * 8;
                    uint32_t sd = sbase + W2OFF + ob * W2BUF + row * X1STR + q * 16;
                    cp_async16(sd, gs);
                }
                CP_COMMIT();
            }

            int dr = tap / 3, dc = tap % 3;
            int rowc = dr * 10 + dc + g;
            const char* A  = smem + W2OFF + buf * W2BUF;
            const char* Bh = smem + mblk * X2BLK;
            #pragma unroll
            for (int k4 = 0; k4 < 4; k4++) {
                int kb = (k4 * 16 + 2 * tg) * 2;
                unsigned af[4][4];
                #pragma unroll
                for (int mt = 0; mt < 4; mt++) {
                    const char* ar = A + (ocb + mt * 16 + g) * X1STR + kb;
                    af[mt][0] = *(const unsigned*)ar;
                    af[mt][1] = *(const unsigned*)(ar + 8 * X1STR);
                    af[mt][2] = *(const unsigned*)(ar + 16);
                    af[mt][3] = *(const unsigned*)(ar + 8 * X1STR + 16);
                }
                #pragma unroll
                for (int nt = 0; nt < 8; nt++) {
                    const char* br = Bh + (rowc + nt * 10) * X1STR + kb;
                    unsigned b0h = *(const unsigned*)br;
                    unsigned b1h = *(const unsigned*)(br + 16);
                    unsigned b0l = *(const unsigned*)(br + X2ARR);
                    unsigned b1l = *(const unsigned*)(br + X2ARR + 16);
                    #pragma unroll
                    for (int mt = 0; mt < 4; mt++) {
                        mma16816h(acc[mt][nt], af[mt], b0h, b1h);
                        mma16816h(acc[mt][nt], af[mt], b0l, b1l);
                    }
                }
            }
        }
    }

    #pragma unroll
    for (int mt = 0; mt < 4; mt++) {
        int oc_a = ocb + mt * 16 + g;
        int oc_b = oc_a + 8;
        float ba = b2[oc_a], bbv = b2[oc_b];
        float* da = g2buf + ((size_t)(blk0 + mblk) * C2 + oc_a) * 64;
        float* db = g2buf + ((size_t)(blk0 + mblk) * C2 + oc_b) * 64;
        float sa = 0.f, qa = 0.f, sb = 0.f, qb = 0.f;
        #pragma unroll
        for (int nt = 0; nt < 8; nt++) {
            int n0 = nt * 8 + tg * 2;
            float2 e0, e1;
            e0.x = fmaxf(acc[mt][nt][0] + ba, 0.f);
            e0.y = fmaxf(acc[mt][nt][1] + ba, 0.f);
            e1.x = fmaxf(acc[mt][nt][2] + bbv, 0.f);
            e1.y = fmaxf(acc[mt][nt][3] + bbv, 0.f);
            sa += e0.x + e0.y; qa += e0.x * e0.x + e0.y * e0.y;
            sb += e1.x + e1.y; qb += e1.x * e1.x + e1.y * e1.y;
            *(float2*)(da + n0) = e0;
            *(float2*)(db + n0) = e1;
        }
        quad_stats(sa, qa, tg, &d_sum2[oc_a], &d_sq2[oc_a]);
        quad_stats(sb, qb, tg, &d_sum2[oc_b], &d_sq2[oc_b]);
    }
}

// ---------------- conv3: 1x1 256->128 via HMMA, 4 blocks/CTA, cp.async W ----------------
#define X3BLK  18432
#define W3OFF  73728
#define W3PART 18432
#define SMEM_C3M (W3OFF + 2 * W3PART)
__global__ __launch_bounds__(256, 1) void conv3m_kernel(const float* __restrict__ b3) {
    extern __shared__ float smf[];
    char* smem = (char*)smf;
    uint32_t sbase = (uint32_t)__cvta_generic_to_shared(smem);
    int t = threadIdx.x, w = t >> 5, lane = t & 31;
    int g = lane >> 2, tg = lane & 3;
    int blk0 = blockIdx.x * 4;
    int mblk = w >> 1;
    int ocb  = (w & 1) * 64;

    float acc[4][8][4];
    #pragma unroll
    for (int mt = 0; mt < 4; mt++)
        #pragma unroll
        for (int nt = 0; nt < 8; nt++)
            #pragma unroll
            for (int e = 0; e < 4; e++) acc[mt][nt][e] = 0.0f;

    int xblk = t >> 6, xic = t & 63;

    for (int chunk = 0; chunk < 4; chunk++) {
        __syncthreads();
        {
            #pragma unroll
            for (int j = 0; j < 8; j++) {
                int idx = t + j * 256;
                int row = idx >> 3, q = idx & 7;
                int part = row >> 7, oc = row & 127;
                const __nv_bfloat16* gs = (part ? w3l : w3h) + (size_t)chunk * 8192 + oc * 64 + q * 8;
                uint32_t sd = sbase + W3OFF + part * W3PART + oc * X1STR + q * 16;
                cp_async16(sd, gs);
            }
            CP_COMMIT();
        }
        {
            int icg = chunk * 64 + xic;
            const float* src = g2buf + ((size_t)(blk0 + xblk) * C2 + icg) * 64;
            float a = d_a2[icg], bb = d_b2[icg];
            char* xb = smem + xblk * X3BLK + xic * 2;
            #pragma unroll
            for (int j = 0; j < 16; j++) {
                float4 v4 = ((const float4*)src)[j];
                float vals[4] = {v4.x, v4.y, v4.z, v4.w};
                #pragma unroll
                for (int e = 0; e < 4; e++) {
                    int px = j * 4 + e;
                    float xv = a * vals[e] + bb;
                    __nv_bfloat16 h = __float2bfloat16(xv);
                    __nv_bfloat16 l = __float2bfloat16(xv - __bfloat162float(h));
                    *(__nv_bfloat16*)(xb + px * X1STR) = h;
                    *(__nv_bfloat16*)(xb + X1PART + px * X1STR) = l;
                }
            }
        }
        CP_WAIT0();
        __syncthreads();

        #pragma unroll 1
        for (int pass = 0; pass < 3; pass++) {
            const char* A  = smem + W3OFF + ((pass == 1) ? W3PART : 0);
            const char* Bp = smem + mblk * X3BLK + ((pass == 2) ? X1PART : 0);
            #pragma unroll
            for (int k4 = 0; k4 < 4; k4++) {
                int kb = (k4 * 16 + 2 * tg) * 2;
                unsigned af[4][4];
                #pragma unroll
                for (int mt = 0; mt < 4; mt++) {
                    const char* ar = A + (ocb + mt * 16 + g) * X1STR + kb;
                    af[mt][0] = *(const unsigned*)ar;
                    af[mt][1] = *(const unsigned*)(ar + 8 * X1STR);
                    af[mt][2] = *(const unsigned*)(ar + 16);
                    af[mt][3] = *(const unsigned*)(ar + 8 * X1STR + 16);
                }
                #pragma unroll
                for (int nt = 0; nt < 8; nt++) {
                    const char* br = Bp + (nt * 8 + g) * X1STR + kb;
                    unsigned b0 = *(const unsigned*)br;
                    unsigned b1v = *(const unsigned*)(br + 16);
                    #pragma unroll
                    for (int mt = 0; mt < 4; mt++)
                        mma16816(acc[mt][nt], af[mt], b0, b1v);
                }
            }
        }
    }

    #pragma unroll
    for (int mt = 0; mt < 4; mt++) {
        int oc_a = ocb + mt * 16 + g;
        int oc_b = oc_a + 8;
        float ba = b3[oc_a], bbv = b3[oc_b];
        float* da = g3buf + ((size_t)(blk0 + mblk) * COUT + oc_a) * 64;
        float* db = g3buf + ((size_t)(blk0 + mblk) * COUT + oc_b) * 64;
        float sa = 0.f, qa = 0.f, sb = 0.f, qb = 0.f;
        #pragma unroll
        for (int nt = 0; nt < 8; nt++) {
            int n0 = nt * 8 + tg * 2;
            float2 e0, e1;
            e0.x = fmaxf(acc[mt][nt][0] + ba, 0.f);
            e0.y = fmaxf(acc[mt][nt][1] + ba, 0.f);
            e1.x = fmaxf(acc[mt][nt][2] + bbv, 0.f);
            e1.y = fmaxf(acc[mt][nt][3] + bbv, 0.f);
            sa += e0.x + e0.y; qa += e0.x * e0.x + e0.y * e0.y;
            sb += e1.x + e1.y; qb += e1.x * e1.x + e1.y * e1.y;
            *(float2*)(da + n0) = e0;
            *(float2*)(db + n0) = e1;
        }
        quad_stats(sa, qa, tg, &d_sum3[oc_a], &d_sq3[oc_a]);
        quad_stats(sb, qb, tg, &d_sum3[oc_b], &d_sq3[oc_b]);
    }
}

// ---------------- scatter: BN3(g3) -> image ----------------
__global__ __launch_bounds__(256) void scatter_kernel(const int* __restrict__ abi,
                                                      float* __restrict__ out) {
    int blk = blockIdx.x;
    int n  = abi[blk * 3 + 0];
    int bi = abi[blk * 3 + 1];
    int bj = abi[blk * 3 + 2];
    const float* src = g3buf + (size_t)blk * COUT * 64;
    float* dst = out + (((size_t)(n * COUT)) << 16) + bi * 8 * 256 + bj * 8;
    for (int i = threadIdx.x; i < 2048; i += 256) {
        int c = i >> 4, q = i & 15;
        int r = q >> 1, c4 = (q & 1) * 4;
        float4 v = *reinterpret_cast<const float4*>(src + c * 64 + q * 4);
        float a = d_a3[c], bb = d_b3[c];
        v.x = a * v.x + bb; v.y = a * v.y + bb;
        v.z = a * v.z + bb; v.w = a * v.w + bb;
        *reinterpret_cast<float4*>(dst + (((size_t)c) << 16) + r * 256 + c4) = v;
    }
}

// ---------------- launch ----------------
extern "C" void kernel_launch(void* const* d_in, const int* in_sizes, int n_in,
                              void* d_out, int out_size) {
    const float* x    = (const float*)d_in[0];
    const int*   abi  = (const int*)  d_in[1];
    const float* w_c  = (const float*)d_in[2];
    const float* b_c  = (const float*)d_in[3];
    const float* gm_c = (const float*)d_in[4];
    const float* be_c = (const float*)d_in[5];
    const float* w1   = (const float*)d_in[6];
    const float* b1   = (const float*)d_in[7];
    const float* gm1  = (const float*)d_in[8];
    const float* be1  = (const float*)d_in[9];
    const float* w2   = (const float*)d_in[10];
    const float* b2   = (const float*)d_in[11];
    const float* gm2  = (const float*)d_in[12];
    const float* be2  = (const float*)d_in[13];
    const float* w3   = (const float*)d_in[14];
    const float* b3   = (const float*)d_in[15];
    const float* gm3  = (const float*)d_in[16];
    const float* be3  = (const float*)d_in[17];
    float* out = (float*)d_out;

    cudaFuncSetAttribute(convcm_kernel, cudaFuncAttributeMaxDynamicSharedMemorySize, SMEM_CCM);
    cudaFuncSetAttribute(conv1m_kernel, cudaFuncAttributeMaxDynamicSharedMemorySize, SMEM_C1M);
    cudaFuncSetAttribute(conv2m_kernel, cudaFuncAttributeMaxDynamicSharedMemorySize, SMEM_C2M);
    cudaFuncSetAttribute(conv3m_kernel, cudaFuncAttributeMaxDynamicSharedMemorySize, SMEM_C3M);

    zero_stats_kernel<<<1, 256>>>();
    w2cvt_kernel<<<576, 256>>>(w2);
    w13cvt_kernel<<<64, 256>>>(w1, w3, w_c);

    convcm_kernel<<<4096, 256, SMEM_CCM>>>(x, b_c, out);
    finalize_kernel<<<1, 256>>>(0, gm_c, be_c, 1.0 / 524288.0);
    bnapply_kernel<<<16384, 256>>>(out);

    conv1m_kernel<<<2048, 256, SMEM_C1M>>>(out, abi, b1);
    finalize_kernel<<<1, 256>>>(1, gm1, be1, 1.0 / 262144.0);

    conv2m_kernel<<<2048, 256, SMEM_C2M>>>(b2);
    finalize_kernel<<<1, 256>>>(2, gm2, be2, 1.0 / 262144.0);

    conv3m_kernel<<<1024, 256, SMEM_C3M>>>(b3);
    finalize_kernel<<<1, 256>>>(3, gm3, be3, 1.0 / 262144.0);

    scatter_kernel<<<4096, 256>>>(abi, out);
}

// round 12
// speedup vs baseline: 3.9207x; 1.0300x over previous
#include <cuda_runtime.h>
#include <cuda_bf16.h>
#include <cuda_fp16.h>
#include <math.h>
#include <stdint.h>

#define B_    8
#define CIN   64
#define COUT  128
#define C2    256
#define HW    65536
#define NBLK  4096
#define EPSV  1e-5f

// ---------------- scratch ----------------
__device__ float g1buf[(size_t)NBLK * C2 * 64];
__device__ float g2buf[(size_t)NBLK * C2 * 64];
__device__ float g3buf[(size_t)NBLK * COUT * 64];

// fp16 weights (single plane each)
__device__ __half w216[36 * 16384];  // [tap*4+chunk][oc 256][ic 64]
__device__ __half w116[2 * 16384];   // [chunk2][oc 256][ic 64]
__device__ __half w316[4 * 8192];    // [chunk4][oc 128][ic 64]
__device__ __half wc16[8192];        // [oc 128][ic 64]

__device__ double d_sum0[COUT], d_sq0[COUT];
__device__ double d_sum1[C2],   d_sq1[C2];
__device__ double d_sum2[C2],   d_sq2[C2];
__device__ double d_sum3[COUT], d_sq3[COUT];
__device__ float  d_a0[COUT], d_b0[COUT];
__device__ float  d_a1[C2],   d_b1[C2];
__device__ float  d_a2[C2],   d_b2[C2];
__device__ float  d_a3[COUT], d_b3[COUT];

#define PKU(x, y) ((unsigned)(x) | ((unsigned)(y) << 16))

// ---------------- MMA helper (fp16) ----------------
__device__ __forceinline__ void mma16816h(float* d, const unsigned* a, unsigned b0, unsigned b1) {
    asm volatile(
        "mma.sync.aligned.m16n8k16.row.col.f32.f16.f16.f32 "
        "{%0,%1,%2,%3}, {%4,%5,%6,%7}, {%8,%9}, {%0,%1,%2,%3};"
        : "+f"(d[0]), "+f"(d[1]), "+f"(d[2]), "+f"(d[3])
        : "r"(a[0]), "r"(a[1]), "r"(a[2]), "r"(a[3]), "r"(b0), "r"(b1));
}

__device__ __forceinline__ void cp_async16(uint32_t sdst, const void* gsrc) {
    asm volatile("cp.async.cg.shared.global [%0], [%1], 16;" :: "r"(sdst), "l"(gsrc));
}
#define CP_COMMIT() asm volatile("cp.async.commit_group;" ::: "memory")
#define CP_WAIT0()  asm volatile("cp.async.wait_group 0;" ::: "memory")

__device__ __forceinline__ void quad_stats(float s, float s2, int tg,
                                           double* gsum, double* gsq) {
    s  += __shfl_xor_sync(0xffffffffu, s, 1);
    s  += __shfl_xor_sync(0xffffffffu, s, 2);
    s2 += __shfl_xor_sync(0xffffffffu, s2, 1);
    s2 += __shfl_xor_sync(0xffffffffu, s2, 2);
    if (tg == 0) { atomicAdd(gsum, (double)s); atomicAdd(gsq, (double)s2); }
}

// ---------------- utility ----------------
__global__ void zero_stats_kernel() {
    int t = threadIdx.x;
    if (t < COUT) { d_sum0[t] = 0.0; d_sq0[t] = 0.0; d_sum3[t] = 0.0; d_sq3[t] = 0.0; }
    d_sum1[t] = 0.0; d_sq1[t] = 0.0; d_sum2[t] = 0.0; d_sq2[t] = 0.0;
}

__global__ void finalize_kernel(int stage, const float* __restrict__ gamma,
                                const float* __restrict__ beta, double invN) {
    int t = threadIdx.x;
    const double *sum, *sq; float *a, *bsh; int C;
    if (stage == 0)      { sum = d_sum0; sq = d_sq0; a = d_a0; bsh = d_b0; C = COUT; }
    else if (stage == 1) { sum = d_sum1; sq = d_sq1; a = d_a1; bsh = d_b1; C = C2; }
    else if (stage == 2) { sum = d_sum2; sq = d_sq2; a = d_a2; bsh = d_b2; C = C2; }
    else                 { sum = d_sum3; sq = d_sq3; a = d_a3; bsh = d_b3; C = COUT; }
    if (t < C) {
        double mean = sum[t] * invN;
        double var  = sq[t] * invN - mean * mean;
        float v = fmaxf((float)var, 0.0f);
        float av = gamma[t] * rsqrtf(v + EPSV);
        a[t] = av;
        bsh[t] = beta[t] - av * (float)mean;
    }
}

// ---------------- weight converts ----------------
__global__ __launch_bounds__(256) void w2cvt_kernel(const float* __restrict__ w2) {
    int i4 = blockIdx.x * 256 + threadIdx.x;
    int ic0 = (i4 & 15) * 4;
    int oc  = (i4 >> 4) & 255;
    int tc  = i4 >> 12;
    int tap = tc >> 2, chunk = tc & 3;
    #pragma unroll
    for (int e = 0; e < 4; e++) {
        int ic = ic0 + e;
        float v = w2[(size_t)oc * 2304 + (chunk * 64 + ic) * 9 + tap];
        w216[(size_t)tc * 16384 + oc * 64 + ic] = __float2half(v);
    }
}

__global__ __launch_bounds__(256) void w13cvt_kernel(const float* __restrict__ w1,
                                                     const float* __restrict__ w3,
                                                     const float* __restrict__ wc) {
    int i = blockIdx.x * 256 + threadIdx.x;   // 0..16383
    {
        #pragma unroll
        for (int e = 0; e < 2; e++) {
            int idx = i * 2 + e;
            int ic = idx & 63, oc = (idx >> 6) & 255, ch = idx >> 14;
            w116[idx] = __float2half(w1[(size_t)oc * 128 + ch * 64 + ic]);
        }
    }
    {
        #pragma unroll
        for (int e = 0; e < 2; e++) {
            int idx = i * 2 + e;
            int ic = idx & 63, oc = (idx >> 6) & 127, ch = idx >> 13;
            w316[idx] = __float2half(w3[(size_t)oc * 256 + ch * 64 + ic]);
        }
    }
    if (i < 8192) wc16[i] = __float2half(wc[i]);
}

// ---------------- convc: 1x1 64->128 + relu via fp16 HMMA 2-pass, fused stats ----------------
#define XCSTR  144
#define XCPART 18432
#define WCOFF  36864
#define SMEM_CCM (WCOFF + 18432)
__global__ __launch_bounds__(256, 2) void convcm_kernel(const float* __restrict__ x,
                                                        const float* __restrict__ bc,
                                                        float* __restrict__ out) {
    extern __shared__ float smf[];
    char* smem = (char*)smf;
    int t = threadIdx.x, w = t >> 5, lane = t & 31;
    int g = lane >> 2, tg = lane & 3;
    int b  = blockIdx.x >> 9;
    int p0 = (blockIdx.x & 511) << 7;
    int ocb = (w & 1) * 64;
    int pxb = (w >> 1) * 32;

    // X build: fp16 hi/lo planes
    {
        int icp = t & 31, pxg = t >> 5;
        const float* s0 = x + (((size_t)(b * CIN + icp * 2)) << 16) + p0 + pxg * 16;
        const float* s1 = s0 + HW;
        char* xb = smem + icp * 4;
        #pragma unroll
        for (int q = 0; q < 4; q++) {
            float4 u0 = ((const float4*)s0)[q];
            float4 u1 = ((const float4*)s1)[q];
            float v0[4] = {u0.x, u0.y, u0.z, u0.w};
            float v1[4] = {u1.x, u1.y, u1.z, u1.w};
            #pragma unroll
            for (int e = 0; e < 4; e++) {
                int px = pxg * 16 + q * 4 + e;
                __half h0 = __float2half(v0[e]);
                __half h1 = __float2half(v1[e]);
                __half l0 = __float2half(v0[e] - __half2float(h0));
                __half l1 = __float2half(v1[e] - __half2float(h1));
                *(unsigned*)(xb + px * XCSTR) =
                    PKU(__half_as_ushort(h0), __half_as_ushort(h1));
                *(unsigned*)(xb + XCPART + px * XCSTR) =
                    PKU(__half_as_ushort(l0), __half_as_ushort(l1));
            }
        }
    }
    // W copy (single plane, 128 rows)
    {
        int oc = t >> 1, qh = (t & 1) * 4;
        const uint4* s = (const uint4*)(wc16 + oc * 64 + qh * 8);
        uint4* d = (uint4*)(smem + WCOFF + oc * XCSTR + qh * 16);
        #pragma unroll
        for (int q = 0; q < 4; q++) d[q] = s[q];
    }
    __syncthreads();

    float acc[4][4][4];
    #pragma unroll
    for (int mt = 0; mt < 4; mt++)
        #pragma unroll
        for (int nt = 0; nt < 4; nt++)
            #pragma unroll
            for (int e = 0; e < 4; e++) acc[mt][nt][e] = 0.0f;

    const char* A  = smem + WCOFF;
    const char* Bh = smem;
    #pragma unroll
    for (int k4 = 0; k4 < 4; k4++) {
        int kb = (k4 * 16 + 2 * tg) * 2;
        unsigned af[4][4];
        #pragma unroll
        for (int mt = 0; mt < 4; mt++) {
            const char* ar = A + (ocb + mt * 16 + g) * XCSTR + kb;
            af[mt][0] = *(const unsigned*)ar;
            af[mt][1] = *(const unsigned*)(ar + 8 * XCSTR);
            af[mt][2] = *(const unsigned*)(ar + 16);
            af[mt][3] = *(const unsigned*)(ar + 8 * XCSTR + 16);
        }
        #pragma unroll
        for (int nt = 0; nt < 4; nt++) {
            const char* br = Bh + (pxb + nt * 8 + g) * XCSTR + kb;
            unsigned b0h = *(const unsigned*)br;
            unsigned b1h = *(const unsigned*)(br + 16);
            unsigned b0l = *(const unsigned*)(br + XCPART);
            unsigned b1l = *(const unsigned*)(br + XCPART + 16);
            #pragma unroll
            for (int mt = 0; mt < 4; mt++) {
                mma16816h(acc[mt][nt], af[mt], b0h, b1h);
                mma16816h(acc[mt][nt], af[mt], b0l, b1l);
            }
        }
    }

    float* dstb = out + (((size_t)(b * COUT)) << 16) + p0;
    #pragma unroll
    for (int mt = 0; mt < 4; mt++) {
        int oc_a = ocb + mt * 16 + g;
        int oc_b = oc_a + 8;
        float ba = bc[oc_a], bbv = bc[oc_b];
        float* da = dstb + (((size_t)oc_a) << 16) + pxb;
        float* db = dstb + (((size_t)oc_b) << 16) + pxb;
        float sa = 0.f, qa = 0.f, sb = 0.f, qb = 0.f;
        #pragma unroll
        for (int nt = 0; nt < 4; nt++) {
            int n0 = nt * 8 + tg * 2;
            float2 e0, e1;
            e0.x = fmaxf(acc[mt][nt][0] + ba, 0.f);
            e0.y = fmaxf(acc[mt][nt][1] + ba, 0.f);
            e1.x = fmaxf(acc[mt][nt][2] + bbv, 0.f);
            e1.y = fmaxf(acc[mt][nt][3] + bbv, 0.f);
            sa += e0.x + e0.y; qa += e0.x * e0.x + e0.y * e0.y;
            sb += e1.x + e1.y; qb += e1.x * e1.x + e1.y * e1.y;
            *(float2*)(da + n0) = e0;
            *(float2*)(db + n0) = e1;
        }
        quad_stats(sa, qa, tg, &d_sum0[oc_a], &d_sq0[oc_a]);
        quad_stats(sb, qb, tg, &d_sum0[oc_b], &d_sq0[oc_b]);
    }
}

__global__ __launch_bounds__(256) void bnapply_kernel(float* __restrict__ y) {
    int nth = gridDim.x * blockDim.x;
    int total = (B_ * COUT * HW) / 4;
    for (int i = blockIdx.x * blockDim.x + threadIdx.x; i < total; i += nth) {
        int c = (i >> 14) & 127;
        float4 v = reinterpret_cast<float4*>(y)[i];
        float a = d_a0[c], bb = d_b0[c];
        v.x = a * v.x + bb; v.y = a * v.y + bb;
        v.z = a * v.z + bb; v.w = a * v.w + bb;
        reinterpret_cast<float4*>(y)[i] = v;
    }
}

// ---------------- conv1: gather + 1x1 128->256 via fp16 HMMA 2-pass, cp.async W ----------------
#define X1STR  144
#define X1PART 9216
#define X1BLK  18432
#define W1OFF  36864
#define SMEM_C1M (W1OFF + 36864)
__global__ __launch_bounds__(256, 1) void conv1m_kernel(const float* __restrict__ xbn,
                                                        const int* __restrict__ abi,
                                                        const float* __restrict__ b1) {
    extern __shared__ float smf[];
    char* smem = (char*)smf;
    uint32_t sbase = (uint32_t)__cvta_generic_to_shared(smem);
    int t = threadIdx.x, w = t >> 5, lane = t & 31;
    int g = lane >> 2, tg = lane & 3;
    int blk0 = blockIdx.x * 2;
    int mblk = w >> 2;
    int ocb  = (w & 3) * 64;

    float acc[4][8][4];
    #pragma unroll
    for (int mt = 0; mt < 4; mt++)
        #pragma unroll
        for (int nt = 0; nt < 8; nt++)
            #pragma unroll
            for (int e = 0; e < 4; e++) acc[mt][nt][e] = 0.0f;

    int brow = t >> 1, bsub = t & 1;
    int xblk = brow >> 6, xic = brow & 63;
    int n_  = abi[(blk0 + xblk) * 3 + 0];
    int bi_ = abi[(blk0 + xblk) * 3 + 1];
    int bj_ = abi[(blk0 + xblk) * 3 + 2];
    const float* gsrc0 = xbn + (((size_t)(n_ * COUT)) << 16) + bi_ * 2048 + bj_ * 8;

    for (int chunk = 0; chunk < 2; chunk++) {
        __syncthreads();
        // W(chunk): single fp16 plane (2048 x 16B), cp.async overlapped with X build
        {
            #pragma unroll
            for (int j = 0; j < 8; j++) {
                int idx = t + j * 256;
                int row = idx >> 3, q = idx & 7;
                const __half* gs = w116 + (size_t)chunk * 16384 + row * 64 + q * 8;
                uint32_t sd = sbase + W1OFF + row * X1STR + q * 16;
                cp_async16(sd, gs);
            }
            CP_COMMIT();
        }
        {
            int icg = chunk * 64 + xic;
            const float* src = gsrc0 + (((size_t)icg) << 16) + bsub * 4 * 256;
            char* xb = smem + xblk * X1BLK + xic * 2;
            #pragma unroll
            for (int r4 = 0; r4 < 4; r4++) {
                float4 u  = *reinterpret_cast<const float4*>(src + r4 * 256);
                float4 v2 = *reinterpret_cast<const float4*>(src + r4 * 256 + 4);
                float vals[8] = {u.x, u.y, u.z, u.w, v2.x, v2.y, v2.z, v2.w};
                int px0 = bsub * 32 + r4 * 8;
                #pragma unroll
                for (int e = 0; e < 8; e++) {
                    float xv = vals[e];
                    __half h = __float2half(xv);
                    __half l = __float2half(xv - __half2float(h));
                    *(__half*)(xb + (px0 + e) * X1STR) = h;
                    *(__half*)(xb + X1PART + (px0 + e) * X1STR) = l;
                }
            }
        }
        CP_WAIT0();
        __syncthreads();

        const char* A  = smem + W1OFF;
        const char* Bh = smem + mblk * X1BLK;
        #pragma unroll
        for (int k4 = 0; k4 < 4; k4++) {
            int kb = (k4 * 16 + 2 * tg) * 2;
            unsigned af[4][4];
            #pragma unroll
            for (int mt = 0; mt < 4; mt++) {
                const char* ar = A + (ocb + mt * 16 + g) * X1STR + kb;
                af[mt][0] = *(const unsigned*)ar;
                af[mt][1] = *(const unsigned*)(ar + 8 * X1STR);
                af[mt][2] = *(const unsigned*)(ar + 16);
                af[mt][3] = *(const unsigned*)(ar + 8 * X1STR + 16);
            }
            #pragma unroll
            for (int nt = 0; nt < 8; nt++) {
                const char* br = Bh + (nt * 8 + g) * X1STR + kb;
                unsigned b0h = *(const unsigned*)br;
                unsigned b1h = *(const unsigned*)(br + 16);
                unsigned b0l = *(const unsigned*)(br + X1PART);
                unsigned b1l = *(const unsigned*)(br + X1PART + 16);
                #pragma unroll
                for (int mt = 0; mt < 4; mt++) {
                    mma16816h(acc[mt][nt], af[mt], b0h, b1h);
                    mma16816h(acc[mt][nt], af[mt], b0l, b1l);
                }
            }
        }
    }

    #pragma unroll
    for (int mt = 0; mt < 4; mt++) {
        int oc_a = ocb + mt * 16 + g;
        int oc_b = oc_a + 8;
        float ba = b1[oc_a], bbv = b1[oc_b];
        float* da = g1buf + ((size_t)(blk0 + mblk) * C2 + oc_a) * 64;
        float* db = g1buf + ((size_t)(blk0 + mblk) * C2 + oc_b) * 64;
        float sa = 0.f, qa = 0.f, sb = 0.f, qb = 0.f;
        #pragma unroll
        for (int nt = 0; nt < 8; nt++) {
            int n0 = nt * 8 + tg * 2;
            float2 e0, e1;
            e0.x = fmaxf(acc[mt][nt][0] + ba, 0.f);
            e0.y = fmaxf(acc[mt][nt][1] + ba, 0.f);
            e1.x = fmaxf(acc[mt][nt][2] + bbv, 0.f);
            e1.y = fmaxf(acc[mt][nt][3] + bbv, 0.f);
            sa += e0.x + e0.y; qa += e0.x * e0.x + e0.y * e0.y;
            sb += e1.x + e1.y; qb += e1.x * e1.x + e1.y * e1.y;
            *(float2*)(da + n0) = e0;
            *(float2*)(db + n0) = e1;
        }
        quad_stats(sa, qa, tg, &d_sum1[oc_a], &d_sq1[oc_a]);
        quad_stats(sb, qb, tg, &d_sum1[oc_b], &d_sq1[oc_b]);
    }
}

// ---------------- conv2: 3x3 via fp16 HMMA 2-pass, padded-2D X, cp.async dbuf W ----------------
#define X2ARR  14400
#define X2BLK  28800
#define W2OFF  57600
#define W2BUF  36864
#define SMEM_C2M (W2OFF + 2 * W2BUF)
__global__ __launch_bounds__(256, 1) void conv2m_kernel(const float* __restrict__ b2) {
    extern __shared__ float smf[];
    char* smem = (char*)smf;
    uint32_t sbase = (uint32_t)__cvta_generic_to_shared(smem);
    int t = threadIdx.x, w = t >> 5, lane = t & 31;
    int g = lane >> 2, tg = lane & 3;
    int blk0 = blockIdx.x * 2;
    int mblk = w >> 2;
    int ocb  = (w & 3) * 64;

    float acc[4][8][4];
    #pragma unroll
    for (int mt = 0; mt < 4; mt++)
        #pragma unroll
        for (int nt = 0; nt < 8; nt++)
            #pragma unroll
            for (int e = 0; e < 4; e++) acc[mt][nt][e] = 0.0f;

    for (int i = t; i < W2OFF / 16; i += 256) ((uint4*)smem)[i] = make_uint4(0, 0, 0, 0);

    int xblk = t >> 7;
    int icp  = (t >> 2) & 31;
    int pxg  = t & 3;

    for (int chunk = 0; chunk < 4; chunk++) {
        __syncthreads();
        {
            int tc = chunk;
            #pragma unroll
            for (int j = 0; j < 8; j++) {
                int idx = t + j * 256;
                int row = idx >> 3, q = idx & 7;
                const __half* gs = w216 + (size_t)tc * 16384 + row * 64 + q * 8;
                uint32_t sd = sbase + W2OFF + row * X1STR + q * 16;
                cp_async16(sd, gs);
            }
            CP_COMMIT();
        }
        {
            int ic0 = chunk * 64 + icp * 2;
            const float* s0 = g1buf + ((size_t)(blk0 + xblk) * C2 + ic0) * 64 + pxg * 16;
            const float* s1 = s0 + 64;
            float a0 = d_a1[ic0],     c0 = d_b1[ic0];
            float a1 = d_a1[ic0 + 1], c1 = d_b1[ic0 + 1];
            char* xb = smem + xblk * X2BLK + icp * 4;
            #pragma unroll
            for (int q = 0; q < 4; q++) {
                float4 u0 = ((const float4*)s0)[q];
                float4 u1 = ((const float4*)s1)[q];
                float v0[4] = {u0.x, u0.y, u0.z, u0.w};
                float v1[4] = {u1.x, u1.y, u1.z, u1.w};
                #pragma unroll
                for (int e = 0; e < 4; e++) {
                    int p = pxg * 16 + q * 4 + e;
                    int row = ((p >> 3) + 1) * 10 + (p & 7) + 1;
                    float x0 = a0 * v0[e] + c0;
                    float x1 = a1 * v1[e] + c1;
                    __half h0 = __float2half(x0);
                    __half h1 = __float2half(x1);
                    __half l0 = __float2half(x0 - __half2float(h0));
                    __half l1 = __float2half(x1 - __half2float(h1));
                    *(unsigned*)(xb + row * X1STR) =
                        PKU(__half_as_ushort(h0), __half_as_ushort(h1));
                    *(unsigned*)(xb + X2ARR + row * X1STR) =
                        PKU(__half_as_ushort(l0), __half_as_ushort(l1));
                }
            }
        }

        for (int tap = 0; tap < 9; tap++) {
            CP_WAIT0();
            __syncthreads();
            int buf = tap & 1;
            if (tap < 8) {
                int tc = (tap + 1) * 4 + chunk;
                int ob = buf ^ 1;
                #pragma unroll
                for (int j = 0; j < 8; j++) {
                    int idx = t + j * 256;
                    int row = idx >> 3, q = idx & 7;
                    const __half* gs = w216 + (size_t)tc * 16384 + row * 64 + q * 8;
                    uint32_t sd = sbase + W2OFF + ob * W2BUF + row * X1STR + q * 16;
                    cp_async16(sd, gs);
                }
                CP_COMMIT();
            }

            int dr = tap / 3, dc = tap % 3;
            int rowc = dr * 10 + dc + g;
            const char* A  = smem + W2OFF + buf * W2BUF;
            const char* Bh = smem + mblk * X2BLK;
            #pragma unroll
            for (int k4 = 0; k4 < 4; k4++) {
                int kb = (k4 * 16 + 2 * tg) * 2;
                unsigned af[4][4];
                #pragma unroll
                for (int mt = 0; mt < 4; mt++) {
                    const char* ar = A + (ocb + mt * 16 + g) * X1STR + kb;
                    af[mt][0] = *(const unsigned*)ar;
                    af[mt][1] = *(const unsigned*)(ar + 8 * X1STR);
                    af[mt][2] = *(const unsigned*)(ar + 16);
                    af[mt][3] = *(const unsigned*)(ar + 8 * X1STR + 16);
                }
                #pragma unroll
                for (int nt = 0; nt < 8; nt++) {
                    const char* br = Bh + (rowc + nt * 10) * X1STR + kb;
                    unsigned b0h = *(const unsigned*)br;
                    unsigned b1h = *(const unsigned*)(br + 16);
                    unsigned b0l = *(const unsigned*)(br + X2ARR);
                    unsigned b1l = *(const unsigned*)(br + X2ARR + 16);
                    #pragma unroll
                    for (int mt = 0; mt < 4; mt++) {
                        mma16816h(acc[mt][nt], af[mt], b0h, b1h);
                        mma16816h(acc[mt][nt], af[mt], b0l, b1l);
                    }
                }
            }
        }
    }

    #pragma unroll
    for (int mt = 0; mt < 4; mt++) {
        int oc_a = ocb + mt * 16 + g;
        int oc_b = oc_a + 8;
        float ba = b2[oc_a], bbv = b2[oc_b];
        float* da = g2buf + ((size_t)(blk0 + mblk) * C2 + oc_a) * 64;
        float* db = g2buf + ((size_t)(blk0 + mblk) * C2 + oc_b) * 64;
        float sa = 0.f, qa = 0.f, sb = 0.f, qb = 0.f;
        #pragma unroll
        for (int nt = 0; nt < 8; nt++) {
            int n0 = nt * 8 + tg * 2;
            float2 e0, e1;
            e0.x = fmaxf(acc[mt][nt][0] + ba, 0.f);
            e0.y = fmaxf(acc[mt][nt][1] + ba, 0.f);
            e1.x = fmaxf(acc[mt][nt][2] + bbv, 0.f);
            e1.y = fmaxf(acc[mt][nt][3] + bbv, 0.f);
            sa += e0.x + e0.y; qa += e0.x * e0.x + e0.y * e0.y;
            sb += e1.x + e1.y; qb += e1.x * e1.x + e1.y * e1.y;
            *(float2*)(da + n0) = e0;
            *(float2*)(db + n0) = e1;
        }
        quad_stats(sa, qa, tg, &d_sum2[oc_a], &d_sq2[oc_a]);
        quad_stats(sb, qb, tg, &d_sum2[oc_b], &d_sq2[oc_b]);
    }
}

// ---------------- conv3: 1x1 256->128 via fp16 HMMA 2-pass, 4 blocks/CTA, cp.async W ----------------
#define X3BLK  18432
#define W3OFF  73728
#define SMEM_C3M (W3OFF + 18432)
__global__ __launch_bounds__(256, 1) void conv3m_kernel(const float* __restrict__ b3) {
    extern __shared__ float smf[];
    char* smem = (char*)smf;
    uint32_t sbase = (uint32_t)__cvta_generic_to_shared(smem);
    int t = threadIdx.x, w = t >> 5, lane = t & 31;
    int g = lane >> 2, tg = lane & 3;
    int blk0 = blockIdx.x * 4;
    int mblk = w >> 1;
    int ocb  = (w & 1) * 64;

    float acc[4][8][4];
    #pragma unroll
    for (int mt = 0; mt < 4; mt++)
        #pragma unroll
        for (int nt = 0; nt < 8; nt++)
            #pragma unroll
            for (int e = 0; e < 4; e++) acc[mt][nt][e] = 0.0f;

    int xblk = t >> 6, xic = t & 63;

    for (int chunk = 0; chunk < 4; chunk++) {
        __syncthreads();
        // W(chunk): single fp16 plane (1024 x 16B)
        {
            #pragma unroll
            for (int j = 0; j < 4; j++) {
                int idx = t + j * 256;
                int row = idx >> 3, q = idx & 7;
                const __half* gs = w316 + (size_t)chunk * 8192 + row * 64 + q * 8;
                uint32_t sd = sbase + W3OFF + row * X1STR + q * 16;
                cp_async16(sd, gs);
            }
            CP_COMMIT();
        }
        {
            int icg = chunk * 64 + xic;
            const float* src = g2buf + ((size_t)(blk0 + xblk) * C2 + icg) * 64;
            float a = d_a2[icg], bb = d_b2[icg];
            char* xb = smem + xblk * X3BLK + xic * 2;
            #pragma unroll
            for (int j = 0; j < 16; j++) {
                float4 v4 = ((const float4*)src)[j];
                float vals[4] = {v4.x, v4.y, v4.z, v4.w};
                #pragma unroll
                for (int e = 0; e < 4; e++) {
                    int px = j * 4 + e;
                    float xv = a * vals[e] + bb;
                    __half h = __float2half(xv);
                    __half l = __float2half(xv - __half2float(h));
                    *(__half*)(xb + px * X1STR) = h;
                    *(__half*)(xb + X1PART + px * X1STR) = l;
                }
            }
        }
        CP_WAIT0();
        __syncthreads();

        const char* A  = smem + W3OFF;
        const char* Bh = smem + mblk * X3BLK;
        #pragma unroll
        for (int k4 = 0; k4 < 4; k4++) {
            int kb = (k4 * 16 + 2 * tg) * 2;
            unsigned af[4][4];
            #pragma unroll
            for (int mt = 0; mt < 4; mt++) {
                const char* ar = A + (ocb + mt * 16 + g) * X1STR + kb;
                af[mt][0] = *(const unsigned*)ar;
                af[mt][1] = *(const unsigned*)(ar + 8 * X1STR);
                af[mt][2] = *(const unsigned*)(ar + 16);
                af[mt][3] = *(const unsigned*)(ar + 8 * X1STR + 16);
            }
            #pragma unroll
            for (int nt = 0; nt < 8; nt++) {
                const char* br = Bh + (nt * 8 + g) * X1STR + kb;
                unsigned b0h = *(const unsigned*)br;
                unsigned b1h = *(const unsigned*)(br + 16);
                unsigned b0l = *(const unsigned*)(br + X1PART);
                unsigned b1l = *(const unsigned*)(br + X1PART + 16);
                #pragma unroll
                for (int mt = 0; mt < 4; mt++) {
                    mma16816h(acc[mt][nt], af[mt], b0h, b1h);
                    mma16816h(acc[mt][nt], af[mt], b0l, b1l);
                }
            }
        }
    }

    #pragma unroll
    for (int mt = 0; mt < 4; mt++) {
        int oc_a = ocb + mt * 16 + g;
        int oc_b = oc_a + 8;
        float ba = b3[oc_a], bbv = b3[oc_b];
        float* da = g3buf + ((size_t)(blk0 + mblk) * COUT + oc_a) * 64;
        float* db = g3buf + ((size_t)(blk0 + mblk) * COUT + oc_b) * 64;
        float sa = 0.f, qa = 0.f, sb = 0.f, qb = 0.f;
        #pragma unroll
        for (int nt = 0; nt < 8; nt++) {
            int n0 = nt * 8 + tg * 2;
            float2 e0, e1;
            e0.x = fmaxf(acc[mt][nt][0] + ba, 0.f);
            e0.y = fmaxf(acc[mt][nt][1] + ba, 0.f);
            e1.x = fmaxf(acc[mt][nt][2] + bbv, 0.f);
            e1.y = fmaxf(acc[mt][nt][3] + bbv, 0.f);
            sa += e0.x + e0.y; qa += e0.x * e0.x + e0.y * e0.y;
            sb += e1.x + e1.y; qb += e1.x * e1.x + e1.y * e1.y;
            *(float2*)(da + n0) = e0;
            *(float2*)(db + n0) = e1;
        }
        quad_stats(sa, qa, tg, &d_sum3[oc_a], &d_sq3[oc_a]);
        quad_stats(sb, qb, tg, &d_sum3[oc_b], &d_sq3[oc_b]);
    }
}

// ---------------- scatter: BN3(g3) -> image ----------------
__global__ __launch_bounds__(256) void scatter_kernel(const int* __restrict__ abi,
                                                      float* __restrict__ out) {
    int blk = blockIdx.x;
    int n  = abi[blk * 3 + 0];
    int bi = abi[blk * 3 + 1];
    int bj = abi[blk * 3 + 2];
    const float* src = g3buf + (size_t)blk * COUT * 64;
    float* dst = out + (((size_t)(n * COUT)) << 16) + bi * 8 * 256 + bj * 8;
    for (int i = threadIdx.x; i < 2048; i += 256) {
        int c = i >> 4, q = i & 15;
        int r = q >> 1, c4 = (q & 1) * 4;
        float4 v = *reinterpret_cast<const float4*>(src + c * 64 + q * 4);
        float a = d_a3[c], bb = d_b3[c];
        v.x = a * v.x + bb; v.y = a * v.y + bb;
        v.z = a * v.z + bb; v.w = a * v.w + bb;
        *reinterpret_cast<float4*>(dst + (((size_t)c) << 16) + r * 256 + c4) = v;
    }
}

// ---------------- launch ----------------
extern "C" void kernel_launch(void* const* d_in, const int* in_sizes, int n_in,
                              void* d_out, int out_size) {
    const float* x    = (const float*)d_in[0];
    const int*   abi  = (const int*)  d_in[1];
    const float* w_c  = (const float*)d_in[2];
    const float* b_c  = (const float*)d_in[3];
    const float* gm_c = (const float*)d_in[4];
    const float* be_c = (const float*)d_in[5];
    const float* w1   = (const float*)d_in[6];
    const float* b1   = (const float*)d_in[7];
    const float* gm1  = (const float*)d_in[8];
    const float* be1  = (const float*)d_in[9];
    const float* w2   = (const float*)d_in[10];
    const float* b2   = (const float*)d_in[11];
    const float* gm2  = (const float*)d_in[12];
    const float* be2  = (const float*)d_in[13];
    const float* w3   = (const float*)d_in[14];
    const float* b3   = (const float*)d_in[15];
    const float* gm3  = (const float*)d_in[16];
    const float* be3  = (const float*)d_in[17];
    float* out = (float*)d_out;

    cudaFuncSetAttribute(convcm_kernel, cudaFuncAttributeMaxDynamicSharedMemorySize, SMEM_CCM);
    cudaFuncSetAttribute(conv1m_kernel, cudaFuncAttributeMaxDynamicSharedMemorySize, SMEM_C1M);
    cudaFuncSetAttribute(conv2m_kernel, cudaFuncAttributeMaxDynamicSharedMemorySize, SMEM_C2M);
    cudaFuncSetAttribute(conv3m_kernel, cudaFuncAttributeMaxDynamicSharedMemorySize, SMEM_C3M);

    zero_stats_kernel<<<1, 256>>>();
    w2cvt_kernel<<<576, 256>>>(w2);
    w13cvt_kernel<<<64, 256>>>(w1, w3, w_c);

    convcm_kernel<<<4096, 256, SMEM_CCM>>>(x, b_c, out);
    finalize_kernel<<<1, 256>>>(0, gm_c, be_c, 1.0 / 524288.0);
    bnapply_kernel<<<16384, 256>>>(out);

    conv1m_kernel<<<2048, 256, SMEM_C1M>>>(out, abi, b1);
    finalize_kernel<<<1, 256>>>(1, gm1, be1, 1.0 / 262144.0);

    conv2m_kernel<<<2048, 256, SMEM_C2M>>>(b2);
    finalize_kernel<<<1, 256>>>(2, gm2, be2, 1.0 / 262144.0);

    conv3m_kernel<<<1024, 256, SMEM_C3M>>>(b3);
    finalize_kernel<<<1, 256>>>(3, gm3, be3, 1.0 / 262144.0);

    scatter_kernel<<<4096, 256>>>(abi, out);
}